// round 1
// baseline (speedup 1.0000x reference)
#include <cuda_runtime.h>

#define T_TOTAL     4194304
#define NTHREADS    16384
#define CHUNK_LEN   (T_TOTAL / NTHREADS)   // 256
#define WARM        1024
#define BLOCK       128
#define NBLOCKS     (NTHREADS / BLOCK)     // 128
#define RED_BLOCKS  256
#define RED_THREADS 256

struct Consts {
    float A0, A1, A2, A3;   // (W0+U)*scale per gate
    float C0, C1, C2, C3;   // W3*scale (z coeff)
    float Y0, Y1, Y2, Y3;   // W1*scale (y_prev coeff)
    float R0, R1, R2, R3;   // W2*scale (rv_prev coeff)
    float B0, B1, B2, B3;   // b*scale
    float H0, K2, phi, alpha;
    float lam, eta0, h0, z0, rs0;
};

__device__ Consts g_cs;
__device__ double g_psum[RED_BLOCKS];
__device__ double g_psq[RED_BLOCKS];

// ---------------- deterministic variance reduction ----------------
__global__ void k_reduce(const float* __restrict__ y) {
    __shared__ double ss[RED_THREADS];
    __shared__ double sq[RED_THREADS];
    double a = 0.0, b = 0.0;
    for (int i = blockIdx.x * blockDim.x + threadIdx.x; i < T_TOTAL;
         i += gridDim.x * blockDim.x) {
        double v = (double)y[i];
        a += v;
        b += v * v;
    }
    int t = threadIdx.x;
    ss[t] = a; sq[t] = b;
    __syncthreads();
    for (int s = RED_THREADS / 2; s > 0; s >>= 1) {
        if (t < s) { ss[t] += ss[t + s]; sq[t] += sq[t + s]; }
        __syncthreads();
    }
    if (t == 0) { g_psum[blockIdx.x] = ss[0]; g_psq[blockIdx.x] = sq[0]; }
}

__global__ void k_setup(
    const float* y,
    const float* Wi, const float* Ui, const float* bi,
    const float* Wf, const float* Uf, const float* bf,
    const float* Wo, const float* Uo, const float* bo,
    const float* Wc, const float* Uc, const float* bc,
    const float* omega, const float* alpha, const float* phi,
    const float* lam, const float* gam) {
    double sum = 0.0, sumsq = 0.0;
    for (int i = 0; i < RED_BLOCKS; i++) { sum += g_psum[i]; sumsq += g_psq[i]; }
    double mean = sum / (double)T_TOTAL;
    double var  = sumsq / (double)T_TOTAL - mean * mean;

    const float NL2E  = -1.44269504088896340736f;  // -log2(e) for sigmoid gates
    const float P2L2E =  2.88539008177792681472f;  // +2*log2(e) for tanh gate

    float W[4][4], U[4], B[4];
    for (int k = 0; k < 4; k++) {
        W[0][k] = Wi[k]; W[1][k] = Wf[k]; W[2][k] = Wo[k]; W[3][k] = Wc[k];
    }
    U[0] = Ui[0]; U[1] = Uf[0]; U[2] = Uo[0]; U[3] = Uc[0];
    B[0] = bi[0]; B[1] = bf[0]; B[2] = bo[0]; B[3] = bc[0];

    float sc[4] = {NL2E, NL2E, NL2E, P2L2E};
    float A[4], C[4], Y[4], R[4], Bb[4];
    for (int g = 0; g < 4; g++) {
        A[g]  = sc[g] * (W[g][0] + U[g]);
        Y[g]  = sc[g] * W[g][1];
        R[g]  = sc[g] * W[g][2];
        C[g]  = sc[g] * W[g][3];
        Bb[g] = sc[g] * B[g];
    }
    Consts cs;
    cs.A0 = A[0]; cs.A1 = A[1]; cs.A2 = A[2]; cs.A3 = A[3];
    cs.C0 = C[0]; cs.C1 = C[1]; cs.C2 = C[2]; cs.C3 = C[3];
    cs.Y0 = Y[0]; cs.Y1 = Y[1]; cs.Y2 = Y[2]; cs.Y3 = Y[3];
    cs.R0 = R[0]; cs.R1 = R[1]; cs.R2 = R[2]; cs.R3 = R[3];
    cs.B0 = Bb[0]; cs.B1 = Bb[1]; cs.B2 = Bb[2]; cs.B3 = Bb[3];
    cs.H0 = omega[0] * (1.0f - phi[0]) - alpha[0];
    cs.K2 = 2.0f * alpha[0] * gam[0];
    cs.phi = phi[0]; cs.alpha = alpha[0]; cs.lam = lam[0];
    cs.eta0 = (float)var;
    cs.h0   = (float)var;
    double se = sqrt(var);
    cs.z0  = (float)(((double)y[0] - (double)lam[0] * var) / se);
    cs.rs0 = (float)(1.0 / se);
    g_cs = cs;
}

// ---------------- fast approx intrinsics (MUFU) ----------------
__device__ __forceinline__ float ex2f(float x) {
    float r; asm("ex2.approx.f32 %0, %1;" : "=f"(r) : "f"(x)); return r;
}
__device__ __forceinline__ float rcpf(float x) {
    float r; asm("rcp.approx.f32 %0, %1;" : "=f"(r) : "f"(x)); return r;
}
__device__ __forceinline__ float rsqf(float x) {
    float r; asm("rsqrt.approx.f32 %0, %1;" : "=f"(r) : "f"(x)); return r;
}
__device__ __forceinline__ float sqtf(float x) {
    float r; asm("sqrt.approx.f32 %0, %1;" : "=f"(r) : "f"(x)); return r;
}

// one recurrence step: outputs updated (eta, c, h, z); h uses OLD z, OLD h.
__device__ __forceinline__ void step1(const Consts& cs,
                                      float yp, float rvp, float yt,
                                      float& eta, float& c, float& h, float& z) {
    // data-only terms (off critical path)
    float D0 = fmaf(cs.R0, rvp, fmaf(cs.Y0, yp, cs.B0));
    float D1 = fmaf(cs.R1, rvp, fmaf(cs.Y1, yp, cs.B1));
    float D2 = fmaf(cs.R2, rvp, fmaf(cs.Y2, yp, cs.B2));
    float D3 = fmaf(cs.R3, rvp, fmaf(cs.Y3, yp, cs.B3));
    // scaled pre-activations
    float a0 = fmaf(cs.A0, eta, fmaf(cs.C0, z, D0));
    float a1 = fmaf(cs.A1, eta, fmaf(cs.C1, z, D1));
    float a2 = fmaf(cs.A2, eta, fmaf(cs.C2, z, D2));
    float a3 = fmaf(cs.A3, eta, fmaf(cs.C3, z, D3));
    // i,f,o = sigmoid = rcp(1 + e^{-pre});  g = tanh = 1 - 2*rcp(1 + e^{2 pre})
    float ri = rcpf(1.0f + ex2f(a0));
    float rf = rcpf(1.0f + ex2f(a1));
    float ro = rcpf(1.0f + ex2f(a2));
    float rg = rcpf(1.0f + ex2f(a3));
    float gg = fmaf(-2.0f, rg, 1.0f);
    c = fmaf(rf, c, ri * gg);
    // tanh(c)
    float ec = ex2f(c * 2.8853900817779268f);
    float tc = fmaf(-2.0f, rcpf(1.0f + ec), 1.0f);
    // h update uses old z, old h (independent chain)
    float sh = sqtf(h);
    h = fmaf(-cs.K2, sh * z, fmaf(cs.alpha, z * z, fmaf(cs.phi, h, cs.H0)));
    // eta = softplus(o*tanh(c)); |s| < 1 strictly -> even Taylor poly of log(2cosh(s/2)) + s/2
    float s = ro * tc;
    float u = s * s;
    float p = fmaf(fmaf(fmaf(-2.6351698e-5f, u, 3.4722222e-4f), u,
                        -5.2083333e-3f), u, 0.125f);
    eta = fmaf(u, p, fmaf(0.5f, s, 0.69314718056f));
    // z = (y_t - lam*eta) / sqrt(eta)
    z = fmaf(-cs.lam, eta, yt) * rsqf(eta);
}

__global__ void __launch_bounds__(BLOCK)
k_main(const float* __restrict__ y, const float* __restrict__ rv,
       float* __restrict__ zo, float* __restrict__ ho) {
    const Consts cs = g_cs;
    int tid  = blockIdx.x * BLOCK + threadIdx.x;
    int t0   = tid * CHUNK_LEN;
    int tend = t0 + CHUNK_LEN;

    float eta = cs.eta0, c = 0.0f, h = cs.h0, z;
    float yp, rvp;
    int base;

    int s = t0 - WARM - 1;
    if (s < 0) {
        // exact initial state at index 0
        yp = y[0]; rvp = rv[0]; z = cs.z0;
        if (t0 == 0) { zo[0] = cs.z0; ho[0] = cs.h0; }
        #pragma unroll
        for (int t = 1; t < 4; ++t) {
            float yt = y[t];
            step1(cs, yp, rvp, yt, eta, c, h, z);
            if (t0 == 0) { zo[t] = z; ho[t] = h; }
            yp = yt; rvp = rv[t];
        }
        base = 4;
    } else {
        // guessed state at index s; contraction kills the error over WARM steps
        yp = y[s]; rvp = rv[s];
        z = fmaf(-cs.lam, cs.eta0, yp) * cs.rs0;
        base = s + 1;   // multiple of 4
    }

    for (; base < tend; base += 4) {
        float4 y4 = *reinterpret_cast<const float4*>(y + base);
        float4 r4 = *reinterpret_cast<const float4*>(rv + base);
        float4 zz, hh;
        step1(cs, yp,   rvp,  y4.x, eta, c, h, z); zz.x = z; hh.x = h;
        step1(cs, y4.x, r4.x, y4.y, eta, c, h, z); zz.y = z; hh.y = h;
        step1(cs, y4.y, r4.y, y4.z, eta, c, h, z); zz.z = z; hh.z = h;
        step1(cs, y4.z, r4.z, y4.w, eta, c, h, z); zz.w = z; hh.w = h;
        yp = y4.w; rvp = r4.w;
        if (base >= t0) {
            *reinterpret_cast<float4*>(zo + base) = zz;
            *reinterpret_cast<float4*>(ho + base) = hh;
        }
    }
}

extern "C" void kernel_launch(void* const* d_in, const int* in_sizes, int n_in,
                              void* d_out, int out_size) {
    const float* y  = (const float*)d_in[0];
    const float* rv = (const float*)d_in[1];
    float* zo = (float*)d_out;
    float* ho = zo + T_TOTAL;

    k_reduce<<<RED_BLOCKS, RED_THREADS>>>(y);
    k_setup<<<1, 1>>>(y,
        (const float*)d_in[2],  (const float*)d_in[3],  (const float*)d_in[4],
        (const float*)d_in[5],  (const float*)d_in[6],  (const float*)d_in[7],
        (const float*)d_in[8],  (const float*)d_in[9],  (const float*)d_in[10],
        (const float*)d_in[11], (const float*)d_in[12], (const float*)d_in[13],
        (const float*)d_in[14], (const float*)d_in[15], (const float*)d_in[16],
        (const float*)d_in[17], (const float*)d_in[18]);
    k_main<<<NBLOCKS, BLOCK>>>(y, rv, zo, ho);
}

// round 3
// speedup vs baseline: 2.2434x; 2.2434x over previous
#include <cuda_runtime.h>

#define T_TOTAL     4194304
// kernel A (LSTM z-chain)
#define NTH_A       32768
#define CHUNK_A     (T_TOTAL / NTH_A)      // 128
#define WARM_Z      256
#define BLOCK       128
#define NBLK_A      (NTH_A / BLOCK)        // 256
// kernel B (GARCH h-chain over stored z)
#define NTH_B       32768
#define CHUNK_B     (T_TOTAL / NTH_B)      // 128
#define WARM_H      1280
#define NBLK_B      (NTH_B / BLOCK)        // 256
// reduction
#define RED_BLOCKS  256
#define RED_THREADS 256

struct Consts {
    float A0, A1, A2, A3;   // eta coeff per gate (scaled)
    float C0, C1, C2, C3;   // z coeff
    float Y0, Y1, Y2, Y3;   // y_prev coeff
    float R0, R1, R2, R3;   // rv_prev coeff
    float B0, B1, B2, B3;   // bias
    float H0, K2, phi, alpha;
    float lam, eta0, h0, z0, rs0;
};

__device__ Consts g_cs;
__device__ double g_psum[RED_BLOCKS];
__device__ double g_psq[RED_BLOCKS];

// ---------------- deterministic variance reduction (FP32 accumulate) -------
__global__ void __launch_bounds__(RED_THREADS)
k_reduce(const float4* __restrict__ y4) {
    float s0 = 0.f, s1 = 0.f, s2 = 0.f, s3 = 0.f;
    float q0 = 0.f, q1 = 0.f, q2 = 0.f, q3 = 0.f;
    const int stride = gridDim.x * blockDim.x;
    for (int i = blockIdx.x * blockDim.x + threadIdx.x; i < T_TOTAL / 4;
         i += stride) {
        float4 v = y4[i];
        s0 += v.x; s1 += v.y; s2 += v.z; s3 += v.w;
        q0 = fmaf(v.x, v.x, q0); q1 = fmaf(v.y, v.y, q1);
        q2 = fmaf(v.z, v.z, q2); q3 = fmaf(v.w, v.w, q3);
    }
    float ss = (s0 + s1) + (s2 + s3);
    float qq = (q0 + q1) + (q2 + q3);
    #pragma unroll
    for (int o = 16; o > 0; o >>= 1) {
        ss += __shfl_down_sync(0xffffffffu, ss, o);
        qq += __shfl_down_sync(0xffffffffu, qq, o);
    }
    __shared__ float sw[RED_THREADS / 32], qw[RED_THREADS / 32];
    int lane = threadIdx.x & 31, wid = threadIdx.x >> 5;
    if (lane == 0) { sw[wid] = ss; qw[wid] = qq; }
    __syncthreads();
    if (wid == 0) {
        float a = (lane < RED_THREADS / 32) ? sw[lane] : 0.f;
        float b = (lane < RED_THREADS / 32) ? qw[lane] : 0.f;
        #pragma unroll
        for (int o = 4; o > 0; o >>= 1) {
            a += __shfl_down_sync(0xffffffffu, a, o);
            b += __shfl_down_sync(0xffffffffu, b, o);
        }
        if (lane == 0) { g_psum[blockIdx.x] = (double)a; g_psq[blockIdx.x] = (double)b; }
    }
}

// ---------------- finalize: parallel stage-2 reduce + constant prep --------
__global__ void __launch_bounds__(RED_BLOCKS)
k_setup(
    const float* y,
    const float* Wi, const float* Ui, const float* bi,
    const float* Wf, const float* Uf, const float* bf,
    const float* Wo, const float* Uo, const float* bo,
    const float* Wc, const float* Uc, const float* bc,
    const float* omega, const float* alpha, const float* phi,
    const float* lam, const float* gam) {
    __shared__ double ss[RED_BLOCKS];
    __shared__ double sq[RED_BLOCKS];
    int t = threadIdx.x;
    ss[t] = g_psum[t];
    sq[t] = g_psq[t];
    __syncthreads();
    for (int s = RED_BLOCKS / 2; s > 0; s >>= 1) {
        if (t < s) { ss[t] += ss[t + s]; sq[t] += sq[t + s]; }
        __syncthreads();
    }
    if (t != 0) return;

    double mean = ss[0] / (double)T_TOTAL;
    double var  = sq[0] / (double)T_TOTAL - mean * mean;

    float W[4][4], U[4], B[4];
    for (int k = 0; k < 4; k++) {
        W[0][k] = Wi[k]; W[1][k] = Wf[k]; W[2][k] = Wo[k]; W[3][k] = Wc[k];
    }
    U[0] = Ui[0]; U[1] = Uf[0]; U[2] = Uo[0]; U[3] = Uc[0];
    B[0] = bi[0]; B[1] = bf[0]; B[2] = bo[0]; B[3] = bc[0];

    // sigmoid(x) = 0.5*tanh(0.5x)+0.5 -> scale i,f,o pre-activations by 0.5
    // g = tanh(pre) -> scale 1.0
    float sc[4] = {0.5f, 0.5f, 0.5f, 1.0f};
    float A[4], C[4], Y[4], R[4], Bb[4];
    for (int g = 0; g < 4; g++) {
        A[g]  = sc[g] * (W[g][0] + U[g]);
        Y[g]  = sc[g] * W[g][1];
        R[g]  = sc[g] * W[g][2];
        C[g]  = sc[g] * W[g][3];
        Bb[g] = sc[g] * B[g];
    }
    Consts cs;
    cs.A0 = A[0]; cs.A1 = A[1]; cs.A2 = A[2]; cs.A3 = A[3];
    cs.C0 = C[0]; cs.C1 = C[1]; cs.C2 = C[2]; cs.C3 = C[3];
    cs.Y0 = Y[0]; cs.Y1 = Y[1]; cs.Y2 = Y[2]; cs.Y3 = Y[3];
    cs.R0 = R[0]; cs.R1 = R[1]; cs.R2 = R[2]; cs.R3 = R[3];
    cs.B0 = Bb[0]; cs.B1 = Bb[1]; cs.B2 = Bb[2]; cs.B3 = Bb[3];
    cs.H0 = omega[0] * (1.0f - phi[0]) - alpha[0];
    cs.K2 = 2.0f * alpha[0] * gam[0];
    cs.phi = phi[0]; cs.alpha = alpha[0]; cs.lam = lam[0];
    cs.eta0 = (float)var;
    cs.h0   = (float)var;
    double se = sqrt(var);
    cs.z0  = (float)(((double)y[0] - (double)lam[0] * var) / se);
    cs.rs0 = (float)(1.0 / se);
    g_cs = cs;
}

// ---------------- fast approx intrinsics (MUFU) ----------------
__device__ __forceinline__ float tanha(float x) {
    float r; asm("tanh.approx.f32 %0, %1;" : "=f"(r) : "f"(x)); return r;
}
__device__ __forceinline__ float rsqf(float x) {
    float r; asm("rsqrt.approx.f32 %0, %1;" : "=f"(r) : "f"(x)); return r;
}
__device__ __forceinline__ float sqtf(float x) {
    float r; asm("sqrt.approx.f32 %0, %1;" : "=f"(r) : "f"(x)); return r;
}

// one LSTM step: updates (eta, c, z). No h (computed in kernel B).
__device__ __forceinline__ void stepz(const Consts& cs,
                                      float yp, float rvp, float yt,
                                      float& eta, float& c, float& z) {
    // data-only terms (off critical path)
    float D0 = fmaf(cs.R0, rvp, fmaf(cs.Y0, yp, cs.B0));
    float D1 = fmaf(cs.R1, rvp, fmaf(cs.Y1, yp, cs.B1));
    float D2 = fmaf(cs.R2, rvp, fmaf(cs.Y2, yp, cs.B2));
    float D3 = fmaf(cs.R3, rvp, fmaf(cs.Y3, yp, cs.B3));
    float a0 = fmaf(cs.A0, eta, fmaf(cs.C0, z, D0));
    float a1 = fmaf(cs.A1, eta, fmaf(cs.C1, z, D1));
    float a2 = fmaf(cs.A2, eta, fmaf(cs.C2, z, D2));
    float a3 = fmaf(cs.A3, eta, fmaf(cs.C3, z, D3));
    float ti = tanha(a0);
    float tf = tanha(a1);
    float to = tanha(a2);
    float gg = tanha(a3);          // tanh gate (pre scaled by 1.0)
    float i_ = fmaf(0.5f, ti, 0.5f);
    float f_ = fmaf(0.5f, tf, 0.5f);
    float o_ = fmaf(0.5f, to, 0.5f);
    c = fmaf(f_, c, i_ * gg);
    float tc = tanha(c);
    // eta = softplus(o*tanh(c)); |s| < 1 -> even series of log(2cosh(s/2)) + s/2
    float s = o_ * tc;
    float u = s * s;
    float p = fmaf(fmaf(fmaf(-2.6351698e-5f, u, 3.4722222e-4f), u,
                        -5.2083333e-3f), u, 0.125f);
    eta = fmaf(u, p, fmaf(0.5f, s, 0.69314718056f));
    z = fmaf(-cs.lam, eta, yt) * rsqf(eta);
}

__global__ void __launch_bounds__(BLOCK)
k_main(const float* __restrict__ y, const float* __restrict__ rv,
       float* __restrict__ zo) {
    const Consts cs = g_cs;
    int tid  = blockIdx.x * BLOCK + threadIdx.x;
    int t0   = tid * CHUNK_A;
    int tend = t0 + CHUNK_A;

    float eta = cs.eta0, c = 0.0f, z;
    float yp, rvp;
    int base;

    int s = t0 - WARM_Z - 1;
    if (s < 0) {
        // exact initial state at index 0
        yp = y[0]; rvp = rv[0]; z = cs.z0;
        if (t0 == 0) zo[0] = cs.z0;
        #pragma unroll
        for (int t = 1; t < 4; ++t) {
            float yt = y[t];
            stepz(cs, yp, rvp, yt, eta, c, z);
            if (t0 == 0) zo[t] = z;
            yp = yt; rvp = rv[t];
        }
        base = 4;
    } else {
        // guessed state; fast LSTM contraction kills the error over WARM_Z steps
        yp = y[s]; rvp = rv[s];
        z = fmaf(-cs.lam, cs.eta0, yp) * cs.rs0;
        base = s + 1;   // multiple of 4
    }

    // warm loop: no stores
    for (; base < t0; base += 4) {
        float4 y4 = *reinterpret_cast<const float4*>(y + base);
        float4 r4 = *reinterpret_cast<const float4*>(rv + base);
        stepz(cs, yp,   rvp,  y4.x, eta, c, z);
        stepz(cs, y4.x, r4.x, y4.y, eta, c, z);
        stepz(cs, y4.y, r4.y, y4.z, eta, c, z);
        stepz(cs, y4.z, r4.z, y4.w, eta, c, z);
        yp = y4.w; rvp = r4.w;
    }
    // emit loop
    for (; base < tend; base += 4) {
        float4 y4 = *reinterpret_cast<const float4*>(y + base);
        float4 r4 = *reinterpret_cast<const float4*>(rv + base);
        float4 zz;
        stepz(cs, yp,   rvp,  y4.x, eta, c, z); zz.x = z;
        stepz(cs, y4.x, r4.x, y4.y, eta, c, z); zz.y = z;
        stepz(cs, y4.y, r4.y, y4.z, eta, c, z); zz.z = z;
        stepz(cs, y4.z, r4.z, y4.w, eta, c, z); zz.w = z;
        yp = y4.w; rvp = r4.w;
        *reinterpret_cast<float4*>(zo + base) = zz;
    }
}

// one GARCH h step: h' = phi*h + H0 + alpha*z^2 - K2*z*sqrt(h)  (z = z_{t-1})
__device__ __forceinline__ void steph(const Consts& cs, float zp, float& h) {
    float sh = sqtf(h);
    float base = fmaf(cs.alpha, zp * zp, fmaf(cs.phi, h, cs.H0));
    h = fmaf(-cs.K2 * zp, sh, base);
}

__global__ void __launch_bounds__(BLOCK)
k_hvol(const float* __restrict__ zo, float* __restrict__ ho) {
    const Consts cs = g_cs;
    int tid  = blockIdx.x * BLOCK + threadIdx.x;
    int t0   = tid * CHUNK_B;
    int tend = t0 + CHUNK_B;
    int start = t0 - WARM_H;
    if (start < 0) start = 0;        // exact h0 at index 0

    float h = cs.h0;
    if (t0 == 0) ho[0] = h;

    // scalar prologue: steps t = start+1 .. start+3 (uses z[start..start+2])
    float4 z4 = *reinterpret_cast<const float4*>(zo + start);
    steph(cs, z4.x, h); if (start + 1 >= t0) ho[start + 1] = h;
    steph(cs, z4.y, h); if (start + 2 >= t0) ho[start + 2] = h;
    steph(cs, z4.z, h); if (start + 3 >= t0) ho[start + 3] = h;
    float zp = z4.w;

    int base = start + 4;
    // warm loop (no stores)
    for (; base < t0; base += 4) {
        float4 q = *reinterpret_cast<const float4*>(zo + base);
        steph(cs, zp,  h);
        steph(cs, q.x, h);
        steph(cs, q.y, h);
        steph(cs, q.z, h);
        zp = q.w;
    }
    // emit loop
    for (; base < tend; base += 4) {
        float4 q = *reinterpret_cast<const float4*>(zo + base);
        float4 hh;
        steph(cs, zp,  h); hh.x = h;
        steph(cs, q.x, h); hh.y = h;
        steph(cs, q.y, h); hh.z = h;
        steph(cs, q.z, h); hh.w = h;
        zp = q.w;
        *reinterpret_cast<float4*>(ho + base) = hh;
    }
}

extern "C" void kernel_launch(void* const* d_in, const int* in_sizes, int n_in,
                              void* d_out, int out_size) {
    const float* y  = (const float*)d_in[0];
    const float* rv = (const float*)d_in[1];
    float* zo = (float*)d_out;
    float* ho = zo + T_TOTAL;

    k_reduce<<<RED_BLOCKS, RED_THREADS>>>((const float4*)y);
    k_setup<<<1, RED_BLOCKS>>>(y,
        (const float*)d_in[2],  (const float*)d_in[3],  (const float*)d_in[4],
        (const float*)d_in[5],  (const float*)d_in[6],  (const float*)d_in[7],
        (const float*)d_in[8],  (const float*)d_in[9],  (const float*)d_in[10],
        (const float*)d_in[11], (const float*)d_in[12], (const float*)d_in[13],
        (const float*)d_in[14], (const float*)d_in[15], (const float*)d_in[16],
        (const float*)d_in[17], (const float*)d_in[18]);
    k_main<<<NBLK_A, BLOCK>>>(y, rv, zo);
    k_hvol<<<NBLK_B, BLOCK>>>(zo, ho);
}

// round 4
// speedup vs baseline: 2.6014x; 1.1596x over previous
#include <cuda_runtime.h>

#define T_TOTAL 4194304
// kernel A (LSTM z-chain)
#define NTH_A   32768
#define CHUNK_A 128
#define WARM_A  257                    // g0 = t0 - 257 -> first group t0-256 (4-aligned)
#define BLOCK_A 128
#define NBLK_A  (NTH_A / BLOCK_A)      // 256
// kernel B (GARCH h-chain)
#define NTH_B   16384
#define CHUNK_B 256
#define WARM_B  1024
#define BLOCK_B 32
#define NBLK_B  (NTH_B / BLOCK_B)      // 512
#define SPAN_B  (BLOCK_B * CHUNK_B)    // 8192 outputs per block
#define REG_B   (SPAN_B + WARM_B)      // 9216 staged floats
#define REG_B_PAD (REG_B + REG_B / 256)// 9252
// reduction
#define RED_BLOCKS  256
#define RED_THREADS 256

struct Consts {
    float A0, A1, A2, A3;   // eta coeff per gate (scaled)
    float C0, C1, C2, C3;   // z coeff
    float Y0, Y1, Y2, Y3;   // y_prev coeff
    float R0, R1, R2, R3;   // rv_prev coeff
    float B0, B1, B2, B3;   // bias
    float H0, nK2, phi, alpha;
    float lam, eta0, h0, z0, rs0;
    float s0h, r0h;         // sqrt(h0), 1/sqrt(h0)
};

__device__ Consts g_cs;
__device__ double g_psum[RED_BLOCKS];
__device__ double g_psq[RED_BLOCKS];

// ---------------- deterministic variance reduction (FP32 accumulate) -------
__global__ void __launch_bounds__(RED_THREADS)
k_reduce(const float4* __restrict__ y4) {
    float s0 = 0.f, s1 = 0.f, s2 = 0.f, s3 = 0.f;
    float q0 = 0.f, q1 = 0.f, q2 = 0.f, q3 = 0.f;
    const int stride = gridDim.x * blockDim.x;
    for (int i = blockIdx.x * blockDim.x + threadIdx.x; i < T_TOTAL / 4;
         i += stride) {
        float4 v = y4[i];
        s0 += v.x; s1 += v.y; s2 += v.z; s3 += v.w;
        q0 = fmaf(v.x, v.x, q0); q1 = fmaf(v.y, v.y, q1);
        q2 = fmaf(v.z, v.z, q2); q3 = fmaf(v.w, v.w, q3);
    }
    float ss = (s0 + s1) + (s2 + s3);
    float qq = (q0 + q1) + (q2 + q3);
    #pragma unroll
    for (int o = 16; o > 0; o >>= 1) {
        ss += __shfl_down_sync(0xffffffffu, ss, o);
        qq += __shfl_down_sync(0xffffffffu, qq, o);
    }
    __shared__ float sw[RED_THREADS / 32], qw[RED_THREADS / 32];
    int lane = threadIdx.x & 31, wid = threadIdx.x >> 5;
    if (lane == 0) { sw[wid] = ss; qw[wid] = qq; }
    __syncthreads();
    if (wid == 0) {
        float a = (lane < RED_THREADS / 32) ? sw[lane] : 0.f;
        float b = (lane < RED_THREADS / 32) ? qw[lane] : 0.f;
        #pragma unroll
        for (int o = 4; o > 0; o >>= 1) {
            a += __shfl_down_sync(0xffffffffu, a, o);
            b += __shfl_down_sync(0xffffffffu, b, o);
        }
        if (lane == 0) { g_psum[blockIdx.x] = (double)a; g_psq[blockIdx.x] = (double)b; }
    }
}

// ---------------- finalize: parallel stage-2 reduce + constant prep --------
__global__ void __launch_bounds__(RED_BLOCKS)
k_setup(
    const float* y,
    const float* Wi, const float* Ui, const float* bi,
    const float* Wf, const float* Uf, const float* bf,
    const float* Wo, const float* Uo, const float* bo,
    const float* Wc, const float* Uc, const float* bc,
    const float* omega, const float* alpha, const float* phi,
    const float* lam, const float* gam) {
    __shared__ double ss[RED_BLOCKS];
    __shared__ double sq[RED_BLOCKS];
    int t = threadIdx.x;
    ss[t] = g_psum[t];
    sq[t] = g_psq[t];
    __syncthreads();
    for (int s = RED_BLOCKS / 2; s > 0; s >>= 1) {
        if (t < s) { ss[t] += ss[t + s]; sq[t] += sq[t + s]; }
        __syncthreads();
    }
    if (t != 0) return;

    double mean = ss[0] / (double)T_TOTAL;
    double var  = sq[0] / (double)T_TOTAL - mean * mean;

    float W[4][4], U[4], B[4];
    for (int k = 0; k < 4; k++) {
        W[0][k] = Wi[k]; W[1][k] = Wf[k]; W[2][k] = Wo[k]; W[3][k] = Wc[k];
    }
    U[0] = Ui[0]; U[1] = Uf[0]; U[2] = Uo[0]; U[3] = Uc[0];
    B[0] = bi[0]; B[1] = bf[0]; B[2] = bo[0]; B[3] = bc[0];

    // sigmoid(x) = 0.5*tanh(0.5x)+0.5 -> scale i,f,o pre-activations by 0.5
    float sc[4] = {0.5f, 0.5f, 0.5f, 1.0f};
    float A[4], C[4], Y[4], R[4], Bb[4];
    for (int g = 0; g < 4; g++) {
        A[g]  = sc[g] * (W[g][0] + U[g]);
        Y[g]  = sc[g] * W[g][1];
        R[g]  = sc[g] * W[g][2];
        C[g]  = sc[g] * W[g][3];
        Bb[g] = sc[g] * B[g];
    }
    Consts cs;
    cs.A0 = A[0]; cs.A1 = A[1]; cs.A2 = A[2]; cs.A3 = A[3];
    cs.C0 = C[0]; cs.C1 = C[1]; cs.C2 = C[2]; cs.C3 = C[3];
    cs.Y0 = Y[0]; cs.Y1 = Y[1]; cs.Y2 = Y[2]; cs.Y3 = Y[3];
    cs.R0 = R[0]; cs.R1 = R[1]; cs.R2 = R[2]; cs.R3 = R[3];
    cs.B0 = Bb[0]; cs.B1 = Bb[1]; cs.B2 = Bb[2]; cs.B3 = Bb[3];
    cs.H0 = omega[0] * (1.0f - phi[0]) - alpha[0];
    cs.nK2 = -2.0f * alpha[0] * gam[0];
    cs.phi = phi[0]; cs.alpha = alpha[0]; cs.lam = lam[0];
    cs.eta0 = (float)var;
    cs.h0   = (float)var;
    double se = sqrt(var);
    cs.z0  = (float)(((double)y[0] - (double)lam[0] * var) / se);
    cs.rs0 = (float)(1.0 / se);
    cs.s0h = (float)se;
    cs.r0h = (float)(1.0 / se);
    g_cs = cs;
}

// ---------------- fast approx intrinsics ----------------
__device__ __forceinline__ float tanha(float x) {
    float r; asm("tanh.approx.f32 %0, %1;" : "=f"(r) : "f"(x)); return r;
}
__device__ __forceinline__ float rsqf(float x) {
    float r; asm("rsqrt.approx.f32 %0, %1;" : "=f"(r) : "f"(x)); return r;
}

// one LSTM step: updates (eta, c, z).
__device__ __forceinline__ void stepz(const Consts& cs,
                                      float yp, float rvp, float yt,
                                      float& eta, float& c, float& z) {
    float D0 = fmaf(cs.R0, rvp, fmaf(cs.Y0, yp, cs.B0));
    float D1 = fmaf(cs.R1, rvp, fmaf(cs.Y1, yp, cs.B1));
    float D2 = fmaf(cs.R2, rvp, fmaf(cs.Y2, yp, cs.B2));
    float D3 = fmaf(cs.R3, rvp, fmaf(cs.Y3, yp, cs.B3));
    float a0 = fmaf(cs.A0, eta, fmaf(cs.C0, z, D0));
    float a1 = fmaf(cs.A1, eta, fmaf(cs.C1, z, D1));
    float a2 = fmaf(cs.A2, eta, fmaf(cs.C2, z, D2));
    float a3 = fmaf(cs.A3, eta, fmaf(cs.C3, z, D3));
    float i_ = fmaf(0.5f, tanha(a0), 0.5f);
    float f_ = fmaf(0.5f, tanha(a1), 0.5f);
    float o_ = fmaf(0.5f, tanha(a2), 0.5f);
    float gg = tanha(a3);
    c = fmaf(f_, c, i_ * gg);
    float tc = tanha(c);
    // softplus(o*tanh(c)); |s| < 1 -> even series of log(2cosh(s/2)) + s/2
    float s = o_ * tc;
    float u = s * s;
    float p = fmaf(fmaf(fmaf(-2.6351698e-5f, u, 3.4722222e-4f), u,
                        -5.2083333e-3f), u, 0.125f);
    eta = fmaf(u, p, fmaf(0.5f, s, 0.69314718056f));
    z = fmaf(-cs.lam, eta, yt) * rsqf(eta);
}

__global__ void __launch_bounds__(BLOCK_A)
k_main(const float* __restrict__ y, const float* __restrict__ rv,
       float* __restrict__ zo) {
    const Consts cs = g_cs;
    int tid  = blockIdx.x * BLOCK_A + threadIdx.x;
    int t0   = tid * CHUNK_A;
    int tend = t0 + CHUNK_A;

    bool exact = (t0 < WARM_A);             // only t0 in {0, 128}
    int g0 = exact ? 0 : (t0 - WARM_A);

    float eta = cs.eta0, c = 0.0f, z;
    float yp = y[g0], rvp = rv[g0];
    int gb;

    if (exact) {
        z = cs.z0;
        float z1, z2, z3;
        float yt = y[1]; stepz(cs, yp, rvp, yt, eta, c, z); z1 = z; yp = yt; rvp = rv[1];
        yt = y[2];       stepz(cs, yp, rvp, yt, eta, c, z); z2 = z; yp = yt; rvp = rv[2];
        yt = y[3];       stepz(cs, yp, rvp, yt, eta, c, z); z3 = z; yp = yt; rvp = rv[3];
        if (t0 == 0) {
            float4 v; v.x = cs.z0; v.y = z1; v.z = z2; v.w = z3;
            *reinterpret_cast<float4*>(zo) = v;
        }
        gb = 4;
    } else {
        z = fmaf(-cs.lam, cs.eta0, yp) * cs.rs0;
        gb = g0 + 1;                        // == t0 - 256, 4-aligned
    }

    // software-pipelined group loop (1 group lookahead hides L2 latency)
    float4 ycur = *reinterpret_cast<const float4*>(y + gb);
    float4 rcur = *reinterpret_cast<const float4*>(rv + gb);
    for (; gb < tend; gb += 4) {
        int nb = (gb + 4 < tend) ? (gb + 4) : gb;
        float4 ynxt = *reinterpret_cast<const float4*>(y + nb);
        float4 rnxt = *reinterpret_cast<const float4*>(rv + nb);
        float4 zz;
        stepz(cs, yp,     rvp,    ycur.x, eta, c, z); zz.x = z;
        stepz(cs, ycur.x, rcur.x, ycur.y, eta, c, z); zz.y = z;
        stepz(cs, ycur.y, rcur.y, ycur.z, eta, c, z); zz.z = z;
        stepz(cs, ycur.z, rcur.z, ycur.w, eta, c, z); zz.w = z;
        yp = ycur.w; rvp = rcur.w;
        if (gb >= t0)
            *reinterpret_cast<float4*>(zo + gb) = zz;
        ycur = ynxt; rcur = rnxt;
    }
}

// one GARCH h step with Newton-tracked sqrt (no MUFU on critical path):
// h' = phi*h + H0 + alpha*z^2 - K2*z*s,  s ~= sqrt(h), r ~= 1/sqrt(h)
__device__ __forceinline__ void steph(const Consts& cs, float zp,
                                      float& h, float& s, float& r) {
    float t1 = fmaf(cs.alpha * zp, zp, cs.H0);
    float t2 = fmaf(cs.nK2 * zp, s, t1);
    h = fmaf(cs.phi, h, t2);                 // 4-cyc recurrence
    float hm = 0.5f * h;
    float sn = fmaf(hm, r, 0.5f * s);        // Newton sqrt iter 1
    float tt = fmaf(-sn, r, 1.0f);
    r = fmaf(r, tt, r);                      // Newton recip iter
    s = fmaf(hm, r, 0.5f * sn);              // Newton sqrt iter 2
}

__global__ void __launch_bounds__(BLOCK_B)
k_hvol(const float* __restrict__ zo, float* __restrict__ ho) {
    __shared__ float sz[REG_B_PAD];
    const Consts cs = g_cs;
    const int blk0 = blockIdx.x * SPAN_B;
    int lo = blk0 - WARM_B; if (lo < 0) lo = 0;
    const int n = blk0 + SPAN_B - lo;

    // stage z region into smem (swizzle i + (i>>8): conflict-free strided reads)
    #pragma unroll 4
    for (int i = threadIdx.x; i < n; i += BLOCK_B)
        sz[i + (i >> 8)] = zo[lo + i];
    __syncthreads();

    int t0   = blk0 + threadIdx.x * CHUNK_B;
    int tend = t0 + CHUNK_B;
    bool exact = (t0 < WARM_B);
    int g0 = exact ? 0 : (t0 - WARM_B);

    float h = cs.h0, s = cs.s0h, r = cs.r0h;

    // prologue: 3 scalar steps (g0+1..g0+3) using z[g0..g0+2]
    int rel = g0 - lo;
    float h1, h2, h3;
    {
        float za = sz[rel + (rel >> 8)];
        int r1 = rel + 1; float zb = sz[r1 + (r1 >> 8)];
        int r2 = rel + 2; float zc = sz[r2 + (r2 >> 8)];
        steph(cs, za, h, s, r); h1 = h;
        steph(cs, zb, h, s, r); h2 = h;
        steph(cs, zc, h, s, r); h3 = h;
    }
    if (t0 == 0) {
        float4 v; v.x = cs.h0; v.y = h1; v.z = h2; v.w = h3;
        *reinterpret_cast<float4*>(ho) = v;
    }

    // group loop from g0+4: 4 steps/group, one-group z lookahead
    int zrel = g0 + 3 - lo;   // index of z[gb-1] for first group
    int i0 = zrel,     j0 = i0 + (i0 >> 8);
    int i1 = zrel + 1, j1 = i1 + (i1 >> 8);
    int i2 = zrel + 2, j2 = i2 + (i2 >> 8);
    int i3 = zrel + 3, j3 = i3 + (i3 >> 8);
    float za = sz[j0], zb = sz[j1], zc = sz[j2], zd = sz[j3];
    for (int gb = g0 + 4; gb < tend; gb += 4) {
        int nrel = (gb + 4 < tend) ? (zrel + 4) : zrel;
        int k0 = nrel,     m0 = k0 + (k0 >> 8);
        int k1 = nrel + 1, m1 = k1 + (k1 >> 8);
        int k2 = nrel + 2, m2 = k2 + (k2 >> 8);
        int k3 = nrel + 3, m3 = k3 + (k3 >> 8);
        float na = sz[m0], nb = sz[m1], nc = sz[m2], nd = sz[m3];
        float4 hh;
        steph(cs, za, h, s, r); hh.x = h;
        steph(cs, zb, h, s, r); hh.y = h;
        steph(cs, zc, h, s, r); hh.z = h;
        steph(cs, zd, h, s, r); hh.w = h;
        if (gb >= t0)
            *reinterpret_cast<float4*>(ho + gb) = hh;
        za = na; zb = nb; zc = nc; zd = nd;
        zrel = nrel;
    }
}

extern "C" void kernel_launch(void* const* d_in, const int* in_sizes, int n_in,
                              void* d_out, int out_size) {
    const float* y  = (const float*)d_in[0];
    const float* rv = (const float*)d_in[1];
    float* zo = (float*)d_out;
    float* ho = zo + T_TOTAL;

    k_reduce<<<RED_BLOCKS, RED_THREADS>>>((const float4*)y);
    k_setup<<<1, RED_BLOCKS>>>(y,
        (const float*)d_in[2],  (const float*)d_in[3],  (const float*)d_in[4],
        (const float*)d_in[5],  (const float*)d_in[6],  (const float*)d_in[7],
        (const float*)d_in[8],  (const float*)d_in[9],  (const float*)d_in[10],
        (const float*)d_in[11], (const float*)d_in[12], (const float*)d_in[13],
        (const float*)d_in[14], (const float*)d_in[15], (const float*)d_in[16],
        (const float*)d_in[17], (const float*)d_in[18]);
    k_main<<<NBLK_A, BLOCK_A>>>(y, rv, zo);
    k_hvol<<<NBLK_B, BLOCK_B>>>(zo, ho);
}

// round 5
// speedup vs baseline: 2.7780x; 1.0679x over previous
#include <cuda_runtime.h>

#define T_TOTAL 4194304
// kernel A (LSTM z-chain): each thread runs 2 independent chains (ILP=2)
#define CHUNK_A 128
#define WARM_A  256                       // non-exact start at t0-257
#define PAIRS_A 16384                     // threads
#define BLOCK_A 128
#define NBLK_A  (PAIRS_A / BLOCK_A)       // 128
#define TRIPS_A ((WARM_A + CHUNK_A) / 4)  // 96
// kernel B (GARCH h-chain): ILP=2, smem-staged z
#define CHUNK_B 128
#define WARM_B  768
#define BLOCK_B 32
#define PAIRS_B 16384
#define NBLK_B  (PAIRS_B / BLOCK_B)       // 512
#define SPAN_B  (BLOCK_B * 2 * CHUNK_B)   // 8192
#define REG_B   (SPAN_B + WARM_B)         // 8960
#define REG_B_PAD (REG_B + (REG_B >> 8))  // 8995
#define TRIPS_B ((WARM_B + CHUNK_B - 4) / 4) // 223
// reduction
#define RED_BLOCKS  256
#define RED_THREADS 256

struct Consts {
    float A0, A1, A2, A3;   // eta coeff per gate (scaled)
    float C0, C1, C2, C3;   // z coeff
    float Y0, Y1, Y2, Y3;   // y_prev coeff
    float R0, R1, R2, R3;   // rv_prev coeff
    float B0, B1, B2, B3;   // bias
    float H0, nK2, phi, alpha;
    float lam, eta0, h0, z0, rs0, omega;
};

__device__ Consts g_cs;
__device__ double g_psum[RED_BLOCKS];
__device__ double g_psq[RED_BLOCKS];

// ---------------- deterministic variance reduction (FP32 accumulate) -------
__global__ void __launch_bounds__(RED_THREADS)
k_reduce(const float4* __restrict__ y4) {
    float s0 = 0.f, s1 = 0.f, s2 = 0.f, s3 = 0.f;
    float q0 = 0.f, q1 = 0.f, q2 = 0.f, q3 = 0.f;
    const int stride = gridDim.x * blockDim.x;
    for (int i = blockIdx.x * blockDim.x + threadIdx.x; i < T_TOTAL / 4;
         i += stride) {
        float4 v = y4[i];
        s0 += v.x; s1 += v.y; s2 += v.z; s3 += v.w;
        q0 = fmaf(v.x, v.x, q0); q1 = fmaf(v.y, v.y, q1);
        q2 = fmaf(v.z, v.z, q2); q3 = fmaf(v.w, v.w, q3);
    }
    float ss = (s0 + s1) + (s2 + s3);
    float qq = (q0 + q1) + (q2 + q3);
    #pragma unroll
    for (int o = 16; o > 0; o >>= 1) {
        ss += __shfl_down_sync(0xffffffffu, ss, o);
        qq += __shfl_down_sync(0xffffffffu, qq, o);
    }
    __shared__ float sw[RED_THREADS / 32], qw[RED_THREADS / 32];
    int lane = threadIdx.x & 31, wid = threadIdx.x >> 5;
    if (lane == 0) { sw[wid] = ss; qw[wid] = qq; }
    __syncthreads();
    if (wid == 0) {
        float a = (lane < RED_THREADS / 32) ? sw[lane] : 0.f;
        float b = (lane < RED_THREADS / 32) ? qw[lane] : 0.f;
        #pragma unroll
        for (int o = 4; o > 0; o >>= 1) {
            a += __shfl_down_sync(0xffffffffu, a, o);
            b += __shfl_down_sync(0xffffffffu, b, o);
        }
        if (lane == 0) { g_psum[blockIdx.x] = (double)a; g_psq[blockIdx.x] = (double)b; }
    }
}

// ---------------- finalize: parallel stage-2 reduce + constant prep --------
__global__ void __launch_bounds__(RED_BLOCKS)
k_setup(
    const float* y,
    const float* Wi, const float* Ui, const float* bi,
    const float* Wf, const float* Uf, const float* bf,
    const float* Wo, const float* Uo, const float* bo,
    const float* Wc, const float* Uc, const float* bc,
    const float* omega, const float* alpha, const float* phi,
    const float* lam, const float* gam) {
    __shared__ double ss[RED_BLOCKS];
    __shared__ double sq[RED_BLOCKS];
    int t = threadIdx.x;
    ss[t] = g_psum[t];
    sq[t] = g_psq[t];
    __syncthreads();
    for (int s = RED_BLOCKS / 2; s > 0; s >>= 1) {
        if (t < s) { ss[t] += ss[t + s]; sq[t] += sq[t + s]; }
        __syncthreads();
    }
    if (t != 0) return;

    double mean = ss[0] / (double)T_TOTAL;
    double var  = sq[0] / (double)T_TOTAL - mean * mean;

    float W[4][4], U[4], B[4];
    for (int k = 0; k < 4; k++) {
        W[0][k] = Wi[k]; W[1][k] = Wf[k]; W[2][k] = Wo[k]; W[3][k] = Wc[k];
    }
    U[0] = Ui[0]; U[1] = Uf[0]; U[2] = Uo[0]; U[3] = Uc[0];
    B[0] = bi[0]; B[1] = bf[0]; B[2] = bo[0]; B[3] = bc[0];

    // sigmoid(x) = 0.5*tanh(0.5x)+0.5 -> scale i,f,o pre-activations by 0.5
    float sc[4] = {0.5f, 0.5f, 0.5f, 1.0f};
    float A[4], C[4], Y[4], R[4], Bb[4];
    for (int g = 0; g < 4; g++) {
        A[g]  = sc[g] * (W[g][0] + U[g]);
        Y[g]  = sc[g] * W[g][1];
        R[g]  = sc[g] * W[g][2];
        C[g]  = sc[g] * W[g][3];
        Bb[g] = sc[g] * B[g];
    }
    Consts cs;
    cs.A0 = A[0]; cs.A1 = A[1]; cs.A2 = A[2]; cs.A3 = A[3];
    cs.C0 = C[0]; cs.C1 = C[1]; cs.C2 = C[2]; cs.C3 = C[3];
    cs.Y0 = Y[0]; cs.Y1 = Y[1]; cs.Y2 = Y[2]; cs.Y3 = Y[3];
    cs.R0 = R[0]; cs.R1 = R[1]; cs.R2 = R[2]; cs.R3 = R[3];
    cs.B0 = Bb[0]; cs.B1 = Bb[1]; cs.B2 = Bb[2]; cs.B3 = Bb[3];
    cs.H0 = omega[0] * (1.0f - phi[0]) - alpha[0];
    cs.nK2 = -2.0f * alpha[0] * gam[0];
    cs.phi = phi[0]; cs.alpha = alpha[0]; cs.lam = lam[0];
    cs.omega = omega[0];
    cs.eta0 = (float)var;
    cs.h0   = (float)var;
    double se = sqrt(var);
    cs.z0  = (float)(((double)y[0] - (double)lam[0] * var) / se);
    cs.rs0 = (float)(1.0 / se);
    g_cs = cs;
}

// ---------------- fast approx intrinsics ----------------
__device__ __forceinline__ float tanha(float x) {
    float r; asm("tanh.approx.f32 %0, %1;" : "=f"(r) : "f"(x)); return r;
}
__device__ __forceinline__ float rsqf(float x) {
    float r; asm("rsqrt.approx.f32 %0, %1;" : "=f"(r) : "f"(x)); return r;
}
__device__ __forceinline__ float sqtf(float x) {
    float r; asm("sqrt.approx.f32 %0, %1;" : "=f"(r) : "f"(x)); return r;
}

// one LSTM step: updates (eta, c, z).
__device__ __forceinline__ void stepz(const Consts& cs,
                                      float yp, float rvp, float yt,
                                      float& eta, float& c, float& z) {
    float D0 = fmaf(cs.R0, rvp, fmaf(cs.Y0, yp, cs.B0));
    float D1 = fmaf(cs.R1, rvp, fmaf(cs.Y1, yp, cs.B1));
    float D2 = fmaf(cs.R2, rvp, fmaf(cs.Y2, yp, cs.B2));
    float D3 = fmaf(cs.R3, rvp, fmaf(cs.Y3, yp, cs.B3));
    float a0 = fmaf(cs.A0, eta, fmaf(cs.C0, z, D0));
    float a1 = fmaf(cs.A1, eta, fmaf(cs.C1, z, D1));
    float a2 = fmaf(cs.A2, eta, fmaf(cs.C2, z, D2));
    float a3 = fmaf(cs.A3, eta, fmaf(cs.C3, z, D3));
    float gg = tanha(a3);
    float i_ = fmaf(0.5f, tanha(a0), 0.5f);
    float f_ = fmaf(0.5f, tanha(a1), 0.5f);
    float o_ = fmaf(0.5f, tanha(a2), 0.5f);
    c = fmaf(f_, c, i_ * gg);
    float tc = tanha(c);
    // softplus(o*tanh(c)); |s| < 1 -> even series of log(2cosh(s/2)) + s/2
    float s = o_ * tc;
    float u = s * s;
    float p = fmaf(fmaf(3.4722222e-4f, u, -5.2083333e-3f), u, 0.125f);
    eta = fmaf(u, p, fmaf(0.5f, s, 0.69314718056f));
    z = fmaf(-cs.lam, eta, yt) * rsqf(eta);
}

// ---- one z-chain (state in registers; group-pipelined loads) ----
struct ZChain {
    float eta, c, z, yp, rvp;
    float4 ycur, rcur;
    int gb, t0, tend;

    __device__ __forceinline__ void init(const Consts& cs,
                                         const float* __restrict__ y,
                                         const float* __restrict__ rv,
                                         float* __restrict__ zo, int t0_) {
        t0 = t0_; tend = t0_ + CHUNK_A;
        eta = cs.eta0; c = 0.0f;
        if (t0 > WARM_A) {
            int g0 = t0 - (WARM_A + 1);
            yp = y[g0]; rvp = rv[g0];
            z = fmaf(-cs.lam, cs.eta0, yp) * cs.rs0;
            gb = g0 + 1;
        } else {
            yp = y[0]; rvp = rv[0]; z = cs.z0;
            float z1, z2, z3, yt;
            yt = y[1]; stepz(cs, yp, rvp, yt, eta, c, z); z1 = z; yp = yt; rvp = rv[1];
            yt = y[2]; stepz(cs, yp, rvp, yt, eta, c, z); z2 = z; yp = yt; rvp = rv[2];
            yt = y[3]; stepz(cs, yp, rvp, yt, eta, c, z); z3 = z; yp = yt; rvp = rv[3];
            if (t0 == 0) {
                float4 v; v.x = cs.z0; v.y = z1; v.z = z2; v.w = z3;
                *reinterpret_cast<float4*>(zo) = v;
            }
            gb = 4;
        }
        ycur = *reinterpret_cast<const float4*>(y + gb);
        rcur = *reinterpret_cast<const float4*>(rv + gb);
    }

    __device__ __forceinline__ void iter(const Consts& cs,
                                         const float* __restrict__ y,
                                         const float* __restrict__ rv,
                                         float* __restrict__ zo) {
        int nb = (gb + 4 < tend) ? (gb + 4) : gb;
        float4 yn = *reinterpret_cast<const float4*>(y + nb);
        float4 rn = *reinterpret_cast<const float4*>(rv + nb);
        float4 zz;
        stepz(cs, yp,     rvp,    ycur.x, eta, c, z); zz.x = z;
        stepz(cs, ycur.x, rcur.x, ycur.y, eta, c, z); zz.y = z;
        stepz(cs, ycur.y, rcur.y, ycur.z, eta, c, z); zz.z = z;
        stepz(cs, ycur.z, rcur.z, ycur.w, eta, c, z); zz.w = z;
        if (gb >= t0 && gb < tend)
            *reinterpret_cast<float4*>(zo + gb) = zz;
        yp = ycur.w; rvp = rcur.w;
        ycur = yn; rcur = rn;
        gb += 4;
    }
};

__global__ void __launch_bounds__(BLOCK_A)
k_main(const float* __restrict__ y, const float* __restrict__ rv,
       float* __restrict__ zo) {
    const Consts cs = g_cs;
    int u = blockIdx.x * BLOCK_A + threadIdx.x;   // pair index
    ZChain A, B;
    A.init(cs, y, rv, zo, u * (2 * CHUNK_A));
    B.init(cs, y, rv, zo, u * (2 * CHUNK_A) + CHUNK_A);
    #pragma unroll 2
    for (int it = 0; it < TRIPS_A; ++it) {
        A.iter(cs, y, rv, zo);
        B.iter(cs, y, rv, zo);
    }
}

// one GARCH h step: h' = phi*h + H0 + alpha*z^2 + nK2*z*sqrt(h)
__device__ __forceinline__ void steph(const Consts& cs, float zp, float& h) {
    float u = fmaf(cs.alpha * zp, zp, cs.H0);
    h = fmaf(cs.phi, h, fmaf(cs.nK2 * zp, sqtf(h), u));
}

__device__ __forceinline__ int swz(int i) { return i + (i >> 8); }

// ---- one h-chain over smem-staged z ----
struct HChain {
    float h, za, zb, zc, zd;
    int gb, t0, tend, zrel;   // zrel = smem rel index of z[gb-1]

    __device__ __forceinline__ void init(const Consts& cs,
                                         const float* __restrict__ sz,
                                         float* __restrict__ ho,
                                         int t0_, int lo) {
        t0 = t0_; tend = t0_ + CHUNK_B;
        int g0;
        if (t0 > WARM_B) { g0 = t0 - WARM_B; h = cs.omega; }
        else             { g0 = 0;           h = cs.h0; }
        int rel = g0 - lo;
        float h1, h2, h3;
        steph(cs, sz[swz(rel)],     h); h1 = h;
        steph(cs, sz[swz(rel + 1)], h); h2 = h;
        steph(cs, sz[swz(rel + 2)], h); h3 = h;
        if (t0 == 0) {
            float4 v; v.x = cs.h0; v.y = h1; v.z = h2; v.w = h3;
            *reinterpret_cast<float4*>(ho) = v;
        }
        gb = g0 + 4;
        zrel = rel + 3;
        za = sz[swz(zrel)];
        zb = sz[swz(zrel + 1)];
        zc = sz[swz(zrel + 2)];
        zd = sz[swz(zrel + 3)];
    }

    __device__ __forceinline__ void iter(const Consts& cs,
                                         const float* __restrict__ sz,
                                         float* __restrict__ ho) {
        int nrel = (gb + 4 < tend) ? (zrel + 4) : zrel;
        float na = sz[swz(nrel)];
        float nb = sz[swz(nrel + 1)];
        float nc = sz[swz(nrel + 2)];
        float nd = sz[swz(nrel + 3)];
        float4 hh;
        steph(cs, za, h); hh.x = h;
        steph(cs, zb, h); hh.y = h;
        steph(cs, zc, h); hh.z = h;
        steph(cs, zd, h); hh.w = h;
        if (gb >= t0 && gb < tend)
            *reinterpret_cast<float4*>(ho + gb) = hh;
        za = na; zb = nb; zc = nc; zd = nd;
        zrel = nrel;
        gb += 4;
    }
};

__global__ void __launch_bounds__(BLOCK_B)
k_hvol(const float* __restrict__ zo, float* __restrict__ ho) {
    __shared__ float sz[REG_B_PAD];
    const Consts cs = g_cs;
    const int blk0 = blockIdx.x * SPAN_B;
    int lo = blk0 - WARM_B; if (lo < 0) lo = 0;
    const int n = blk0 + SPAN_B - lo;          // multiple of 4

    // stage z region into smem (float4 loads, swizzled scalar stores)
    for (int i = threadIdx.x * 4; i < n; i += BLOCK_B * 4) {
        float4 v = *reinterpret_cast<const float4*>(zo + lo + i);
        int j = swz(i);          // i%4==0 and i%256<=252 -> swz(i+k)=swz(i)+k
        sz[j]     = v.x;
        sz[j + 1] = v.y;
        sz[j + 2] = v.z;
        sz[j + 3] = v.w;
    }
    __syncthreads();

    int ti = threadIdx.x;
    HChain A, B;
    A.init(cs, sz, ho, blk0 + ti * (2 * CHUNK_B), lo);
    B.init(cs, sz, ho, blk0 + ti * (2 * CHUNK_B) + CHUNK_B, lo);
    #pragma unroll 2
    for (int it = 0; it < TRIPS_B; ++it) {
        A.iter(cs, sz, ho);
        B.iter(cs, sz, ho);
    }
}

extern "C" void kernel_launch(void* const* d_in, const int* in_sizes, int n_in,
                              void* d_out, int out_size) {
    const float* y  = (const float*)d_in[0];
    const float* rv = (const float*)d_in[1];
    float* zo = (float*)d_out;
    float* ho = zo + T_TOTAL;

    k_reduce<<<RED_BLOCKS, RED_THREADS>>>((const float4*)y);
    k_setup<<<1, RED_BLOCKS>>>(y,
        (const float*)d_in[2],  (const float*)d_in[3],  (const float*)d_in[4],
        (const float*)d_in[5],  (const float*)d_in[6],  (const float*)d_in[7],
        (const float*)d_in[8],  (const float*)d_in[9],  (const float*)d_in[10],
        (const float*)d_in[11], (const float*)d_in[12], (const float*)d_in[13],
        (const float*)d_in[14], (const float*)d_in[15], (const float*)d_in[16],
        (const float*)d_in[17], (const float*)d_in[18]);
    k_main<<<NBLK_A, BLOCK_A>>>(y, rv, zo);
    k_hvol<<<NBLK_B, BLOCK_B>>>(zo, ho);
}

// round 6
// speedup vs baseline: 3.1514x; 1.1344x over previous
#include <cuda_runtime.h>

#define T_TOTAL 4194304
// ---- kernel A (LSTM z-chain): ILP=2 chains/thread, rv smem-staged ----
#define CHUNK_A  128
#define WARM_A   256
#define BLOCK_A  32
#define SPAN_A   (BLOCK_A * 2 * CHUNK_A)     // 8192
#define NBLK_A   (T_TOTAL / SPAN_A)          // 512
#define PROL_A   260                         // staged lead (warm 257, 4-aligned)
#define NSTG_A   (SPAN_A + PROL_A)           // 8452
#define PAD_A    (NSTG_A + (NSTG_A >> 8))    // 8485
#define WITER_A  (WARM_A / 4)                // 64
#define EITER_A  (CHUNK_A / 4)               // 32
#define TRIPS_A  (WITER_A + EITER_A)         // 96
// ---- kernel B (GARCH h-chain): ILP=2, z smem-staged ----
#define CHUNK_B  64
#define WARM_B   576
#define BLOCK_B  32
#define SPAN_B   (BLOCK_B * 2 * CHUNK_B)     // 4096
#define NBLK_B   (T_TOTAL / SPAN_B)          // 1024
#define NSTG_B   (SPAN_B + WARM_B)           // 4672
#define PAD_B    (NSTG_B + (NSTG_B >> 7))    // 4708
#define WITER_B  ((WARM_B - 4) / 4)          // 143
#define EITER_B  (CHUNK_B / 4)               // 16
#define TRIPS_B  (WITER_B + EITER_B)         // 159
// ---- reduction ----
#define RED_BLOCKS  512
#define RED_THREADS 256

struct Consts {
    float A0, A1, A2, A3;   // eta coeff per gate (scaled)
    float C0, C1, C2, C3;   // z coeff
    float Y0, Y1, Y2, Y3;   // y_prev coeff
    float R0, R1, R2, R3;   // rv_prev coeff
    float B0, B1, B2, B3;   // bias
    float H0, nK2, phi, alpha;
    float lam, eta0, h0, z0, rs0, omega;
};

__device__ Consts g_cs;
__device__ double g_psum[RED_BLOCKS];
__device__ double g_psq[RED_BLOCKS];

// ---------------- deterministic variance reduction (FP32 accumulate) -------
__global__ void __launch_bounds__(RED_THREADS)
k_reduce(const float4* __restrict__ y4) {
    float s0 = 0.f, s1 = 0.f, s2 = 0.f, s3 = 0.f;
    float q0 = 0.f, q1 = 0.f, q2 = 0.f, q3 = 0.f;
    const int stride = gridDim.x * blockDim.x;
    for (int i = blockIdx.x * blockDim.x + threadIdx.x; i < T_TOTAL / 4;
         i += stride) {
        float4 v = y4[i];
        s0 += v.x; s1 += v.y; s2 += v.z; s3 += v.w;
        q0 = fmaf(v.x, v.x, q0); q1 = fmaf(v.y, v.y, q1);
        q2 = fmaf(v.z, v.z, q2); q3 = fmaf(v.w, v.w, q3);
    }
    float ss = (s0 + s1) + (s2 + s3);
    float qq = (q0 + q1) + (q2 + q3);
    #pragma unroll
    for (int o = 16; o > 0; o >>= 1) {
        ss += __shfl_down_sync(0xffffffffu, ss, o);
        qq += __shfl_down_sync(0xffffffffu, qq, o);
    }
    __shared__ float sw[RED_THREADS / 32], qw[RED_THREADS / 32];
    int lane = threadIdx.x & 31, wid = threadIdx.x >> 5;
    if (lane == 0) { sw[wid] = ss; qw[wid] = qq; }
    __syncthreads();
    if (wid == 0) {
        float a = (lane < RED_THREADS / 32) ? sw[lane] : 0.f;
        float b = (lane < RED_THREADS / 32) ? qw[lane] : 0.f;
        #pragma unroll
        for (int o = 4; o > 0; o >>= 1) {
            a += __shfl_down_sync(0xffffffffu, a, o);
            b += __shfl_down_sync(0xffffffffu, b, o);
        }
        if (lane == 0) { g_psum[blockIdx.x] = (double)a; g_psq[blockIdx.x] = (double)b; }
    }
}

// ---------------- finalize: parallel stage-2 reduce + constant prep --------
__global__ void __launch_bounds__(RED_BLOCKS)
k_setup(
    const float* y,
    const float* Wi, const float* Ui, const float* bi,
    const float* Wf, const float* Uf, const float* bf,
    const float* Wo, const float* Uo, const float* bo,
    const float* Wc, const float* Uc, const float* bc,
    const float* omega, const float* alpha, const float* phi,
    const float* lam, const float* gam) {
    __shared__ double ss[RED_BLOCKS];
    __shared__ double sq[RED_BLOCKS];
    int t = threadIdx.x;
    ss[t] = g_psum[t];
    sq[t] = g_psq[t];
    __syncthreads();
    for (int s = RED_BLOCKS / 2; s > 0; s >>= 1) {
        if (t < s) { ss[t] += ss[t + s]; sq[t] += sq[t + s]; }
        __syncthreads();
    }
    if (t != 0) return;

    double mean = ss[0] / (double)T_TOTAL;
    double var  = sq[0] / (double)T_TOTAL - mean * mean;

    float W[4][4], U[4], B[4];
    for (int k = 0; k < 4; k++) {
        W[0][k] = Wi[k]; W[1][k] = Wf[k]; W[2][k] = Wo[k]; W[3][k] = Wc[k];
    }
    U[0] = Ui[0]; U[1] = Uf[0]; U[2] = Uo[0]; U[3] = Uc[0];
    B[0] = bi[0]; B[1] = bf[0]; B[2] = bo[0]; B[3] = bc[0];

    // sigmoid(x) = 0.5*tanh(0.5x)+0.5 -> scale i,f,o pre-activations by 0.5
    float sc[4] = {0.5f, 0.5f, 0.5f, 1.0f};
    float A[4], C[4], Y[4], R[4], Bb[4];
    for (int g = 0; g < 4; g++) {
        A[g]  = sc[g] * (W[g][0] + U[g]);
        Y[g]  = sc[g] * W[g][1];
        R[g]  = sc[g] * W[g][2];
        C[g]  = sc[g] * W[g][3];
        Bb[g] = sc[g] * B[g];
    }
    Consts cs;
    cs.A0 = A[0]; cs.A1 = A[1]; cs.A2 = A[2]; cs.A3 = A[3];
    cs.C0 = C[0]; cs.C1 = C[1]; cs.C2 = C[2]; cs.C3 = C[3];
    cs.Y0 = Y[0]; cs.Y1 = Y[1]; cs.Y2 = Y[2]; cs.Y3 = Y[3];
    cs.R0 = R[0]; cs.R1 = R[1]; cs.R2 = R[2]; cs.R3 = R[3];
    cs.B0 = Bb[0]; cs.B1 = Bb[1]; cs.B2 = Bb[2]; cs.B3 = Bb[3];
    cs.H0 = omega[0] * (1.0f - phi[0]) - alpha[0];
    cs.nK2 = -2.0f * alpha[0] * gam[0];
    cs.phi = phi[0]; cs.alpha = alpha[0]; cs.lam = lam[0];
    cs.omega = omega[0];
    cs.eta0 = (float)var;
    cs.h0   = (float)var;
    double se = sqrt(var);
    cs.z0  = (float)(((double)y[0] - (double)lam[0] * var) / se);
    cs.rs0 = (float)(1.0 / se);
    g_cs = cs;
}

// ---------------- fast approx intrinsics ----------------
__device__ __forceinline__ float tanha(float x) {
    float r; asm("tanh.approx.f32 %0, %1;" : "=f"(r) : "f"(x)); return r;
}
__device__ __forceinline__ float rsqf(float x) {
    float r; asm("rsqrt.approx.f32 %0, %1;" : "=f"(r) : "f"(x)); return r;
}
__device__ __forceinline__ float sqtf(float x) {
    float r; asm("sqrt.approx.f32 %0, %1;" : "=f"(r) : "f"(x)); return r;
}

// one LSTM step: updates (eta, c, z).
__device__ __forceinline__ void stepz(const Consts& cs,
                                      float yp, float rvp, float yt,
                                      float& eta, float& c, float& z) {
    float D0 = fmaf(cs.R0, rvp, fmaf(cs.Y0, yp, cs.B0));
    float D1 = fmaf(cs.R1, rvp, fmaf(cs.Y1, yp, cs.B1));
    float D2 = fmaf(cs.R2, rvp, fmaf(cs.Y2, yp, cs.B2));
    float D3 = fmaf(cs.R3, rvp, fmaf(cs.Y3, yp, cs.B3));
    float a0 = fmaf(cs.A0, eta, fmaf(cs.C0, z, D0));
    float a1 = fmaf(cs.A1, eta, fmaf(cs.C1, z, D1));
    float a2 = fmaf(cs.A2, eta, fmaf(cs.C2, z, D2));
    float a3 = fmaf(cs.A3, eta, fmaf(cs.C3, z, D3));
    float gg = tanha(a3);
    float i_ = fmaf(0.5f, tanha(a0), 0.5f);
    float f_ = fmaf(0.5f, tanha(a1), 0.5f);
    float o_ = fmaf(0.5f, tanha(a2), 0.5f);
    c = fmaf(f_, c, i_ * gg);
    float tc = tanha(c);
    // softplus(o*tanh(c)); |s| < 1 -> even series of log(2cosh(s/2)) + s/2
    float s = o_ * tc;
    float u = s * s;
    float p = fmaf(fmaf(3.4722222e-4f, u, -5.2083333e-3f), u, 0.125f);
    eta = fmaf(u, p, fmaf(0.5f, s, 0.69314718056f));
    z = fmaf(-cs.lam, eta, yt) * rsqf(eta);
}

struct ZC {
    float eta, c, z, yp, rvp;
    float4 ycur;
    int gb, rrel;   // rrel = gb - lo (smem rv rel index)
};

// MODE: 0 = warm (no store, no clamp), 1 = emit (store, clamp load),
//       2 = predicated (slow path)
template<int MODE>
__device__ __forceinline__ void z_iter(const Consts& cs, ZC& S,
    const float* __restrict__ y, const float* __restrict__ srv,
    float* __restrict__ zo, int t0, int tend) {
    int nb = S.gb + 4;
    if (MODE != 0) nb = (nb < tend) ? nb : S.gb;
    float4 yn = *reinterpret_cast<const float4*>(y + nb);
    int j = S.rrel + (S.rrel >> 8);
    float r0 = srv[j], r1 = srv[j + 1], r2 = srv[j + 2], r3 = srv[j + 3];
    float4 zz;
    stepz(cs, S.yp,     S.rvp, S.ycur.x, S.eta, S.c, S.z); zz.x = S.z;
    stepz(cs, S.ycur.x, r0,    S.ycur.y, S.eta, S.c, S.z); zz.y = S.z;
    stepz(cs, S.ycur.y, r1,    S.ycur.z, S.eta, S.c, S.z); zz.z = S.z;
    stepz(cs, S.ycur.z, r2,    S.ycur.w, S.eta, S.c, S.z); zz.w = S.z;
    if (MODE == 1)
        *reinterpret_cast<float4*>(zo + S.gb) = zz;
    if (MODE == 2) {
        if (S.gb >= t0 && S.gb < tend)
            *reinterpret_cast<float4*>(zo + S.gb) = zz;
    }
    S.yp = S.ycur.w; S.rvp = r3;
    S.ycur = yn;
    S.gb += 4; S.rrel += 4;
}

__device__ __forceinline__ void z_seed(const Consts& cs, ZC& S,
    const float* __restrict__ y, const float* __restrict__ srv,
    int t0, int lo) {
    S.eta = cs.eta0; S.c = 0.0f;
    int g0 = t0 - (WARM_A + 1);
    S.yp = y[g0];
    int rr = g0 - lo;
    S.rvp = srv[rr + (rr >> 8)];
    S.z = fmaf(-cs.lam, cs.eta0, S.yp) * cs.rs0;
    S.gb = g0 + 1;
    S.rrel = S.gb - lo;
    S.ycur = *reinterpret_cast<const float4*>(y + S.gb);
}

// exact-capable init (block 0 only; lo == 0 there)
__device__ __forceinline__ void z_init_any(const Consts& cs, ZC& S,
    const float* __restrict__ y, const float* __restrict__ srv,
    float* __restrict__ zo, int t0) {
    if (t0 > WARM_A) { z_seed(cs, S, y, srv, t0, 0); return; }
    S.eta = cs.eta0; S.c = 0.0f;
    S.yp = y[0]; S.rvp = srv[0]; S.z = cs.z0;
    float z1, z2, z3, yt;
    yt = y[1]; stepz(cs, S.yp, S.rvp, yt, S.eta, S.c, S.z); z1 = S.z; S.yp = yt; S.rvp = srv[1];
    yt = y[2]; stepz(cs, S.yp, S.rvp, yt, S.eta, S.c, S.z); z2 = S.z; S.yp = yt; S.rvp = srv[2];
    yt = y[3]; stepz(cs, S.yp, S.rvp, yt, S.eta, S.c, S.z); z3 = S.z; S.yp = yt; S.rvp = srv[3];
    if (t0 == 0) {
        float4 v; v.x = cs.z0; v.y = z1; v.z = z2; v.w = z3;
        *reinterpret_cast<float4*>(zo) = v;
    }
    S.gb = 4; S.rrel = 4;
    S.ycur = *reinterpret_cast<const float4*>(y + 4);
}

__global__ void __launch_bounds__(BLOCK_A)
k_main(const float* __restrict__ y, const float* __restrict__ rv,
       float* __restrict__ zo) {
    __shared__ float srv[PAD_A];
    const Consts cs = g_cs;
    const int blk0 = blockIdx.x * SPAN_A;
    int lo = blk0 - PROL_A; if (lo < 0) lo = 0;
    const int n = blk0 + SPAN_A - lo;
    for (int i = threadIdx.x * 4; i < n; i += BLOCK_A * 4) {
        float4 v = *reinterpret_cast<const float4*>(rv + lo + i);
        int j = i + (i >> 8);
        srv[j] = v.x; srv[j + 1] = v.y; srv[j + 2] = v.z; srv[j + 3] = v.w;
    }
    __syncwarp();

    int t0A = blk0 + threadIdx.x * (2 * CHUNK_A);
    int t0B = t0A + CHUNK_A;
    ZC A, B;
    if (blockIdx.x != 0) {
        z_seed(cs, A, y, srv, t0A, lo);
        z_seed(cs, B, y, srv, t0B, lo);
        #pragma unroll 2
        for (int it = 0; it < WITER_A; ++it) {
            z_iter<0>(cs, A, y, srv, zo, t0A, t0A + CHUNK_A);
            z_iter<0>(cs, B, y, srv, zo, t0B, t0B + CHUNK_A);
        }
        #pragma unroll 2
        for (int it = 0; it < EITER_A; ++it) {
            z_iter<1>(cs, A, y, srv, zo, t0A, t0A + CHUNK_A);
            z_iter<1>(cs, B, y, srv, zo, t0B, t0B + CHUNK_A);
        }
    } else {
        z_init_any(cs, A, y, srv, zo, t0A);
        z_init_any(cs, B, y, srv, zo, t0B);
        for (int it = 0; it < TRIPS_A; ++it) {
            z_iter<2>(cs, A, y, srv, zo, t0A, t0A + CHUNK_A);
            z_iter<2>(cs, B, y, srv, zo, t0B, t0B + CHUNK_A);
        }
    }
}

// one GARCH h step: h' = phi*h + H0 + alpha*z^2 + nK2*z*sqrt(h)
__device__ __forceinline__ void steph(const Consts& cs, float zp, float& h) {
    float u = fmaf(cs.alpha * zp, zp, cs.H0);
    h = fmaf(cs.phi, h, fmaf(cs.nK2 * zp, sqtf(h), u));
}

__device__ __forceinline__ int swz7(int i) { return i + (i >> 7); }

struct HC {
    float h, za, zb, zc, zd;
    int gb, zrel;   // zrel = rel index of z[gb-1]
};

template<int MODE>   // 0 warm, 1 emit, 2 predicated
__device__ __forceinline__ void h_iter(const Consts& cs, HC& S,
    const float* __restrict__ sz, float* __restrict__ ho,
    int t0, int tend) {
    int nrel = S.zrel + 4;
    if (MODE != 0) nrel = (S.gb + 4 < tend) ? nrel : S.zrel;
    float na = sz[swz7(nrel)];
    float nb = sz[swz7(nrel + 1)];
    float nc = sz[swz7(nrel + 2)];
    float nd = sz[swz7(nrel + 3)];
    float4 hh;
    steph(cs, S.za, S.h); hh.x = S.h;
    steph(cs, S.zb, S.h); hh.y = S.h;
    steph(cs, S.zc, S.h); hh.z = S.h;
    steph(cs, S.zd, S.h); hh.w = S.h;
    if (MODE == 1)
        *reinterpret_cast<float4*>(ho + S.gb) = hh;
    if (MODE == 2) {
        if (S.gb >= t0 && S.gb < tend)
            *reinterpret_cast<float4*>(ho + S.gb) = hh;
    }
    S.za = na; S.zb = nb; S.zc = nc; S.zd = nd;
    S.zrel = nrel;
    S.gb += 4;
}

__device__ __forceinline__ void h_seed(const Consts& cs, HC& S,
    const float* __restrict__ sz, int t0, int lo) {
    int g0 = t0 - WARM_B;
    S.h = cs.omega;
    int rel = g0 - lo;
    steph(cs, sz[swz7(rel)],     S.h);
    steph(cs, sz[swz7(rel + 1)], S.h);
    steph(cs, sz[swz7(rel + 2)], S.h);
    S.gb = g0 + 4;
    S.zrel = rel + 3;
    S.za = sz[swz7(S.zrel)];
    S.zb = sz[swz7(S.zrel + 1)];
    S.zc = sz[swz7(S.zrel + 2)];
    S.zd = sz[swz7(S.zrel + 3)];
}

__device__ __forceinline__ void h_init_any(const Consts& cs, HC& S,
    const float* __restrict__ sz, float* __restrict__ ho, int t0) {
    if (t0 > WARM_B) { h_seed(cs, S, sz, t0, 0); return; }
    S.h = cs.h0;
    float h1, h2, h3;
    steph(cs, sz[swz7(0)], S.h); h1 = S.h;
    steph(cs, sz[swz7(1)], S.h); h2 = S.h;
    steph(cs, sz[swz7(2)], S.h); h3 = S.h;
    if (t0 == 0) {
        float4 v; v.x = cs.h0; v.y = h1; v.z = h2; v.w = h3;
        *reinterpret_cast<float4*>(ho) = v;
    }
    S.gb = 4; S.zrel = 3;
    S.za = sz[swz7(3)];
    S.zb = sz[swz7(4)];
    S.zc = sz[swz7(5)];
    S.zd = sz[swz7(6)];
}

__global__ void __launch_bounds__(BLOCK_B)
k_hvol(const float* __restrict__ zo, float* __restrict__ ho) {
    __shared__ float sz[PAD_B];
    const Consts cs = g_cs;
    const int blk0 = blockIdx.x * SPAN_B;
    int lo = blk0 - WARM_B; if (lo < 0) lo = 0;
    const int n = blk0 + SPAN_B - lo;
    for (int i = threadIdx.x * 4; i < n; i += BLOCK_B * 4) {
        float4 v = *reinterpret_cast<const float4*>(zo + lo + i);
        int j = swz7(i);       // i%4==0 and i%128<=124 -> swz7(i+k)=swz7(i)+k
        sz[j] = v.x; sz[j + 1] = v.y; sz[j + 2] = v.z; sz[j + 3] = v.w;
    }
    __syncwarp();

    int t0A = blk0 + threadIdx.x * (2 * CHUNK_B);
    int t0B = t0A + CHUNK_B;
    HC A, B;
    if (blockIdx.x != 0) {
        h_seed(cs, A, sz, t0A, lo);
        h_seed(cs, B, sz, t0B, lo);
        #pragma unroll 4
        for (int it = 0; it < WITER_B; ++it) {
            h_iter<0>(cs, A, sz, ho, t0A, t0A + CHUNK_B);
            h_iter<0>(cs, B, sz, ho, t0B, t0B + CHUNK_B);
        }
        #pragma unroll 4
        for (int it = 0; it < EITER_B; ++it) {
            h_iter<1>(cs, A, sz, ho, t0A, t0A + CHUNK_B);
            h_iter<1>(cs, B, sz, ho, t0B, t0B + CHUNK_B);
        }
    } else {
        h_init_any(cs, A, sz, ho, t0A);
        h_init_any(cs, B, sz, ho, t0B);
        for (int it = 0; it < TRIPS_B; ++it) {
            h_iter<2>(cs, A, sz, ho, t0A, t0A + CHUNK_B);
            h_iter<2>(cs, B, sz, ho, t0B, t0B + CHUNK_B);
        }
    }
}

extern "C" void kernel_launch(void* const* d_in, const int* in_sizes, int n_in,
                              void* d_out, int out_size) {
    const float* y  = (const float*)d_in[0];
    const float* rv = (const float*)d_in[1];
    float* zo = (float*)d_out;
    float* ho = zo + T_TOTAL;

    k_reduce<<<RED_BLOCKS, RED_THREADS>>>((const float4*)y);
    k_setup<<<1, RED_BLOCKS>>>(y,
        (const float*)d_in[2],  (const float*)d_in[3],  (const float*)d_in[4],
        (const float*)d_in[5],  (const float*)d_in[6],  (const float*)d_in[7],
        (const float*)d_in[8],  (const float*)d_in[9],  (const float*)d_in[10],
        (const float*)d_in[11], (const float*)d_in[12], (const float*)d_in[13],
        (const float*)d_in[14], (const float*)d_in[15], (const float*)d_in[16],
        (const float*)d_in[17], (const float*)d_in[18]);
    k_main<<<NBLK_A, BLOCK_A>>>(y, rv, zo);
    k_hvol<<<NBLK_B, BLOCK_B>>>(zo, ho);
}

// round 7
// speedup vs baseline: 3.2392x; 1.0279x over previous
#include <cuda_runtime.h>

#define T_TOTAL 4194304
// ---- kernel A (LSTM z-chain): ILP=2 chains/thread, rv smem-staged,
//      2-deep y prefetch ----
#define CHUNK_A  128
#define WARM_A   256
#define BLOCK_A  32
#define SPAN_A   (BLOCK_A * 2 * CHUNK_A)     // 8192
#define NBLK_A   (T_TOTAL / SPAN_A)          // 512
#define PROL_A   260                         // staged lead (warm 257, 4-aligned)
#define NSTG_A   (SPAN_A + PROL_A)           // 8452
#define PAD_A    (NSTG_A + (NSTG_A >> 8))    // 8485
#define WITER_A  (WARM_A / 4)                // 64
#define EITER_A  (CHUNK_A / 4)               // 32
#define TRIPS_A  (WITER_A + EITER_A)         // 96
// ---- kernel B (GARCH h-chain): ILP=2, z smem-staged ----
#define CHUNK_B  128
#define WARM_B   576
#define BLOCK_B  32
#define SPAN_B   (BLOCK_B * 2 * CHUNK_B)     // 8192
#define NBLK_B   (T_TOTAL / SPAN_B)          // 512
#define NSTG_B   (SPAN_B + WARM_B)           // 8768
#define PAD_B    (NSTG_B + (NSTG_B >> 8))    // 8802
#define WITER_B  ((WARM_B - 4) / 4)          // 143
#define EITER_B  (CHUNK_B / 4)               // 32
#define TRIPS_B  (WITER_B + EITER_B)         // 175
// ---- reduction ----
#define RED_BLOCKS  512
#define RED_THREADS 256

struct Consts {
    float A0, A1, A2, A3;   // eta coeff per gate (scaled)
    float C0, C1, C2, C3;   // z coeff
    float Y0, Y1, Y2, Y3;   // y_prev coeff
    float R0, R1, R2, R3;   // rv_prev coeff
    float B0, B1, B2, B3;   // bias
    float H0, nK2, phi, alpha;
    float lam, eta0, h0, z0, rs0, omega;
};

__device__ Consts g_cs;
__device__ double g_psum[RED_BLOCKS];
__device__ double g_psq[RED_BLOCKS];

// ---------------- deterministic variance reduction (FP32 accumulate) -------
__global__ void __launch_bounds__(RED_THREADS)
k_reduce(const float4* __restrict__ y4) {
    float s0 = 0.f, s1 = 0.f, s2 = 0.f, s3 = 0.f;
    float q0 = 0.f, q1 = 0.f, q2 = 0.f, q3 = 0.f;
    const int stride = gridDim.x * blockDim.x;
    for (int i = blockIdx.x * blockDim.x + threadIdx.x; i < T_TOTAL / 4;
         i += stride) {
        float4 v = y4[i];
        s0 += v.x; s1 += v.y; s2 += v.z; s3 += v.w;
        q0 = fmaf(v.x, v.x, q0); q1 = fmaf(v.y, v.y, q1);
        q2 = fmaf(v.z, v.z, q2); q3 = fmaf(v.w, v.w, q3);
    }
    float ss = (s0 + s1) + (s2 + s3);
    float qq = (q0 + q1) + (q2 + q3);
    #pragma unroll
    for (int o = 16; o > 0; o >>= 1) {
        ss += __shfl_down_sync(0xffffffffu, ss, o);
        qq += __shfl_down_sync(0xffffffffu, qq, o);
    }
    __shared__ float sw[RED_THREADS / 32], qw[RED_THREADS / 32];
    int lane = threadIdx.x & 31, wid = threadIdx.x >> 5;
    if (lane == 0) { sw[wid] = ss; qw[wid] = qq; }
    __syncthreads();
    if (wid == 0) {
        float a = (lane < RED_THREADS / 32) ? sw[lane] : 0.f;
        float b = (lane < RED_THREADS / 32) ? qw[lane] : 0.f;
        #pragma unroll
        for (int o = 4; o > 0; o >>= 1) {
            a += __shfl_down_sync(0xffffffffu, a, o);
            b += __shfl_down_sync(0xffffffffu, b, o);
        }
        if (lane == 0) { g_psum[blockIdx.x] = (double)a; g_psq[blockIdx.x] = (double)b; }
    }
}

// ---------------- finalize: parallel stage-2 reduce + constant prep --------
__global__ void __launch_bounds__(RED_BLOCKS)
k_setup(
    const float* y,
    const float* Wi, const float* Ui, const float* bi,
    const float* Wf, const float* Uf, const float* bf,
    const float* Wo, const float* Uo, const float* bo,
    const float* Wc, const float* Uc, const float* bc,
    const float* omega, const float* alpha, const float* phi,
    const float* lam, const float* gam) {
    __shared__ double ss[RED_BLOCKS];
    __shared__ double sq[RED_BLOCKS];
    int t = threadIdx.x;
    ss[t] = g_psum[t];
    sq[t] = g_psq[t];
    __syncthreads();
    for (int s = RED_BLOCKS / 2; s > 0; s >>= 1) {
        if (t < s) { ss[t] += ss[t + s]; sq[t] += sq[t + s]; }
        __syncthreads();
    }
    if (t != 0) return;

    double mean = ss[0] / (double)T_TOTAL;
    double var  = sq[0] / (double)T_TOTAL - mean * mean;

    float W[4][4], U[4], B[4];
    for (int k = 0; k < 4; k++) {
        W[0][k] = Wi[k]; W[1][k] = Wf[k]; W[2][k] = Wo[k]; W[3][k] = Wc[k];
    }
    U[0] = Ui[0]; U[1] = Uf[0]; U[2] = Uo[0]; U[3] = Uc[0];
    B[0] = bi[0]; B[1] = bf[0]; B[2] = bo[0]; B[3] = bc[0];

    // sigmoid(x) = 0.5*tanh(0.5x)+0.5 -> scale i,f,o pre-activations by 0.5
    float sc[4] = {0.5f, 0.5f, 0.5f, 1.0f};
    float A[4], C[4], Y[4], R[4], Bb[4];
    for (int g = 0; g < 4; g++) {
        A[g]  = sc[g] * (W[g][0] + U[g]);
        Y[g]  = sc[g] * W[g][1];
        R[g]  = sc[g] * W[g][2];
        C[g]  = sc[g] * W[g][3];
        Bb[g] = sc[g] * B[g];
    }
    Consts cs;
    cs.A0 = A[0]; cs.A1 = A[1]; cs.A2 = A[2]; cs.A3 = A[3];
    cs.C0 = C[0]; cs.C1 = C[1]; cs.C2 = C[2]; cs.C3 = C[3];
    cs.Y0 = Y[0]; cs.Y1 = Y[1]; cs.Y2 = Y[2]; cs.Y3 = Y[3];
    cs.R0 = R[0]; cs.R1 = R[1]; cs.R2 = R[2]; cs.R3 = R[3];
    cs.B0 = Bb[0]; cs.B1 = Bb[1]; cs.B2 = Bb[2]; cs.B3 = Bb[3];
    cs.H0 = omega[0] * (1.0f - phi[0]) - alpha[0];
    cs.nK2 = -2.0f * alpha[0] * gam[0];
    cs.phi = phi[0]; cs.alpha = alpha[0]; cs.lam = lam[0];
    cs.omega = omega[0];
    cs.eta0 = (float)var;
    cs.h0   = (float)var;
    double se = sqrt(var);
    cs.z0  = (float)(((double)y[0] - (double)lam[0] * var) / se);
    cs.rs0 = (float)(1.0 / se);
    g_cs = cs;
}

// ---------------- fast approx intrinsics ----------------
__device__ __forceinline__ float tanha(float x) {
    float r; asm("tanh.approx.f32 %0, %1;" : "=f"(r) : "f"(x)); return r;
}
__device__ __forceinline__ float rsqf(float x) {
    float r; asm("rsqrt.approx.f32 %0, %1;" : "=f"(r) : "f"(x)); return r;
}
__device__ __forceinline__ float sqtf(float x) {
    float r; asm("sqrt.approx.f32 %0, %1;" : "=f"(r) : "f"(x)); return r;
}

// one LSTM step: updates (eta, c, z).
__device__ __forceinline__ void stepz(const Consts& cs,
                                      float yp, float rvp, float yt,
                                      float& eta, float& c, float& z) {
    float D0 = fmaf(cs.R0, rvp, fmaf(cs.Y0, yp, cs.B0));
    float D1 = fmaf(cs.R1, rvp, fmaf(cs.Y1, yp, cs.B1));
    float D2 = fmaf(cs.R2, rvp, fmaf(cs.Y2, yp, cs.B2));
    float D3 = fmaf(cs.R3, rvp, fmaf(cs.Y3, yp, cs.B3));
    float a0 = fmaf(cs.A0, eta, fmaf(cs.C0, z, D0));
    float a1 = fmaf(cs.A1, eta, fmaf(cs.C1, z, D1));
    float a2 = fmaf(cs.A2, eta, fmaf(cs.C2, z, D2));
    float a3 = fmaf(cs.A3, eta, fmaf(cs.C3, z, D3));
    float gg = tanha(a3);
    float i_ = fmaf(0.5f, tanha(a0), 0.5f);
    float f_ = fmaf(0.5f, tanha(a1), 0.5f);
    float o_ = fmaf(0.5f, tanha(a2), 0.5f);
    c = fmaf(f_, c, i_ * gg);
    float tc = tanha(c);
    // softplus(o*tanh(c)); |s| < 1 -> even series of log(2cosh(s/2)) + s/2
    float s = o_ * tc;
    float u = s * s;
    float p = fmaf(fmaf(3.4722222e-4f, u, -5.2083333e-3f), u, 0.125f);
    eta = fmaf(u, p, fmaf(0.5f, s, 0.69314718056f));
    z = fmaf(-cs.lam, eta, yt) * rsqf(eta);
}

struct ZC {
    float eta, c, z, yp, rvp;
    float4 ycur, ynxt;          // 2-deep y pipeline
    int gb, rrel;               // rrel = gb - lo (smem rv rel index)
};

// fast path, MODE: 0 = warm (no store, no clamp), 1 = emit (store, clamp)
template<int MODE>
__device__ __forceinline__ void z_iter(const Consts& cs, ZC& S,
    const float* __restrict__ y, const float* __restrict__ srv,
    float* __restrict__ zo, int tend) {
    int nb = S.gb + 8;
    if (MODE == 1) nb = (nb < tend) ? nb : S.gb;
    float4 yn2 = *reinterpret_cast<const float4*>(y + nb);
    int j = S.rrel + (S.rrel >> 8);
    float r0 = srv[j], r1 = srv[j + 1], r2 = srv[j + 2], r3 = srv[j + 3];
    float4 zz;
    stepz(cs, S.yp,     S.rvp, S.ycur.x, S.eta, S.c, S.z); zz.x = S.z;
    stepz(cs, S.ycur.x, r0,    S.ycur.y, S.eta, S.c, S.z); zz.y = S.z;
    stepz(cs, S.ycur.y, r1,    S.ycur.z, S.eta, S.c, S.z); zz.z = S.z;
    stepz(cs, S.ycur.z, r2,    S.ycur.w, S.eta, S.c, S.z); zz.w = S.z;
    if (MODE == 1)
        *reinterpret_cast<float4*>(zo + S.gb) = zz;
    S.yp = S.ycur.w; S.rvp = r3;
    S.ycur = S.ynxt; S.ynxt = yn2;
    S.gb += 4; S.rrel += 4;
}

// predicated slow path (block 0 only), 1-deep pipeline
__device__ __forceinline__ void z_iter_pred(const Consts& cs, ZC& S,
    const float* __restrict__ y, const float* __restrict__ srv,
    float* __restrict__ zo, int t0, int tend) {
    int nb = S.gb + 4;
    nb = (nb < tend) ? nb : S.gb;
    float4 yn = *reinterpret_cast<const float4*>(y + nb);
    int j = S.rrel + (S.rrel >> 8);
    float r0 = srv[j], r1 = srv[j + 1], r2 = srv[j + 2], r3 = srv[j + 3];
    float4 zz;
    stepz(cs, S.yp,     S.rvp, S.ycur.x, S.eta, S.c, S.z); zz.x = S.z;
    stepz(cs, S.ycur.x, r0,    S.ycur.y, S.eta, S.c, S.z); zz.y = S.z;
    stepz(cs, S.ycur.y, r1,    S.ycur.z, S.eta, S.c, S.z); zz.z = S.z;
    stepz(cs, S.ycur.z, r2,    S.ycur.w, S.eta, S.c, S.z); zz.w = S.z;
    if (S.gb >= t0 && S.gb < tend)
        *reinterpret_cast<float4*>(zo + S.gb) = zz;
    S.yp = S.ycur.w; S.rvp = r3;
    S.ycur = yn;
    S.gb += 4; S.rrel += 4;
}

__device__ __forceinline__ void z_seed(const Consts& cs, ZC& S,
    const float* __restrict__ y, const float* __restrict__ srv,
    int t0, int lo) {
    S.eta = cs.eta0; S.c = 0.0f;
    int g0 = t0 - (WARM_A + 1);
    S.yp = y[g0];
    int rr = g0 - lo;
    S.rvp = srv[rr + (rr >> 8)];
    S.z = fmaf(-cs.lam, cs.eta0, S.yp) * cs.rs0;
    S.gb = g0 + 1;
    S.rrel = S.gb - lo;
    S.ycur = *reinterpret_cast<const float4*>(y + S.gb);
    S.ynxt = *reinterpret_cast<const float4*>(y + S.gb + 4);
}

// exact-capable init (block 0 only; lo == 0 there); 1-deep (pred path)
__device__ __forceinline__ void z_init_any(const Consts& cs, ZC& S,
    const float* __restrict__ y, const float* __restrict__ srv,
    float* __restrict__ zo, int t0) {
    if (t0 > WARM_A) {
        z_seed(cs, S, y, srv, t0, 0);
        return;
    }
    S.eta = cs.eta0; S.c = 0.0f;
    S.yp = y[0]; S.rvp = srv[0]; S.z = cs.z0;
    float z1, z2, z3, yt;
    yt = y[1]; stepz(cs, S.yp, S.rvp, yt, S.eta, S.c, S.z); z1 = S.z; S.yp = yt; S.rvp = srv[1];
    yt = y[2]; stepz(cs, S.yp, S.rvp, yt, S.eta, S.c, S.z); z2 = S.z; S.yp = yt; S.rvp = srv[2];
    yt = y[3]; stepz(cs, S.yp, S.rvp, yt, S.eta, S.c, S.z); z3 = S.z; S.yp = yt; S.rvp = srv[3];
    if (t0 == 0) {
        float4 v; v.x = cs.z0; v.y = z1; v.z = z2; v.w = z3;
        *reinterpret_cast<float4*>(zo) = v;
    }
    S.gb = 4; S.rrel = 4;
    S.ycur = *reinterpret_cast<const float4*>(y + 4);
    S.ynxt = S.ycur;   // unused on pred path
}

__global__ void __launch_bounds__(BLOCK_A)
k_main(const float* __restrict__ y, const float* __restrict__ rv,
       float* __restrict__ zo) {
    __shared__ float srv[PAD_A];
    const Consts cs = g_cs;
    const int blk0 = blockIdx.x * SPAN_A;
    int lo = blk0 - PROL_A; if (lo < 0) lo = 0;
    const int n = blk0 + SPAN_A - lo;
    for (int i = threadIdx.x * 4; i < n; i += BLOCK_A * 4) {
        float4 v = *reinterpret_cast<const float4*>(rv + lo + i);
        int j = i + (i >> 8);
        srv[j] = v.x; srv[j + 1] = v.y; srv[j + 2] = v.z; srv[j + 3] = v.w;
    }
    __syncwarp();

    int t0A = blk0 + threadIdx.x * (2 * CHUNK_A);
    int t0B = t0A + CHUNK_A;
    ZC A, B;
    if (blockIdx.x != 0) {
        z_seed(cs, A, y, srv, t0A, lo);
        z_seed(cs, B, y, srv, t0B, lo);
        #pragma unroll 2
        for (int it = 0; it < WITER_A; ++it) {
            z_iter<0>(cs, A, y, srv, zo, t0A + CHUNK_A);
            z_iter<0>(cs, B, y, srv, zo, t0B + CHUNK_A);
        }
        #pragma unroll 2
        for (int it = 0; it < EITER_A; ++it) {
            z_iter<1>(cs, A, y, srv, zo, t0A + CHUNK_A);
            z_iter<1>(cs, B, y, srv, zo, t0B + CHUNK_A);
        }
    } else {
        z_init_any(cs, A, y, srv, zo, t0A);
        z_init_any(cs, B, y, srv, zo, t0B);
        for (int it = 0; it < TRIPS_A; ++it) {
            z_iter_pred(cs, A, y, srv, zo, t0A, t0A + CHUNK_A);
            z_iter_pred(cs, B, y, srv, zo, t0B, t0B + CHUNK_A);
        }
    }
}

// one GARCH h step: h' = phi*h + H0 + alpha*z^2 + nK2*z*sqrt(h)
__device__ __forceinline__ void steph(const Consts& cs, float zp, float& h) {
    float u = fmaf(cs.alpha * zp, zp, cs.H0);
    h = fmaf(cs.phi, h, fmaf(cs.nK2 * zp, sqtf(h), u));
}

__device__ __forceinline__ int swz8(int i) { return i + (i >> 8); }

struct HC {
    float h, za, zb, zc, zd;
    int gb, zrel;   // zrel = rel index of z[gb-1]
};

template<int MODE>   // 0 warm, 1 emit, 2 predicated
__device__ __forceinline__ void h_iter(const Consts& cs, HC& S,
    const float* __restrict__ sz, float* __restrict__ ho,
    int t0, int tend) {
    int nrel = S.zrel + 4;
    if (MODE != 0) nrel = (S.gb + 4 < tend) ? nrel : S.zrel;
    float na = sz[swz8(nrel)];
    float nb = sz[swz8(nrel + 1)];
    float nc = sz[swz8(nrel + 2)];
    float nd = sz[swz8(nrel + 3)];
    float4 hh;
    steph(cs, S.za, S.h); hh.x = S.h;
    steph(cs, S.zb, S.h); hh.y = S.h;
    steph(cs, S.zc, S.h); hh.z = S.h;
    steph(cs, S.zd, S.h); hh.w = S.h;
    if (MODE == 1)
        *reinterpret_cast<float4*>(ho + S.gb) = hh;
    if (MODE == 2) {
        if (S.gb >= t0 && S.gb < tend)
            *reinterpret_cast<float4*>(ho + S.gb) = hh;
    }
    S.za = na; S.zb = nb; S.zc = nc; S.zd = nd;
    S.zrel = nrel;
    S.gb += 4;
}

__device__ __forceinline__ void h_seed(const Consts& cs, HC& S,
    const float* __restrict__ sz, int t0, int lo) {
    int g0 = t0 - WARM_B;
    S.h = cs.omega;
    int rel = g0 - lo;
    steph(cs, sz[swz8(rel)],     S.h);
    steph(cs, sz[swz8(rel + 1)], S.h);
    steph(cs, sz[swz8(rel + 2)], S.h);
    S.gb = g0 + 4;
    S.zrel = rel + 3;
    S.za = sz[swz8(S.zrel)];
    S.zb = sz[swz8(S.zrel + 1)];
    S.zc = sz[swz8(S.zrel + 2)];
    S.zd = sz[swz8(S.zrel + 3)];
}

__device__ __forceinline__ void h_init_any(const Consts& cs, HC& S,
    const float* __restrict__ sz, float* __restrict__ ho, int t0) {
    if (t0 > WARM_B) { h_seed(cs, S, sz, t0, 0); return; }
    S.h = cs.h0;
    float h1, h2, h3;
    steph(cs, sz[swz8(0)], S.h); h1 = S.h;
    steph(cs, sz[swz8(1)], S.h); h2 = S.h;
    steph(cs, sz[swz8(2)], S.h); h3 = S.h;
    if (t0 == 0) {
        float4 v; v.x = cs.h0; v.y = h1; v.z = h2; v.w = h3;
        *reinterpret_cast<float4*>(ho) = v;
    }
    S.gb = 4; S.zrel = 3;
    S.za = sz[swz8(3)];
    S.zb = sz[swz8(4)];
    S.zc = sz[swz8(5)];
    S.zd = sz[swz8(6)];
}

__global__ void __launch_bounds__(BLOCK_B)
k_hvol(const float* __restrict__ zo, float* __restrict__ ho) {
    __shared__ float sz[PAD_B];
    const Consts cs = g_cs;
    const int blk0 = blockIdx.x * SPAN_B;
    int lo = blk0 - WARM_B; if (lo < 0) lo = 0;
    const int n = blk0 + SPAN_B - lo;
    for (int i = threadIdx.x * 4; i < n; i += BLOCK_B * 4) {
        float4 v = *reinterpret_cast<const float4*>(zo + lo + i);
        int j = swz8(i);       // i%4==0, i%256<=252 -> swz8(i+k)=swz8(i)+k
        sz[j] = v.x; sz[j + 1] = v.y; sz[j + 2] = v.z; sz[j + 3] = v.w;
    }
    __syncwarp();

    int t0A = blk0 + threadIdx.x * (2 * CHUNK_B);
    int t0B = t0A + CHUNK_B;
    HC A, B;
    if (blockIdx.x != 0) {
        h_seed(cs, A, sz, t0A, lo);
        h_seed(cs, B, sz, t0B, lo);
        #pragma unroll 4
        for (int it = 0; it < WITER_B; ++it) {
            h_iter<0>(cs, A, sz, ho, t0A, t0A + CHUNK_B);
            h_iter<0>(cs, B, sz, ho, t0B, t0B + CHUNK_B);
        }
        #pragma unroll 4
        for (int it = 0; it < EITER_B; ++it) {
            h_iter<1>(cs, A, sz, ho, t0A, t0A + CHUNK_B);
            h_iter<1>(cs, B, sz, ho, t0B, t0B + CHUNK_B);
        }
    } else {
        h_init_any(cs, A, sz, ho, t0A);
        h_init_any(cs, B, sz, ho, t0B);
        for (int it = 0; it < TRIPS_B; ++it) {
            h_iter<2>(cs, A, sz, ho, t0A, t0A + CHUNK_B);
            h_iter<2>(cs, B, sz, ho, t0B, t0B + CHUNK_B);
        }
    }
}

extern "C" void kernel_launch(void* const* d_in, const int* in_sizes, int n_in,
                              void* d_out, int out_size) {
    const float* y  = (const float*)d_in[0];
    const float* rv = (const float*)d_in[1];
    float* zo = (float*)d_out;
    float* ho = zo + T_TOTAL;

    k_reduce<<<RED_BLOCKS, RED_THREADS>>>((const float4*)y);
    k_setup<<<1, RED_BLOCKS>>>(y,
        (const float*)d_in[2],  (const float*)d_in[3],  (const float*)d_in[4],
        (const float*)d_in[5],  (const float*)d_in[6],  (const float*)d_in[7],
        (const float*)d_in[8],  (const float*)d_in[9],  (const float*)d_in[10],
        (const float*)d_in[11], (const float*)d_in[12], (const float*)d_in[13],
        (const float*)d_in[14], (const float*)d_in[15], (const float*)d_in[16],
        (const float*)d_in[17], (const float*)d_in[18]);
    k_main<<<NBLK_A, BLOCK_A>>>(y, rv, zo);
    k_hvol<<<NBLK_B, BLOCK_B>>>(zo, ho);
}

// round 8
// speedup vs baseline: 3.5796x; 1.1051x over previous
#include <cuda_runtime.h>

#define T_TOTAL 4194304
// ---- kernel A (LSTM z-chain): ILP=2 chains/thread, rv smem-staged ----
#define CHUNK_A  64
#define WARM_A   192
#define BLOCK_A  32
#define SPAN_A   (BLOCK_A * 2 * CHUNK_A)     // 4096
#define NBLK_A   (T_TOTAL / SPAN_A)          // 1024
#define PROL_A   196                         // staged lead (>= WARM_A+1, 4-aligned)
#define NSTG_A   (SPAN_A + PROL_A)           // 4292
#define PAD_A    (NSTG_A + (NSTG_A >> 7))    // 4325
#define WITER_A  (WARM_A / 4)                // 48
#define EITER_A  (CHUNK_A / 4)               // 16
#define TRIPS_A  (WITER_A + EITER_A)         // 64
// ---- kernel B (GARCH h-chain): ILP=2, z smem-staged ----
#define CHUNK_B  64
#define WARM_B   448
#define BLOCK_B  32
#define SPAN_B   (BLOCK_B * 2 * CHUNK_B)     // 4096
#define NBLK_B   (T_TOTAL / SPAN_B)          // 1024
#define NSTG_B   (SPAN_B + WARM_B)           // 4544
#define PAD_B    (NSTG_B + (NSTG_B >> 7))    // 4579
#define WITER_B  ((WARM_B - 4) / 4)          // 111
#define EITER_B  (CHUNK_B / 4)               // 16
#define TRIPS_B  (WITER_B + EITER_B)         // 127
// ---- reduction ----
#define RED_BLOCKS  512
#define RED_THREADS 256

struct Consts {
    float A0, A1, A2, A3;   // eta coeff per gate (scaled)
    float C0, C1, C2, C3;   // z coeff
    float Y0, Y1, Y2, Y3;   // y_prev coeff
    float R0, R1, R2, R3;   // rv_prev coeff
    float B0, B1, B2, B3;   // bias
    float H0, nK2, phi, alpha;
    float lam, eta0, h0, z0, rs0, omega;
};

__device__ Consts g_cs;
__device__ double g_psum[RED_BLOCKS];
__device__ double g_psq[RED_BLOCKS];

// ---------------- deterministic variance reduction (FP32 accumulate) -------
__global__ void __launch_bounds__(RED_THREADS)
k_reduce(const float4* __restrict__ y4) {
    float s0 = 0.f, s1 = 0.f, s2 = 0.f, s3 = 0.f;
    float q0 = 0.f, q1 = 0.f, q2 = 0.f, q3 = 0.f;
    const int stride = gridDim.x * blockDim.x;
    for (int i = blockIdx.x * blockDim.x + threadIdx.x; i < T_TOTAL / 4;
         i += stride) {
        float4 v = y4[i];
        s0 += v.x; s1 += v.y; s2 += v.z; s3 += v.w;
        q0 = fmaf(v.x, v.x, q0); q1 = fmaf(v.y, v.y, q1);
        q2 = fmaf(v.z, v.z, q2); q3 = fmaf(v.w, v.w, q3);
    }
    float ss = (s0 + s1) + (s2 + s3);
    float qq = (q0 + q1) + (q2 + q3);
    #pragma unroll
    for (int o = 16; o > 0; o >>= 1) {
        ss += __shfl_down_sync(0xffffffffu, ss, o);
        qq += __shfl_down_sync(0xffffffffu, qq, o);
    }
    __shared__ float sw[RED_THREADS / 32], qw[RED_THREADS / 32];
    int lane = threadIdx.x & 31, wid = threadIdx.x >> 5;
    if (lane == 0) { sw[wid] = ss; qw[wid] = qq; }
    __syncthreads();
    if (wid == 0) {
        float a = (lane < RED_THREADS / 32) ? sw[lane] : 0.f;
        float b = (lane < RED_THREADS / 32) ? qw[lane] : 0.f;
        #pragma unroll
        for (int o = 4; o > 0; o >>= 1) {
            a += __shfl_down_sync(0xffffffffu, a, o);
            b += __shfl_down_sync(0xffffffffu, b, o);
        }
        if (lane == 0) { g_psum[blockIdx.x] = (double)a; g_psq[blockIdx.x] = (double)b; }
    }
}

// ---------------- finalize: parallel stage-2 reduce + constant prep --------
__global__ void __launch_bounds__(RED_BLOCKS)
k_setup(
    const float* y,
    const float* Wi, const float* Ui, const float* bi,
    const float* Wf, const float* Uf, const float* bf,
    const float* Wo, const float* Uo, const float* bo,
    const float* Wc, const float* Uc, const float* bc,
    const float* omega, const float* alpha, const float* phi,
    const float* lam, const float* gam) {
    __shared__ double ss[RED_BLOCKS];
    __shared__ double sq[RED_BLOCKS];
    int t = threadIdx.x;
    ss[t] = g_psum[t];
    sq[t] = g_psq[t];
    __syncthreads();
    for (int s = RED_BLOCKS / 2; s > 0; s >>= 1) {
        if (t < s) { ss[t] += ss[t + s]; sq[t] += sq[t + s]; }
        __syncthreads();
    }
    if (t != 0) return;

    double mean = ss[0] / (double)T_TOTAL;
    double var  = sq[0] / (double)T_TOTAL - mean * mean;

    float W[4][4], U[4], B[4];
    for (int k = 0; k < 4; k++) {
        W[0][k] = Wi[k]; W[1][k] = Wf[k]; W[2][k] = Wo[k]; W[3][k] = Wc[k];
    }
    U[0] = Ui[0]; U[1] = Uf[0]; U[2] = Uo[0]; U[3] = Uc[0];
    B[0] = bi[0]; B[1] = bf[0]; B[2] = bo[0]; B[3] = bc[0];

    // sigmoid(x) = 0.5*tanh(0.5x)+0.5 -> scale i,f,o pre-activations by 0.5
    float sc[4] = {0.5f, 0.5f, 0.5f, 1.0f};
    float A[4], C[4], Y[4], R[4], Bb[4];
    for (int g = 0; g < 4; g++) {
        A[g]  = sc[g] * (W[g][0] + U[g]);
        Y[g]  = sc[g] * W[g][1];
        R[g]  = sc[g] * W[g][2];
        C[g]  = sc[g] * W[g][3];
        Bb[g] = sc[g] * B[g];
    }
    Consts cs;
    cs.A0 = A[0]; cs.A1 = A[1]; cs.A2 = A[2]; cs.A3 = A[3];
    cs.C0 = C[0]; cs.C1 = C[1]; cs.C2 = C[2]; cs.C3 = C[3];
    cs.Y0 = Y[0]; cs.Y1 = Y[1]; cs.Y2 = Y[2]; cs.Y3 = Y[3];
    cs.R0 = R[0]; cs.R1 = R[1]; cs.R2 = R[2]; cs.R3 = R[3];
    cs.B0 = Bb[0]; cs.B1 = Bb[1]; cs.B2 = Bb[2]; cs.B3 = Bb[3];
    cs.H0 = omega[0] * (1.0f - phi[0]) - alpha[0];
    cs.nK2 = -2.0f * alpha[0] * gam[0];
    cs.phi = phi[0]; cs.alpha = alpha[0]; cs.lam = lam[0];
    cs.omega = omega[0];
    cs.eta0 = (float)var;
    cs.h0   = (float)var;
    double se = sqrt(var);
    cs.z0  = (float)(((double)y[0] - (double)lam[0] * var) / se);
    cs.rs0 = (float)(1.0 / se);
    g_cs = cs;
}

// ---------------- fast approx intrinsics ----------------
__device__ __forceinline__ float tanha(float x) {
    float r; asm("tanh.approx.f32 %0, %1;" : "=f"(r) : "f"(x)); return r;
}
__device__ __forceinline__ float rsqf(float x) {
    float r; asm("rsqrt.approx.f32 %0, %1;" : "=f"(r) : "f"(x)); return r;
}
__device__ __forceinline__ float sqtf(float x) {
    float r; asm("sqrt.approx.f32 %0, %1;" : "=f"(r) : "f"(x)); return r;
}

__device__ __forceinline__ int swz7(int i) { return i + (i >> 7); }

// one LSTM step: updates (eta, c, z).
__device__ __forceinline__ void stepz(const Consts& cs,
                                      float yp, float rvp, float yt,
                                      float& eta, float& c, float& z) {
    float D0 = fmaf(cs.R0, rvp, fmaf(cs.Y0, yp, cs.B0));
    float D1 = fmaf(cs.R1, rvp, fmaf(cs.Y1, yp, cs.B1));
    float D2 = fmaf(cs.R2, rvp, fmaf(cs.Y2, yp, cs.B2));
    float D3 = fmaf(cs.R3, rvp, fmaf(cs.Y3, yp, cs.B3));
    float a0 = fmaf(cs.A0, eta, fmaf(cs.C0, z, D0));
    float a1 = fmaf(cs.A1, eta, fmaf(cs.C1, z, D1));
    float a2 = fmaf(cs.A2, eta, fmaf(cs.C2, z, D2));
    float a3 = fmaf(cs.A3, eta, fmaf(cs.C3, z, D3));
    float gg = tanha(a3);
    float i_ = fmaf(0.5f, tanha(a0), 0.5f);
    float f_ = fmaf(0.5f, tanha(a1), 0.5f);
    float o_ = fmaf(0.5f, tanha(a2), 0.5f);
    c = fmaf(f_, c, i_ * gg);
    float tc = tanha(c);
    // softplus(o*tanh(c)); |s| < 1 -> even series of log(2cosh(s/2)) + s/2
    float s = o_ * tc;
    float u = s * s;
    float p = fmaf(fmaf(3.4722222e-4f, u, -5.2083333e-3f), u, 0.125f);
    eta = fmaf(u, p, fmaf(0.5f, s, 0.69314718056f));
    z = fmaf(-cs.lam, eta, yt) * rsqf(eta);
}

struct ZC {
    float eta, c, z, yp, rvp;
    float4 ycur, ynxt;          // 2-deep y pipeline
    int gb, rrel;               // rrel = gb - lo (smem rv rel index)
};

// fast path, MODE: 0 = warm (no store, no clamp), 1 = emit (store, clamp)
template<int MODE>
__device__ __forceinline__ void z_iter(const Consts& cs, ZC& S,
    const float* __restrict__ y, const float* __restrict__ srv,
    float* __restrict__ zo, int tend) {
    int nb = S.gb + 8;
    if (MODE == 1) nb = (nb < tend) ? nb : S.gb;
    float4 yn2 = *reinterpret_cast<const float4*>(y + nb);
    int j = swz7(S.rrel);
    float r0 = srv[j], r1 = srv[j + 1], r2 = srv[j + 2], r3 = srv[j + 3];
    float4 zz;
    stepz(cs, S.yp,     S.rvp, S.ycur.x, S.eta, S.c, S.z); zz.x = S.z;
    stepz(cs, S.ycur.x, r0,    S.ycur.y, S.eta, S.c, S.z); zz.y = S.z;
    stepz(cs, S.ycur.y, r1,    S.ycur.z, S.eta, S.c, S.z); zz.z = S.z;
    stepz(cs, S.ycur.z, r2,    S.ycur.w, S.eta, S.c, S.z); zz.w = S.z;
    if (MODE == 1)
        *reinterpret_cast<float4*>(zo + S.gb) = zz;
    S.yp = S.ycur.w; S.rvp = r3;
    S.ycur = S.ynxt; S.ynxt = yn2;
    S.gb += 4; S.rrel += 4;
}

// predicated slow path (block 0 only), 1-deep pipeline
__device__ __forceinline__ void z_iter_pred(const Consts& cs, ZC& S,
    const float* __restrict__ y, const float* __restrict__ srv,
    float* __restrict__ zo, int t0, int tend) {
    int nb = S.gb + 4;
    nb = (nb < tend) ? nb : S.gb;
    float4 yn = *reinterpret_cast<const float4*>(y + nb);
    int j = swz7(S.rrel);
    float r0 = srv[j], r1 = srv[j + 1], r2 = srv[j + 2], r3 = srv[j + 3];
    float4 zz;
    stepz(cs, S.yp,     S.rvp, S.ycur.x, S.eta, S.c, S.z); zz.x = S.z;
    stepz(cs, S.ycur.x, r0,    S.ycur.y, S.eta, S.c, S.z); zz.y = S.z;
    stepz(cs, S.ycur.y, r1,    S.ycur.z, S.eta, S.c, S.z); zz.z = S.z;
    stepz(cs, S.ycur.z, r2,    S.ycur.w, S.eta, S.c, S.z); zz.w = S.z;
    if (S.gb >= t0 && S.gb < tend)
        *reinterpret_cast<float4*>(zo + S.gb) = zz;
    S.yp = S.ycur.w; S.rvp = r3;
    S.ycur = yn;
    S.gb += 4; S.rrel += 4;
}

__device__ __forceinline__ void z_seed(const Consts& cs, ZC& S,
    const float* __restrict__ y, const float* __restrict__ srv,
    int t0, int lo) {
    S.eta = cs.eta0; S.c = 0.0f;
    int g0 = t0 - (WARM_A + 1);
    S.yp = y[g0];
    int rr = g0 - lo;
    S.rvp = srv[swz7(rr)];
    S.z = fmaf(-cs.lam, cs.eta0, S.yp) * cs.rs0;
    S.gb = g0 + 1;
    S.rrel = S.gb - lo;
    S.ycur = *reinterpret_cast<const float4*>(y + S.gb);
    S.ynxt = *reinterpret_cast<const float4*>(y + S.gb + 4);
}

// exact-capable init (block 0 only; lo == 0 there); 1-deep (pred path)
__device__ __forceinline__ void z_init_any(const Consts& cs, ZC& S,
    const float* __restrict__ y, const float* __restrict__ srv,
    float* __restrict__ zo, int t0) {
    if (t0 > WARM_A) {
        z_seed(cs, S, y, srv, t0, 0);
        return;
    }
    S.eta = cs.eta0; S.c = 0.0f;
    S.yp = y[0]; S.rvp = srv[0]; S.z = cs.z0;
    float z1, z2, z3, yt;
    yt = y[1]; stepz(cs, S.yp, S.rvp, yt, S.eta, S.c, S.z); z1 = S.z; S.yp = yt; S.rvp = srv[swz7(1)];
    yt = y[2]; stepz(cs, S.yp, S.rvp, yt, S.eta, S.c, S.z); z2 = S.z; S.yp = yt; S.rvp = srv[swz7(2)];
    yt = y[3]; stepz(cs, S.yp, S.rvp, yt, S.eta, S.c, S.z); z3 = S.z; S.yp = yt; S.rvp = srv[swz7(3)];
    if (t0 == 0) {
        float4 v; v.x = cs.z0; v.y = z1; v.z = z2; v.w = z3;
        *reinterpret_cast<float4*>(zo) = v;
    }
    S.gb = 4; S.rrel = 4;
    S.ycur = *reinterpret_cast<const float4*>(y + 4);
    S.ynxt = S.ycur;   // unused on pred path
}

__global__ void __launch_bounds__(BLOCK_A)
k_main(const float* __restrict__ y, const float* __restrict__ rv,
       float* __restrict__ zo) {
    __shared__ float srv[PAD_A];
    const Consts cs = g_cs;
    const int blk0 = blockIdx.x * SPAN_A;
    int lo = blk0 - PROL_A; if (lo < 0) lo = 0;
    const int n = blk0 + SPAN_A - lo;
    for (int i = threadIdx.x * 4; i < n; i += BLOCK_A * 4) {
        float4 v = *reinterpret_cast<const float4*>(rv + lo + i);
        int j = swz7(i);       // i%4==0, i%128<=124 -> swz7(i+k)=swz7(i)+k
        srv[j] = v.x; srv[j + 1] = v.y; srv[j + 2] = v.z; srv[j + 3] = v.w;
    }
    __syncwarp();

    int t0A = blk0 + threadIdx.x * (2 * CHUNK_A);
    int t0B = t0A + CHUNK_A;
    ZC A, B;
    if (blockIdx.x != 0) {
        z_seed(cs, A, y, srv, t0A, lo);
        z_seed(cs, B, y, srv, t0B, lo);
        #pragma unroll 2
        for (int it = 0; it < WITER_A; ++it) {
            z_iter<0>(cs, A, y, srv, zo, t0A + CHUNK_A);
            z_iter<0>(cs, B, y, srv, zo, t0B + CHUNK_A);
        }
        #pragma unroll 2
        for (int it = 0; it < EITER_A; ++it) {
            z_iter<1>(cs, A, y, srv, zo, t0A + CHUNK_A);
            z_iter<1>(cs, B, y, srv, zo, t0B + CHUNK_A);
        }
    } else {
        z_init_any(cs, A, y, srv, zo, t0A);
        z_init_any(cs, B, y, srv, zo, t0B);
        for (int it = 0; it < TRIPS_A; ++it) {
            z_iter_pred(cs, A, y, srv, zo, t0A, t0A + CHUNK_A);
            z_iter_pred(cs, B, y, srv, zo, t0B, t0B + CHUNK_A);
        }
    }
}

// one GARCH h step: h' = phi*h + H0 + alpha*z^2 + nK2*z*sqrt(h)
__device__ __forceinline__ void steph(const Consts& cs, float zp, float& h) {
    float u = fmaf(cs.alpha * zp, zp, cs.H0);
    h = fmaf(cs.phi, h, fmaf(cs.nK2 * zp, sqtf(h), u));
}

struct HC {
    float h, za, zb, zc, zd;
    int gb, zrel;   // zrel = rel index of z[gb-1]
};

template<int MODE>   // 0 warm, 1 emit, 2 predicated
__device__ __forceinline__ void h_iter(const Consts& cs, HC& S,
    const float* __restrict__ sz, float* __restrict__ ho,
    int t0, int tend) {
    int nrel = S.zrel + 4;
    if (MODE != 0) nrel = (S.gb + 4 < tend) ? nrel : S.zrel;
    float na = sz[swz7(nrel)];
    float nb = sz[swz7(nrel + 1)];
    float nc = sz[swz7(nrel + 2)];
    float nd = sz[swz7(nrel + 3)];
    float4 hh;
    steph(cs, S.za, S.h); hh.x = S.h;
    steph(cs, S.zb, S.h); hh.y = S.h;
    steph(cs, S.zc, S.h); hh.z = S.h;
    steph(cs, S.zd, S.h); hh.w = S.h;
    if (MODE == 1)
        *reinterpret_cast<float4*>(ho + S.gb) = hh;
    if (MODE == 2) {
        if (S.gb >= t0 && S.gb < tend)
            *reinterpret_cast<float4*>(ho + S.gb) = hh;
    }
    S.za = na; S.zb = nb; S.zc = nc; S.zd = nd;
    S.zrel = nrel;
    S.gb += 4;
}

__device__ __forceinline__ void h_seed(const Consts& cs, HC& S,
    const float* __restrict__ sz, int t0, int lo) {
    int g0 = t0 - WARM_B;
    S.h = cs.omega;
    int rel = g0 - lo;
    steph(cs, sz[swz7(rel)],     S.h);
    steph(cs, sz[swz7(rel + 1)], S.h);
    steph(cs, sz[swz7(rel + 2)], S.h);
    S.gb = g0 + 4;
    S.zrel = rel + 3;
    S.za = sz[swz7(S.zrel)];
    S.zb = sz[swz7(S.zrel + 1)];
    S.zc = sz[swz7(S.zrel + 2)];
    S.zd = sz[swz7(S.zrel + 3)];
}

__device__ __forceinline__ void h_init_any(const Consts& cs, HC& S,
    const float* __restrict__ sz, float* __restrict__ ho, int t0) {
    if (t0 > WARM_B) { h_seed(cs, S, sz, t0, 0); return; }
    S.h = cs.h0;
    float h1, h2, h3;
    steph(cs, sz[swz7(0)], S.h); h1 = S.h;
    steph(cs, sz[swz7(1)], S.h); h2 = S.h;
    steph(cs, sz[swz7(2)], S.h); h3 = S.h;
    if (t0 == 0) {
        float4 v; v.x = cs.h0; v.y = h1; v.z = h2; v.w = h3;
        *reinterpret_cast<float4*>(ho) = v;
    }
    S.gb = 4; S.zrel = 3;
    S.za = sz[swz7(3)];
    S.zb = sz[swz7(4)];
    S.zc = sz[swz7(5)];
    S.zd = sz[swz7(6)];
}

__global__ void __launch_bounds__(BLOCK_B)
k_hvol(const float* __restrict__ zo, float* __restrict__ ho) {
    __shared__ float sz[PAD_B];
    const Consts cs = g_cs;
    const int blk0 = blockIdx.x * SPAN_B;
    int lo = blk0 - WARM_B; if (lo < 0) lo = 0;
    const int n = blk0 + SPAN_B - lo;
    for (int i = threadIdx.x * 4; i < n; i += BLOCK_B * 4) {
        float4 v = *reinterpret_cast<const float4*>(zo + lo + i);
        int j = swz7(i);
        sz[j] = v.x; sz[j + 1] = v.y; sz[j + 2] = v.z; sz[j + 3] = v.w;
    }
    __syncwarp();

    int t0A = blk0 + threadIdx.x * (2 * CHUNK_B);
    int t0B = t0A + CHUNK_B;
    HC A, B;
    if (blockIdx.x != 0) {
        h_seed(cs, A, sz, t0A, lo);
        h_seed(cs, B, sz, t0B, lo);
        #pragma unroll 4
        for (int it = 0; it < WITER_B; ++it) {
            h_iter<0>(cs, A, sz, ho, t0A, t0A + CHUNK_B);
            h_iter<0>(cs, B, sz, ho, t0B, t0B + CHUNK_B);
        }
        #pragma unroll 4
        for (int it = 0; it < EITER_B; ++it) {
            h_iter<1>(cs, A, sz, ho, t0A, t0A + CHUNK_B);
            h_iter<1>(cs, B, sz, ho, t0B, t0B + CHUNK_B);
        }
    } else {
        h_init_any(cs, A, sz, ho, t0A);
        h_init_any(cs, B, sz, ho, t0B);
        for (int it = 0; it < TRIPS_B; ++it) {
            h_iter<2>(cs, A, sz, ho, t0A, t0A + CHUNK_B);
            h_iter<2>(cs, B, sz, ho, t0B, t0B + CHUNK_B);
        }
    }
}

extern "C" void kernel_launch(void* const* d_in, const int* in_sizes, int n_in,
                              void* d_out, int out_size) {
    const float* y  = (const float*)d_in[0];
    const float* rv = (const float*)d_in[1];
    float* zo = (float*)d_out;
    float* ho = zo + T_TOTAL;

    k_reduce<<<RED_BLOCKS, RED_THREADS>>>((const float4*)y);
    k_setup<<<1, RED_BLOCKS>>>(y,
        (const float*)d_in[2],  (const float*)d_in[3],  (const float*)d_in[4],
        (const float*)d_in[5],  (const float*)d_in[6],  (const float*)d_in[7],
        (const float*)d_in[8],  (const float*)d_in[9],  (const float*)d_in[10],
        (const float*)d_in[11], (const float*)d_in[12], (const float*)d_in[13],
        (const float*)d_in[14], (const float*)d_in[15], (const float*)d_in[16],
        (const float*)d_in[17], (const float*)d_in[18]);
    k_main<<<NBLK_A, BLOCK_A>>>(y, rv, zo);
    k_hvol<<<NBLK_B, BLOCK_B>>>(zo, ho);
}

// round 9
// speedup vs baseline: 4.0843x; 1.1410x over previous
#include <cuda_runtime.h>

#define T_TOTAL 4194304
// ---- kernel A (LSTM z-chain): ILP=2 chains/thread, rv smem-staged ----
#define CHUNK_A  64
#define WARM_A   160
#define BLOCK_A  32
#define SPAN_A   (BLOCK_A * 2 * CHUNK_A)       // 4096
#define NBLK_A   (T_TOTAL / SPAN_A)            // 1024
#define PROL_A   164                           // staged lead (>= WARM_A+1, 4-aligned)
#define NSTG_A   (SPAN_A + PROL_A)             // 4260
#define PAD_A    (NSTG_A + 4 * (NSTG_A >> 7))  // 4392
#define WITER_A  (WARM_A / 4)                  // 40
#define EITER_A  (CHUNK_A / 4)                 // 16
#define TRIPS_A  (WITER_A + EITER_A)           // 56
// ---- kernel B (GARCH h-chain): ILP=2, z smem-staged ----
#define CHUNK_B  64
#define WARM_B   448
#define BLOCK_B  32
#define SPAN_B   (BLOCK_B * 2 * CHUNK_B)       // 4096
#define NBLK_B   (T_TOTAL / SPAN_B)            // 1024
#define NSTG_B   (SPAN_B + WARM_B)             // 4544
#define PAD_B    (NSTG_B + 4 * (NSTG_B >> 7))  // 4684
#define WITER_B  ((WARM_B - 4) / 4)            // 111
#define EITER_B  (CHUNK_B / 4)                 // 16
#define TRIPS_B  (WITER_B + EITER_B)           // 127
// ---- reduction ----
#define RED_BLOCKS  512
#define RED_THREADS 256

typedef unsigned long long u64;

struct Consts {
    u64 AA01, AA23;   // eta coeff pairs (scaled)
    u64 CC01, CC23;   // z coeff pairs
    u64 YY01, YY23;   // y_prev coeff pairs
    u64 RR01, RR23;   // rv_prev coeff pairs
    u64 BB01, BB23;   // bias pairs
    float H0, nK2, phi, alpha;
    float lam, eta0, h0, z0, rs0, omega;
};

__device__ Consts g_cs;
__device__ double g_psum[RED_BLOCKS];
__device__ double g_psq[RED_BLOCKS];
__device__ unsigned g_cnt = 0;

// ---------------- fast approx intrinsics ----------------
__device__ __forceinline__ float tanha(float x) {
    float r; asm("tanh.approx.f32 %0, %1;" : "=f"(r) : "f"(x)); return r;
}
__device__ __forceinline__ float rsqf(float x) {
    float r; asm("rsqrt.approx.f32 %0, %1;" : "=f"(r) : "f"(x)); return r;
}
__device__ __forceinline__ float sqtf(float x) {
    float r; asm("sqrt.approx.f32 %0, %1;" : "=f"(r) : "f"(x)); return r;
}
// ---------------- packed f32x2 helpers ----------------
__device__ __forceinline__ u64 pk2(float lo, float hi) {
    u64 r; asm("mov.b64 %0, {%1, %2};" : "=l"(r) : "f"(lo), "f"(hi)); return r;
}
__device__ __forceinline__ void upk2(u64 v, float& lo, float& hi) {
    asm("mov.b64 {%0, %1}, %2;" : "=f"(lo), "=f"(hi) : "l"(v));
}
__device__ __forceinline__ u64 fma2(u64 a, u64 b, u64 c) {
    u64 d; asm("fma.rn.f32x2 %0, %1, %2, %3;" : "=l"(d) : "l"(a), "l"(b), "l"(c));
    return d;
}
// ---------------- padded float4 smem swizzle ----------------
__device__ __forceinline__ int j4(int i) { return i + 4 * (i >> 7); }
__device__ __forceinline__ float4 ld4(const float* s, int i) {   // i % 4 == 0
    return *reinterpret_cast<const float4*>(s + j4(i));
}
__device__ __forceinline__ void st4(float* s, int i, float4 v) { // i % 4 == 0
    *reinterpret_cast<float4*>(s + j4(i)) = v;
}
__device__ __forceinline__ float ld1(const float* s, int i) { return s[j4(i)]; }

// ---------------- fused reduction + constant prep ----------------
__global__ void __launch_bounds__(RED_THREADS)
k_reduce(const float4* __restrict__ y4, const float* __restrict__ y,
    const float* Wi, const float* Ui, const float* bi,
    const float* Wf, const float* Uf, const float* bf,
    const float* Wo, const float* Uo, const float* bo,
    const float* Wc, const float* Uc, const float* bc,
    const float* omega, const float* alpha, const float* phi,
    const float* lam, const float* gam) {
    float s0 = 0.f, s1 = 0.f, s2 = 0.f, s3 = 0.f;
    float q0 = 0.f, q1 = 0.f, q2 = 0.f, q3 = 0.f;
    const int stride = gridDim.x * blockDim.x;
    for (int i = blockIdx.x * blockDim.x + threadIdx.x; i < T_TOTAL / 4;
         i += stride) {
        float4 v = y4[i];
        s0 += v.x; s1 += v.y; s2 += v.z; s3 += v.w;
        q0 = fmaf(v.x, v.x, q0); q1 = fmaf(v.y, v.y, q1);
        q2 = fmaf(v.z, v.z, q2); q3 = fmaf(v.w, v.w, q3);
    }
    float ss = (s0 + s1) + (s2 + s3);
    float qq = (q0 + q1) + (q2 + q3);
    #pragma unroll
    for (int o = 16; o > 0; o >>= 1) {
        ss += __shfl_down_sync(0xffffffffu, ss, o);
        qq += __shfl_down_sync(0xffffffffu, qq, o);
    }
    __shared__ float sw[RED_THREADS / 32], qw[RED_THREADS / 32];
    int lane = threadIdx.x & 31, wid = threadIdx.x >> 5;
    if (lane == 0) { sw[wid] = ss; qw[wid] = qq; }
    __syncthreads();
    if (wid == 0) {
        float a = (lane < RED_THREADS / 32) ? sw[lane] : 0.f;
        float b = (lane < RED_THREADS / 32) ? qw[lane] : 0.f;
        #pragma unroll
        for (int o = 4; o > 0; o >>= 1) {
            a += __shfl_down_sync(0xffffffffu, a, o);
            b += __shfl_down_sync(0xffffffffu, b, o);
        }
        if (lane == 0) { g_psum[blockIdx.x] = (double)a; g_psq[blockIdx.x] = (double)b; }
    }
    // ---- last-block finalize (threadFenceReduction pattern) ----
    __threadfence();
    __shared__ unsigned lastv;
    if (threadIdx.x == 0) lastv = atomicAdd(&g_cnt, 1u);
    __syncthreads();
    if (lastv != gridDim.x - 1) return;

    int t = threadIdx.x;
    __shared__ double ds[RED_THREADS], dq[RED_THREADS];
    ds[t] = g_psum[t] + g_psum[t + RED_THREADS];
    dq[t] = g_psq[t] + g_psq[t + RED_THREADS];
    __syncthreads();
    for (int s = RED_THREADS / 2; s > 0; s >>= 1) {
        if (t < s) { ds[t] += ds[t + s]; dq[t] += dq[t + s]; }
        __syncthreads();
    }
    if (t != 0) return;

    double mean = ds[0] / (double)T_TOTAL;
    double var  = dq[0] / (double)T_TOTAL - mean * mean;

    float W[4][4], U[4], B[4];
    for (int k = 0; k < 4; k++) {
        W[0][k] = Wi[k]; W[1][k] = Wf[k]; W[2][k] = Wo[k]; W[3][k] = Wc[k];
    }
    U[0] = Ui[0]; U[1] = Uf[0]; U[2] = Uo[0]; U[3] = Uc[0];
    B[0] = bi[0]; B[1] = bf[0]; B[2] = bo[0]; B[3] = bc[0];

    // sigmoid(x) = 0.5*tanh(0.5x)+0.5 -> scale i,f,o pre-activations by 0.5
    float sc[4] = {0.5f, 0.5f, 0.5f, 1.0f};
    float A[4], C[4], Y[4], R[4], Bb[4];
    for (int g = 0; g < 4; g++) {
        A[g]  = sc[g] * (W[g][0] + U[g]);
        Y[g]  = sc[g] * W[g][1];
        R[g]  = sc[g] * W[g][2];
        C[g]  = sc[g] * W[g][3];
        Bb[g] = sc[g] * B[g];
    }
    Consts cs;
    union PF { float2 f2; u64 u; } p;
    p.f2 = make_float2(A[0], A[1]);  cs.AA01 = p.u;
    p.f2 = make_float2(A[2], A[3]);  cs.AA23 = p.u;
    p.f2 = make_float2(C[0], C[1]);  cs.CC01 = p.u;
    p.f2 = make_float2(C[2], C[3]);  cs.CC23 = p.u;
    p.f2 = make_float2(Y[0], Y[1]);  cs.YY01 = p.u;
    p.f2 = make_float2(Y[2], Y[3]);  cs.YY23 = p.u;
    p.f2 = make_float2(R[0], R[1]);  cs.RR01 = p.u;
    p.f2 = make_float2(R[2], R[3]);  cs.RR23 = p.u;
    p.f2 = make_float2(Bb[0], Bb[1]); cs.BB01 = p.u;
    p.f2 = make_float2(Bb[2], Bb[3]); cs.BB23 = p.u;
    cs.H0 = omega[0] * (1.0f - phi[0]) - alpha[0];
    cs.nK2 = -2.0f * alpha[0] * gam[0];
    cs.phi = phi[0]; cs.alpha = alpha[0]; cs.lam = lam[0];
    cs.omega = omega[0];
    cs.eta0 = (float)var;
    cs.h0   = (float)var;
    double se = sqrt(var);
    cs.z0  = (float)(((double)y[0] - (double)lam[0] * var) / se);
    cs.rs0 = (float)(1.0 / se);
    g_cs = cs;
    g_cnt = 0;    // reset for next launch/replay
}

// one LSTM step: updates (eta, c, z).
__device__ __forceinline__ void stepz(const Consts& cs,
                                      float yp, float rvp, float yt,
                                      float& eta, float& c, float& z) {
    u64 yy = pk2(yp, yp), rr = pk2(rvp, rvp);
    u64 D01 = fma2(cs.RR01, rr, fma2(cs.YY01, yy, cs.BB01));
    u64 D23 = fma2(cs.RR23, rr, fma2(cs.YY23, yy, cs.BB23));
    u64 ee = pk2(eta, eta), zz2 = pk2(z, z);
    u64 a01 = fma2(cs.AA01, ee, fma2(cs.CC01, zz2, D01));
    u64 a23 = fma2(cs.AA23, ee, fma2(cs.CC23, zz2, D23));
    float a0, a1, a2, a3;
    upk2(a01, a0, a1); upk2(a23, a2, a3);
    float ti = tanha(a0), tf = tanha(a1), to = tanha(a2), gg = tanha(a3);
    // c' = (0.5tf+0.5)c + (0.5ti+0.5)g = 0.5*(fma(tf,c,c) + fma(ti,g,g))
    float cf = fmaf(tf, c, c);
    float cg = fmaf(ti, gg, gg);
    c = 0.5f * (cf + cg);
    float tc = tanha(c);
    // s = o*tanh(c) = 0.5w, w = fma(to,tc,tc);  eta = softplus(s)
    // eta = v*q(v) + 0.25w + ln2,  v = w^2,  q(v) = 0.25*p(v/4)
    float w = fmaf(to, tc, tc);
    float v = w * w;
    float q = fmaf(fmaf(5.4253472e-6f, v, -3.2552083e-4f), v, 0.03125f);
    eta = fmaf(v, q, fmaf(0.25f, w, 0.69314718056f));
    z = fmaf(-cs.lam, eta, yt) * rsqf(eta);
}

struct ZC {
    float eta, c, z, yp, rvp;
    float4 ycur, ynxt;          // 2-deep y pipeline
    int gb, rrel;               // rrel = gb - lo (smem rv rel index, 4-aligned)
};

// fast path, MODE: 0 = warm (no store, no clamp), 1 = emit (store, clamp)
template<int MODE>
__device__ __forceinline__ void z_iter(const Consts& cs, ZC& S,
    const float* __restrict__ y, const float* __restrict__ srv,
    float* __restrict__ zo, int tend) {
    int nb = S.gb + 8;
    if (MODE == 1) nb = (nb < tend) ? nb : S.gb;
    float4 yn2 = *reinterpret_cast<const float4*>(y + nb);
    float4 rq = ld4(srv, S.rrel);                 // rv[gb..gb+3]
    float4 zz;
    stepz(cs, S.yp,     S.rvp, S.ycur.x, S.eta, S.c, S.z); zz.x = S.z;
    stepz(cs, S.ycur.x, rq.x,  S.ycur.y, S.eta, S.c, S.z); zz.y = S.z;
    stepz(cs, S.ycur.y, rq.y,  S.ycur.z, S.eta, S.c, S.z); zz.z = S.z;
    stepz(cs, S.ycur.z, rq.z,  S.ycur.w, S.eta, S.c, S.z); zz.w = S.z;
    if (MODE == 1)
        *reinterpret_cast<float4*>(zo + S.gb) = zz;
    S.yp = S.ycur.w; S.rvp = rq.w;
    S.ycur = S.ynxt; S.ynxt = yn2;
    S.gb += 4; S.rrel += 4;
}

// predicated slow path (block 0 only), 1-deep pipeline
__device__ __forceinline__ void z_iter_pred(const Consts& cs, ZC& S,
    const float* __restrict__ y, const float* __restrict__ srv,
    float* __restrict__ zo, int t0, int tend) {
    int nb = S.gb + 4;
    nb = (nb < tend) ? nb : S.gb;
    float4 yn = *reinterpret_cast<const float4*>(y + nb);
    float4 rq = ld4(srv, S.rrel);
    float4 zz;
    stepz(cs, S.yp,     S.rvp, S.ycur.x, S.eta, S.c, S.z); zz.x = S.z;
    stepz(cs, S.ycur.x, rq.x,  S.ycur.y, S.eta, S.c, S.z); zz.y = S.z;
    stepz(cs, S.ycur.y, rq.y,  S.ycur.z, S.eta, S.c, S.z); zz.z = S.z;
    stepz(cs, S.ycur.z, rq.z,  S.ycur.w, S.eta, S.c, S.z); zz.w = S.z;
    if (S.gb >= t0 && S.gb < tend)
        *reinterpret_cast<float4*>(zo + S.gb) = zz;
    S.yp = S.ycur.w; S.rvp = rq.w;
    S.ycur = yn;
    S.gb += 4; S.rrel += 4;
}

__device__ __forceinline__ void z_seed(const Consts& cs, ZC& S,
    const float* __restrict__ y, const float* __restrict__ srv,
    int t0, int lo) {
    S.eta = cs.eta0; S.c = 0.0f;
    int g0 = t0 - (WARM_A + 1);
    S.yp = y[g0];
    S.rvp = ld1(srv, g0 - lo);
    S.z = fmaf(-cs.lam, cs.eta0, S.yp) * cs.rs0;
    S.gb = g0 + 1;                 // == t0 - WARM_A, 4-aligned
    S.rrel = S.gb - lo;
    S.ycur = *reinterpret_cast<const float4*>(y + S.gb);
    S.ynxt = *reinterpret_cast<const float4*>(y + S.gb + 4);
}

// exact-capable init (block 0 only; lo == 0 there); 1-deep (pred path)
__device__ __forceinline__ void z_init_any(const Consts& cs, ZC& S,
    const float* __restrict__ y, const float* __restrict__ srv,
    float* __restrict__ zo, int t0) {
    if (t0 > WARM_A) {
        z_seed(cs, S, y, srv, t0, 0);
        return;
    }
    S.eta = cs.eta0; S.c = 0.0f;
    S.yp = y[0]; S.rvp = srv[0]; S.z = cs.z0;
    float z1, z2, z3, yt;
    yt = y[1]; stepz(cs, S.yp, S.rvp, yt, S.eta, S.c, S.z); z1 = S.z; S.yp = yt; S.rvp = ld1(srv, 1);
    yt = y[2]; stepz(cs, S.yp, S.rvp, yt, S.eta, S.c, S.z); z2 = S.z; S.yp = yt; S.rvp = ld1(srv, 2);
    yt = y[3]; stepz(cs, S.yp, S.rvp, yt, S.eta, S.c, S.z); z3 = S.z; S.yp = yt; S.rvp = ld1(srv, 3);
    if (t0 == 0) {
        float4 v; v.x = cs.z0; v.y = z1; v.z = z2; v.w = z3;
        *reinterpret_cast<float4*>(zo) = v;
    }
    S.gb = 4; S.rrel = 4;
    S.ycur = *reinterpret_cast<const float4*>(y + 4);
    S.ynxt = S.ycur;   // unused on pred path
}

__global__ void __launch_bounds__(BLOCK_A)
k_main(const float* __restrict__ y, const float* __restrict__ rv,
       float* __restrict__ zo) {
    __shared__ alignas(16) float srv[PAD_A];
    const Consts cs = g_cs;
    const int blk0 = blockIdx.x * SPAN_A;
    int lo = blk0 - PROL_A; if (lo < 0) lo = 0;
    const int n = blk0 + SPAN_A - lo;
    for (int i = threadIdx.x * 4; i < n; i += BLOCK_A * 4) {
        float4 v = *reinterpret_cast<const float4*>(rv + lo + i);
        st4(srv, i, v);
    }
    __syncwarp();

    int t0A = blk0 + threadIdx.x * (2 * CHUNK_A);
    int t0B = t0A + CHUNK_A;
    ZC A, B;
    if (blockIdx.x != 0) {
        z_seed(cs, A, y, srv, t0A, lo);
        z_seed(cs, B, y, srv, t0B, lo);
        #pragma unroll 2
        for (int it = 0; it < WITER_A; ++it) {
            z_iter<0>(cs, A, y, srv, zo, t0A + CHUNK_A);
            z_iter<0>(cs, B, y, srv, zo, t0B + CHUNK_A);
        }
        #pragma unroll 2
        for (int it = 0; it < EITER_A; ++it) {
            z_iter<1>(cs, A, y, srv, zo, t0A + CHUNK_A);
            z_iter<1>(cs, B, y, srv, zo, t0B + CHUNK_A);
        }
    } else {
        z_init_any(cs, A, y, srv, zo, t0A);
        z_init_any(cs, B, y, srv, zo, t0B);
        for (int it = 0; it < TRIPS_A; ++it) {
            z_iter_pred(cs, A, y, srv, zo, t0A, t0A + CHUNK_A);
            z_iter_pred(cs, B, y, srv, zo, t0B, t0B + CHUNK_A);
        }
    }
}

// one GARCH h step: h' = phi*h + H0 + alpha*z^2 + nK2*z*sqrt(h)
__device__ __forceinline__ void steph(const Consts& cs, float zp, float& h) {
    float u = fmaf(cs.alpha * zp, zp, cs.H0);
    h = fmaf(cs.phi, h, fmaf(cs.nK2 * zp, sqtf(h), u));
}

struct HC {
    float h, zprev;     // zprev = z[gb-1]
    float4 cur;         // z[gb..gb+3]
    int gb, rel;        // rel = gb - lo (4-aligned)
};

template<int MODE>   // 0 warm, 1 emit, 2 predicated
__device__ __forceinline__ void h_iter(const Consts& cs, HC& S,
    const float* __restrict__ sz, float* __restrict__ ho,
    int t0, int tend) {
    int nrel = S.rel + 4;
    if (MODE != 0) nrel = (S.gb + 4 < tend) ? nrel : S.rel;
    float4 nxt = ld4(sz, nrel);
    float4 hh;
    steph(cs, S.zprev, S.h); hh.x = S.h;   // step gb   uses z[gb-1]
    steph(cs, S.cur.x, S.h); hh.y = S.h;   // step gb+1 uses z[gb]
    steph(cs, S.cur.y, S.h); hh.z = S.h;
    steph(cs, S.cur.z, S.h); hh.w = S.h;
    if (MODE == 1)
        *reinterpret_cast<float4*>(ho + S.gb) = hh;
    if (MODE == 2) {
        if (S.gb >= t0 && S.gb < tend)
            *reinterpret_cast<float4*>(ho + S.gb) = hh;
    }
    S.zprev = S.cur.w;
    S.cur = nxt;
    S.rel = nrel;
    S.gb += 4;
}

__device__ __forceinline__ void h_seed(const Consts& cs, HC& S,
    const float* __restrict__ sz, int t0, int lo) {
    int g0 = t0 - WARM_B;          // 4-aligned
    S.h = cs.omega;
    int rel0 = g0 - lo;            // 4-aligned
    float4 q0 = ld4(sz, rel0);     // z[g0..g0+3]
    steph(cs, q0.x, S.h);
    steph(cs, q0.y, S.h);
    steph(cs, q0.z, S.h);
    S.zprev = q0.w;
    S.gb = g0 + 4;
    S.rel = rel0 + 4;
    S.cur = ld4(sz, S.rel);
}

__device__ __forceinline__ void h_init_any(const Consts& cs, HC& S,
    const float* __restrict__ sz, float* __restrict__ ho, int t0) {
    if (t0 > WARM_B) { h_seed(cs, S, sz, t0, 0); return; }
    S.h = cs.h0;
    float4 q0 = ld4(sz, 0);
    float h1, h2, h3;
    steph(cs, q0.x, S.h); h1 = S.h;
    steph(cs, q0.y, S.h); h2 = S.h;
    steph(cs, q0.z, S.h); h3 = S.h;
    if (t0 == 0) {
        float4 v; v.x = cs.h0; v.y = h1; v.z = h2; v.w = h3;
        *reinterpret_cast<float4*>(ho) = v;
    }
    S.zprev = q0.w;
    S.gb = 4;
    S.rel = 4;
    S.cur = ld4(sz, 4);
}

__global__ void __launch_bounds__(BLOCK_B)
k_hvol(const float* __restrict__ zo, float* __restrict__ ho) {
    __shared__ alignas(16) float sz[PAD_B];
    const Consts cs = g_cs;
    const int blk0 = blockIdx.x * SPAN_B;
    int lo = blk0 - WARM_B; if (lo < 0) lo = 0;
    const int n = blk0 + SPAN_B - lo;
    for (int i = threadIdx.x * 4; i < n; i += BLOCK_B * 4) {
        float4 v = *reinterpret_cast<const float4*>(zo + lo + i);
        st4(sz, i, v);
    }
    __syncwarp();

    int t0A = blk0 + threadIdx.x * (2 * CHUNK_B);
    int t0B = t0A + CHUNK_B;
    HC A, B;
    if (blockIdx.x != 0) {
        h_seed(cs, A, sz, t0A, lo);
        h_seed(cs, B, sz, t0B, lo);
        #pragma unroll 4
        for (int it = 0; it < WITER_B; ++it) {
            h_iter<0>(cs, A, sz, ho, t0A, t0A + CHUNK_B);
            h_iter<0>(cs, B, sz, ho, t0B, t0B + CHUNK_B);
        }
        #pragma unroll 4
        for (int it = 0; it < EITER_B; ++it) {
            h_iter<1>(cs, A, sz, ho, t0A, t0A + CHUNK_B);
            h_iter<1>(cs, B, sz, ho, t0B, t0B + CHUNK_B);
        }
    } else {
        h_init_any(cs, A, sz, ho, t0A);
        h_init_any(cs, B, sz, ho, t0B);
        for (int it = 0; it < TRIPS_B; ++it) {
            h_iter<2>(cs, A, sz, ho, t0A, t0A + CHUNK_B);
            h_iter<2>(cs, B, sz, ho, t0B, t0B + CHUNK_B);
        }
    }
}

extern "C" void kernel_launch(void* const* d_in, const int* in_sizes, int n_in,
                              void* d_out, int out_size) {
    const float* y  = (const float*)d_in[0];
    const float* rv = (const float*)d_in[1];
    float* zo = (float*)d_out;
    float* ho = zo + T_TOTAL;

    k_reduce<<<RED_BLOCKS, RED_THREADS>>>((const float4*)y, y,
        (const float*)d_in[2],  (const float*)d_in[3],  (const float*)d_in[4],
        (const float*)d_in[5],  (const float*)d_in[6],  (const float*)d_in[7],
        (const float*)d_in[8],  (const float*)d_in[9],  (const float*)d_in[10],
        (const float*)d_in[11], (const float*)d_in[12], (const float*)d_in[13],
        (const float*)d_in[14], (const float*)d_in[15], (const float*)d_in[16],
        (const float*)d_in[17], (const float*)d_in[18]);
    k_main<<<NBLK_A, BLOCK_A>>>(y, rv, zo);
    k_hvol<<<NBLK_B, BLOCK_B>>>(zo, ho);
}

// round 10
// speedup vs baseline: 4.2146x; 1.0319x over previous
#include <cuda_runtime.h>

#define T_TOTAL 4194304
// ---- kernel A (LSTM z-chain): ILP=2 chains/thread, rv smem-staged ----
#define CHUNK_A  128
#define WARM_A   128
#define BLOCK_A  32
#define SPAN_A   (BLOCK_A * 2 * CHUNK_A)       // 8192
#define NBLK_A   (T_TOTAL / SPAN_A)            // 512
#define PROL_A   132                           // staged lead (>= WARM_A+1, 4-aligned)
#define NSTG_A   (SPAN_A + PROL_A)             // 8324
#define PAD_A    (NSTG_A + 4 * (NSTG_A >> 7))  // 8584
#define WITER_A  (WARM_A / 4)                  // 32
#define EITER_A  (CHUNK_A / 4)                 // 32
#define TRIPS_A  (WITER_A + EITER_A)           // 64
// ---- kernel B (GARCH h-chain): ILP=2, z smem-staged ----
#define CHUNK_B  64
#define WARM_B   448
#define BLOCK_B  32
#define SPAN_B   (BLOCK_B * 2 * CHUNK_B)       // 4096
#define NBLK_B   (T_TOTAL / SPAN_B)            // 1024
#define NSTG_B   (SPAN_B + WARM_B)             // 4544
#define PAD_B    (NSTG_B + 4 * (NSTG_B >> 7))  // 4684
#define WITER_B  ((WARM_B - 4) / 4)            // 111
#define EITER_B  (CHUNK_B / 4)                 // 16
#define TRIPS_B  (WITER_B + EITER_B)           // 127
// ---- reduction ----
#define RED_BLOCKS  1024
#define RED_THREADS 256
#define RED_LOADS   4   // RED_BLOCKS*RED_THREADS*RED_LOADS == T_TOTAL/4

typedef unsigned long long u64;

struct Consts {
    u64 AA01, AA23;   // eta coeff pairs (scaled)
    u64 CC01, CC23;   // z coeff pairs
    u64 YY01, YY23;   // y_prev coeff pairs
    u64 RR01, RR23;   // rv_prev coeff pairs
    u64 BB01, BB23;   // bias pairs
    float H0, nK2, phi, alpha;
    float lam, eta0, h0, z0, rs0, omega;
};

__device__ Consts g_cs;
__device__ double g_psum[RED_BLOCKS];
__device__ double g_psq[RED_BLOCKS];

// ---------------- fast approx intrinsics ----------------
__device__ __forceinline__ float tanha(float x) {
    float r; asm("tanh.approx.f32 %0, %1;" : "=f"(r) : "f"(x)); return r;
}
__device__ __forceinline__ float rsqf(float x) {
    float r; asm("rsqrt.approx.f32 %0, %1;" : "=f"(r) : "f"(x)); return r;
}
__device__ __forceinline__ float sqtf(float x) {
    float r; asm("sqrt.approx.f32 %0, %1;" : "=f"(r) : "f"(x)); return r;
}
// ---------------- packed f32x2 helpers ----------------
__device__ __forceinline__ u64 pk2(float lo, float hi) {
    u64 r; asm("mov.b64 %0, {%1, %2};" : "=l"(r) : "f"(lo), "f"(hi)); return r;
}
__device__ __forceinline__ void upk2(u64 v, float& lo, float& hi) {
    asm("mov.b64 {%0, %1}, %2;" : "=f"(lo), "=f"(hi) : "l"(v));
}
__device__ __forceinline__ u64 fma2(u64 a, u64 b, u64 c) {
    u64 d; asm("fma.rn.f32x2 %0, %1, %2, %3;" : "=l"(d) : "l"(a), "l"(b), "l"(c));
    return d;
}
// ---------------- padded float4 smem swizzle ----------------
__device__ __forceinline__ int j4(int i) { return i + 4 * (i >> 7); }
__device__ __forceinline__ float4 ld4(const float* s, int i) {   // i % 4 == 0
    return *reinterpret_cast<const float4*>(s + j4(i));
}
__device__ __forceinline__ void st4(float* s, int i, float4 v) { // i % 4 == 0
    *reinterpret_cast<float4*>(s + j4(i)) = v;
}
__device__ __forceinline__ float ld1(const float* s, int i) { return s[j4(i)]; }

// ---------------- deterministic variance reduction (MLP=4 unrolled) -------
__global__ void __launch_bounds__(RED_THREADS)
k_reduce(const float4* __restrict__ y4) {
    const int tid = blockIdx.x * RED_THREADS + threadIdx.x;
    const int stride = RED_BLOCKS * RED_THREADS;
    float4 v0 = y4[tid];
    float4 v1 = y4[tid + stride];
    float4 v2 = y4[tid + 2 * stride];
    float4 v3 = y4[tid + 3 * stride];
    float s0 = (v0.x + v0.y) + (v0.z + v0.w);
    float s1 = (v1.x + v1.y) + (v1.z + v1.w);
    float s2 = (v2.x + v2.y) + (v2.z + v2.w);
    float s3 = (v3.x + v3.y) + (v3.z + v3.w);
    float q0 = fmaf(v0.x, v0.x, v0.y * v0.y) + fmaf(v0.z, v0.z, v0.w * v0.w);
    float q1 = fmaf(v1.x, v1.x, v1.y * v1.y) + fmaf(v1.z, v1.z, v1.w * v1.w);
    float q2 = fmaf(v2.x, v2.x, v2.y * v2.y) + fmaf(v2.z, v2.z, v2.w * v2.w);
    float q3 = fmaf(v3.x, v3.x, v3.y * v3.y) + fmaf(v3.z, v3.z, v3.w * v3.w);
    float ss = (s0 + s1) + (s2 + s3);
    float qq = (q0 + q1) + (q2 + q3);
    #pragma unroll
    for (int o = 16; o > 0; o >>= 1) {
        ss += __shfl_down_sync(0xffffffffu, ss, o);
        qq += __shfl_down_sync(0xffffffffu, qq, o);
    }
    __shared__ float sw[RED_THREADS / 32], qw[RED_THREADS / 32];
    int lane = threadIdx.x & 31, wid = threadIdx.x >> 5;
    if (lane == 0) { sw[wid] = ss; qw[wid] = qq; }
    __syncthreads();
    if (wid == 0) {
        float a = (lane < RED_THREADS / 32) ? sw[lane] : 0.f;
        float b = (lane < RED_THREADS / 32) ? qw[lane] : 0.f;
        #pragma unroll
        for (int o = 4; o > 0; o >>= 1) {
            a += __shfl_down_sync(0xffffffffu, a, o);
            b += __shfl_down_sync(0xffffffffu, b, o);
        }
        if (lane == 0) { g_psum[blockIdx.x] = (double)a; g_psq[blockIdx.x] = (double)b; }
    }
}

// ---------------- stage-2 reduce + constant prep ----------------
__global__ void __launch_bounds__(RED_THREADS)
k_setup(
    const float* y,
    const float* Wi, const float* Ui, const float* bi,
    const float* Wf, const float* Uf, const float* bf,
    const float* Wo, const float* Uo, const float* bo,
    const float* Wc, const float* Uc, const float* bc,
    const float* omega, const float* alpha, const float* phi,
    const float* lam, const float* gam) {
    __shared__ double ds[RED_THREADS], dq[RED_THREADS];
    int t = threadIdx.x;
    double a = 0.0, b = 0.0;
    #pragma unroll
    for (int k = 0; k < RED_BLOCKS / RED_THREADS; k++) {
        a += g_psum[t + k * RED_THREADS];
        b += g_psq[t + k * RED_THREADS];
    }
    ds[t] = a; dq[t] = b;
    __syncthreads();
    for (int s = RED_THREADS / 2; s > 0; s >>= 1) {
        if (t < s) { ds[t] += ds[t + s]; dq[t] += dq[t + s]; }
        __syncthreads();
    }
    if (t != 0) return;

    double mean = ds[0] / (double)T_TOTAL;
    double var  = dq[0] / (double)T_TOTAL - mean * mean;

    float W[4][4], U[4], B[4];
    for (int k = 0; k < 4; k++) {
        W[0][k] = Wi[k]; W[1][k] = Wf[k]; W[2][k] = Wo[k]; W[3][k] = Wc[k];
    }
    U[0] = Ui[0]; U[1] = Uf[0]; U[2] = Uo[0]; U[3] = Uc[0];
    B[0] = bi[0]; B[1] = bf[0]; B[2] = bo[0]; B[3] = bc[0];

    // sigmoid(x) = 0.5*tanh(0.5x)+0.5 -> scale i,f,o pre-activations by 0.5
    float sc[4] = {0.5f, 0.5f, 0.5f, 1.0f};
    float A[4], C[4], Y[4], R[4], Bb[4];
    for (int g = 0; g < 4; g++) {
        A[g]  = sc[g] * (W[g][0] + U[g]);
        Y[g]  = sc[g] * W[g][1];
        R[g]  = sc[g] * W[g][2];
        C[g]  = sc[g] * W[g][3];
        Bb[g] = sc[g] * B[g];
    }
    Consts cs;
    union PF { float2 f2; u64 u; } p;
    p.f2 = make_float2(A[0], A[1]);  cs.AA01 = p.u;
    p.f2 = make_float2(A[2], A[3]);  cs.AA23 = p.u;
    p.f2 = make_float2(C[0], C[1]);  cs.CC01 = p.u;
    p.f2 = make_float2(C[2], C[3]);  cs.CC23 = p.u;
    p.f2 = make_float2(Y[0], Y[1]);  cs.YY01 = p.u;
    p.f2 = make_float2(Y[2], Y[3]);  cs.YY23 = p.u;
    p.f2 = make_float2(R[0], R[1]);  cs.RR01 = p.u;
    p.f2 = make_float2(R[2], R[3]);  cs.RR23 = p.u;
    p.f2 = make_float2(Bb[0], Bb[1]); cs.BB01 = p.u;
    p.f2 = make_float2(Bb[2], Bb[3]); cs.BB23 = p.u;
    cs.H0 = omega[0] * (1.0f - phi[0]) - alpha[0];
    cs.nK2 = -2.0f * alpha[0] * gam[0];
    cs.phi = phi[0]; cs.alpha = alpha[0]; cs.lam = lam[0];
    cs.omega = omega[0];
    cs.eta0 = (float)var;
    cs.h0   = (float)var;
    double se = sqrt(var);
    cs.z0  = (float)(((double)y[0] - (double)lam[0] * var) / se);
    cs.rs0 = (float)(1.0 / se);
    g_cs = cs;
}

// one LSTM step: updates (eta, c, z).
__device__ __forceinline__ void stepz(const Consts& cs,
                                      float yp, float rvp, float yt,
                                      float& eta, float& c, float& z) {
    u64 yy = pk2(yp, yp), rr = pk2(rvp, rvp);
    u64 D01 = fma2(cs.RR01, rr, fma2(cs.YY01, yy, cs.BB01));
    u64 D23 = fma2(cs.RR23, rr, fma2(cs.YY23, yy, cs.BB23));
    u64 ee = pk2(eta, eta), zz2 = pk2(z, z);
    u64 a01 = fma2(cs.AA01, ee, fma2(cs.CC01, zz2, D01));
    u64 a23 = fma2(cs.AA23, ee, fma2(cs.CC23, zz2, D23));
    float a0, a1, a2, a3;
    upk2(a01, a0, a1); upk2(a23, a2, a3);
    float ti = tanha(a0), tf = tanha(a1), to = tanha(a2), gg = tanha(a3);
    // c' = (0.5tf+0.5)c + (0.5ti+0.5)g = 0.5*(fma(tf,c,c) + fma(ti,g,g))
    float cf = fmaf(tf, c, c);
    float cg = fmaf(ti, gg, gg);
    c = 0.5f * (cf + cg);
    float tc = tanha(c);
    // s = o*tanh(c) = 0.5w, w = fma(to,tc,tc);  eta = softplus(s)
    float w = fmaf(to, tc, tc);
    float v = w * w;
    float q = fmaf(fmaf(5.4253472e-6f, v, -3.2552083e-4f), v, 0.03125f);
    eta = fmaf(v, q, fmaf(0.25f, w, 0.69314718056f));
    z = fmaf(-cs.lam, eta, yt) * rsqf(eta);
}

struct ZC {
    float eta, c, z, yp, rvp;
    float4 ycur, ynxt;          // 2-deep y pipeline
    int gb, rrel;               // rrel = gb - lo (smem rv rel index, 4-aligned)
};

// fast path, MODE: 0 = warm (no store, no clamp), 1 = emit (store, clamp)
template<int MODE>
__device__ __forceinline__ void z_iter(const Consts& cs, ZC& S,
    const float* __restrict__ y, const float* __restrict__ srv,
    float* __restrict__ zo, int tend) {
    int nb = S.gb + 8;
    if (MODE == 1) nb = (nb < tend) ? nb : S.gb;
    float4 yn2 = *reinterpret_cast<const float4*>(y + nb);
    float4 rq = ld4(srv, S.rrel);                 // rv[gb..gb+3]
    float4 zz;
    stepz(cs, S.yp,     S.rvp, S.ycur.x, S.eta, S.c, S.z); zz.x = S.z;
    stepz(cs, S.ycur.x, rq.x,  S.ycur.y, S.eta, S.c, S.z); zz.y = S.z;
    stepz(cs, S.ycur.y, rq.y,  S.ycur.z, S.eta, S.c, S.z); zz.z = S.z;
    stepz(cs, S.ycur.z, rq.z,  S.ycur.w, S.eta, S.c, S.z); zz.w = S.z;
    if (MODE == 1)
        *reinterpret_cast<float4*>(zo + S.gb) = zz;
    S.yp = S.ycur.w; S.rvp = rq.w;
    S.ycur = S.ynxt; S.ynxt = yn2;
    S.gb += 4; S.rrel += 4;
}

// predicated slow path (block 0 only), 1-deep pipeline
__device__ __forceinline__ void z_iter_pred(const Consts& cs, ZC& S,
    const float* __restrict__ y, const float* __restrict__ srv,
    float* __restrict__ zo, int t0, int tend) {
    int nb = S.gb + 4;
    nb = (nb < tend) ? nb : S.gb;
    float4 yn = *reinterpret_cast<const float4*>(y + nb);
    float4 rq = ld4(srv, S.rrel);
    float4 zz;
    stepz(cs, S.yp,     S.rvp, S.ycur.x, S.eta, S.c, S.z); zz.x = S.z;
    stepz(cs, S.ycur.x, rq.x,  S.ycur.y, S.eta, S.c, S.z); zz.y = S.z;
    stepz(cs, S.ycur.y, rq.y,  S.ycur.z, S.eta, S.c, S.z); zz.z = S.z;
    stepz(cs, S.ycur.z, rq.z,  S.ycur.w, S.eta, S.c, S.z); zz.w = S.z;
    if (S.gb >= t0 && S.gb < tend)
        *reinterpret_cast<float4*>(zo + S.gb) = zz;
    S.yp = S.ycur.w; S.rvp = rq.w;
    S.ycur = yn;
    S.gb += 4; S.rrel += 4;
}

__device__ __forceinline__ void z_seed(const Consts& cs, ZC& S,
    const float* __restrict__ y, const float* __restrict__ srv,
    int t0, int lo) {
    S.eta = cs.eta0; S.c = 0.0f;
    int g0 = t0 - (WARM_A + 1);
    S.yp = y[g0];
    S.rvp = ld1(srv, g0 - lo);
    S.z = fmaf(-cs.lam, cs.eta0, S.yp) * cs.rs0;
    S.gb = g0 + 1;                 // == t0 - WARM_A, 4-aligned
    S.rrel = S.gb - lo;
    S.ycur = *reinterpret_cast<const float4*>(y + S.gb);
    S.ynxt = *reinterpret_cast<const float4*>(y + S.gb + 4);
}

// exact-capable init (block 0 only; lo == 0 there); 1-deep (pred path)
__device__ __forceinline__ void z_init_any(const Consts& cs, ZC& S,
    const float* __restrict__ y, const float* __restrict__ srv,
    float* __restrict__ zo, int t0) {
    if (t0 > WARM_A) {
        z_seed(cs, S, y, srv, t0, 0);
        return;
    }
    S.eta = cs.eta0; S.c = 0.0f;
    S.yp = y[0]; S.rvp = srv[0]; S.z = cs.z0;
    float z1, z2, z3, yt;
    yt = y[1]; stepz(cs, S.yp, S.rvp, yt, S.eta, S.c, S.z); z1 = S.z; S.yp = yt; S.rvp = ld1(srv, 1);
    yt = y[2]; stepz(cs, S.yp, S.rvp, yt, S.eta, S.c, S.z); z2 = S.z; S.yp = yt; S.rvp = ld1(srv, 2);
    yt = y[3]; stepz(cs, S.yp, S.rvp, yt, S.eta, S.c, S.z); z3 = S.z; S.yp = yt; S.rvp = ld1(srv, 3);
    if (t0 == 0) {
        float4 v; v.x = cs.z0; v.y = z1; v.z = z2; v.w = z3;
        *reinterpret_cast<float4*>(zo) = v;
    }
    S.gb = 4; S.rrel = 4;
    S.ycur = *reinterpret_cast<const float4*>(y + 4);
    S.ynxt = S.ycur;   // unused on pred path
}

__global__ void __launch_bounds__(BLOCK_A)
k_main(const float* __restrict__ y, const float* __restrict__ rv,
       float* __restrict__ zo) {
    __shared__ alignas(16) float srv[PAD_A];
    const Consts cs = g_cs;
    const int blk0 = blockIdx.x * SPAN_A;
    int lo = blk0 - PROL_A; if (lo < 0) lo = 0;
    const int n = blk0 + SPAN_A - lo;
    for (int i = threadIdx.x * 4; i < n; i += BLOCK_A * 4) {
        float4 v = *reinterpret_cast<const float4*>(rv + lo + i);
        st4(srv, i, v);
    }
    __syncwarp();

    int t0A = blk0 + threadIdx.x * (2 * CHUNK_A);
    int t0B = t0A + CHUNK_A;
    ZC A, B;
    if (blockIdx.x != 0) {
        z_seed(cs, A, y, srv, t0A, lo);
        z_seed(cs, B, y, srv, t0B, lo);
        #pragma unroll 2
        for (int it = 0; it < WITER_A; ++it) {
            z_iter<0>(cs, A, y, srv, zo, t0A + CHUNK_A);
            z_iter<0>(cs, B, y, srv, zo, t0B + CHUNK_A);
        }
        #pragma unroll 2
        for (int it = 0; it < EITER_A; ++it) {
            z_iter<1>(cs, A, y, srv, zo, t0A + CHUNK_A);
            z_iter<1>(cs, B, y, srv, zo, t0B + CHUNK_A);
        }
    } else {
        z_init_any(cs, A, y, srv, zo, t0A);
        z_init_any(cs, B, y, srv, zo, t0B);
        for (int it = 0; it < TRIPS_A; ++it) {
            z_iter_pred(cs, A, y, srv, zo, t0A, t0A + CHUNK_A);
            z_iter_pred(cs, B, y, srv, zo, t0B, t0B + CHUNK_A);
        }
    }
}

// one GARCH h step: h' = phi*h + H0 + alpha*z^2 + nK2*z*sqrt(h)
__device__ __forceinline__ void steph(const Consts& cs, float zp, float& h) {
    float u = fmaf(cs.alpha * zp, zp, cs.H0);
    h = fmaf(cs.phi, h, fmaf(cs.nK2 * zp, sqtf(h), u));
}

struct HC {
    float h, zprev;     // zprev = z[gb-1]
    float4 cur;         // z[gb..gb+3]
    int gb, rel;        // rel = gb - lo (4-aligned)
};

template<int MODE>   // 0 warm, 1 emit, 2 predicated
__device__ __forceinline__ void h_iter(const Consts& cs, HC& S,
    const float* __restrict__ sz, float* __restrict__ ho,
    int t0, int tend) {
    int nrel = S.rel + 4;
    if (MODE != 0) nrel = (S.gb + 4 < tend) ? nrel : S.rel;
    float4 nxt = ld4(sz, nrel);
    float4 hh;
    steph(cs, S.zprev, S.h); hh.x = S.h;   // step gb   uses z[gb-1]
    steph(cs, S.cur.x, S.h); hh.y = S.h;   // step gb+1 uses z[gb]
    steph(cs, S.cur.y, S.h); hh.z = S.h;
    steph(cs, S.cur.z, S.h); hh.w = S.h;
    if (MODE == 1)
        *reinterpret_cast<float4*>(ho + S.gb) = hh;
    if (MODE == 2) {
        if (S.gb >= t0 && S.gb < tend)
            *reinterpret_cast<float4*>(ho + S.gb) = hh;
    }
    S.zprev = S.cur.w;
    S.cur = nxt;
    S.rel = nrel;
    S.gb += 4;
}

__device__ __forceinline__ void h_seed(const Consts& cs, HC& S,
    const float* __restrict__ sz, int t0, int lo) {
    int g0 = t0 - WARM_B;          // 4-aligned
    S.h = cs.omega;
    int rel0 = g0 - lo;            // 4-aligned
    float4 q0 = ld4(sz, rel0);     // z[g0..g0+3]
    steph(cs, q0.x, S.h);
    steph(cs, q0.y, S.h);
    steph(cs, q0.z, S.h);
    S.zprev = q0.w;
    S.gb = g0 + 4;
    S.rel = rel0 + 4;
    S.cur = ld4(sz, S.rel);
}

__device__ __forceinline__ void h_init_any(const Consts& cs, HC& S,
    const float* __restrict__ sz, float* __restrict__ ho, int t0) {
    if (t0 > WARM_B) { h_seed(cs, S, sz, t0, 0); return; }
    S.h = cs.h0;
    float4 q0 = ld4(sz, 0);
    float h1, h2, h3;
    steph(cs, q0.x, S.h); h1 = S.h;
    steph(cs, q0.y, S.h); h2 = S.h;
    steph(cs, q0.z, S.h); h3 = S.h;
    if (t0 == 0) {
        float4 v; v.x = cs.h0; v.y = h1; v.z = h2; v.w = h3;
        *reinterpret_cast<float4*>(ho) = v;
    }
    S.zprev = q0.w;
    S.gb = 4;
    S.rel = 4;
    S.cur = ld4(sz, 4);
}

__global__ void __launch_bounds__(BLOCK_B)
k_hvol(const float* __restrict__ zo, float* __restrict__ ho) {
    __shared__ alignas(16) float sz[PAD_B];
    const Consts cs = g_cs;
    const int blk0 = blockIdx.x * SPAN_B;
    int lo = blk0 - WARM_B; if (lo < 0) lo = 0;
    const int n = blk0 + SPAN_B - lo;
    for (int i = threadIdx.x * 4; i < n; i += BLOCK_B * 4) {
        float4 v = *reinterpret_cast<const float4*>(zo + lo + i);
        st4(sz, i, v);
    }
    __syncwarp();

    int t0A = blk0 + threadIdx.x * (2 * CHUNK_B);
    int t0B = t0A + CHUNK_B;
    HC A, B;
    if (blockIdx.x != 0) {
        h_seed(cs, A, sz, t0A, lo);
        h_seed(cs, B, sz, t0B, lo);
        #pragma unroll 4
        for (int it = 0; it < WITER_B; ++it) {
            h_iter<0>(cs, A, sz, ho, t0A, t0A + CHUNK_B);
            h_iter<0>(cs, B, sz, ho, t0B, t0B + CHUNK_B);
        }
        #pragma unroll 4
        for (int it = 0; it < EITER_B; ++it) {
            h_iter<1>(cs, A, sz, ho, t0A, t0A + CHUNK_B);
            h_iter<1>(cs, B, sz, ho, t0B, t0B + CHUNK_B);
        }
    } else {
        h_init_any(cs, A, sz, ho, t0A);
        h_init_any(cs, B, sz, ho, t0B);
        for (int it = 0; it < TRIPS_B; ++it) {
            h_iter<2>(cs, A, sz, ho, t0A, t0A + CHUNK_B);
            h_iter<2>(cs, B, sz, ho, t0B, t0B + CHUNK_B);
        }
    }
}

extern "C" void kernel_launch(void* const* d_in, const int* in_sizes, int n_in,
                              void* d_out, int out_size) {
    const float* y  = (const float*)d_in[0];
    const float* rv = (const float*)d_in[1];
    float* zo = (float*)d_out;
    float* ho = zo + T_TOTAL;

    k_reduce<<<RED_BLOCKS, RED_THREADS>>>((const float4*)y);
    k_setup<<<1, RED_THREADS>>>(y,
        (const float*)d_in[2],  (const float*)d_in[3],  (const float*)d_in[4],
        (const float*)d_in[5],  (const float*)d_in[6],  (const float*)d_in[7],
        (const float*)d_in[8],  (const float*)d_in[9],  (const float*)d_in[10],
        (const float*)d_in[11], (const float*)d_in[12], (const float*)d_in[13],
        (const float*)d_in[14], (const float*)d_in[15], (const float*)d_in[16],
        (const float*)d_in[17], (const float*)d_in[18]);
    k_main<<<NBLK_A, BLOCK_A>>>(y, rv, zo);
    k_hvol<<<NBLK_B, BLOCK_B>>>(zo, ho);
}

// round 11
// speedup vs baseline: 4.2248x; 1.0024x over previous
#include <cuda_runtime.h>

#define T_TOTAL 4194304
// ---- kernel A (LSTM z-chain): ILP=2 chains/thread, rv smem-staged ----
#define CHUNK_A  64
#define WARM_A   128
#define BLOCK_A  32
#define SPAN_A   (BLOCK_A * 2 * CHUNK_A)       // 4096
#define NBLK_A   (T_TOTAL / SPAN_A)            // 1024
#define PROL_A   132                           // staged lead (>= WARM_A+1, 4-aligned)
#define NSTG_A   (SPAN_A + PROL_A)             // 4228
#define PAD_A    (NSTG_A + 4 * (NSTG_A >> 7))  // lane stride 128 -> >>7 pad
#define WITER_A  (WARM_A / 4)                  // 32
#define EITER_A  (CHUNK_A / 4)                 // 16
#define TRIPS_A  (WITER_A + EITER_A)           // 48
// ---- kernel B (GARCH h-chain): ILP=4, z smem-staged ----
#define CHUNK_B  64
#define WARM_B   384
#define BLOCK_B  32
#define SPAN_B   (BLOCK_B * 4 * CHUNK_B)       // 8192
#define NBLK_B   (T_TOTAL / SPAN_B)            // 512
#define NSTG_B   (SPAN_B + WARM_B)             // 8576
#define PAD_B    (NSTG_B + 4 * (NSTG_B >> 8))  // lane stride 256 -> >>8 pad
#define WITER_B  ((WARM_B - 4) / 4)            // 95
#define EITER_B  (CHUNK_B / 4)                 // 16
#define TRIPS_B  (WITER_B + EITER_B)           // 111
// ---- reduction ----
#define RED_BLOCKS  1024
#define RED_THREADS 256

typedef unsigned long long u64;

struct Consts {
    u64 AA01, AA23;   // eta coeff pairs (scaled)
    u64 CC01, CC23;   // z coeff pairs
    u64 YY01, YY23;   // y_prev coeff pairs
    u64 RR01, RR23;   // rv_prev coeff pairs
    u64 BB01, BB23;   // bias pairs
    float H0, nK2, phi, alpha;
    float lam, eta0, h0, z0, rs0, omega;
};

__device__ Consts g_cs;
__device__ double g_psum[RED_BLOCKS];
__device__ double g_psq[RED_BLOCKS];

// ---------------- fast approx intrinsics ----------------
__device__ __forceinline__ float tanha(float x) {
    float r; asm("tanh.approx.f32 %0, %1;" : "=f"(r) : "f"(x)); return r;
}
__device__ __forceinline__ float rsqf(float x) {
    float r; asm("rsqrt.approx.f32 %0, %1;" : "=f"(r) : "f"(x)); return r;
}
__device__ __forceinline__ float sqtf(float x) {
    float r; asm("sqrt.approx.f32 %0, %1;" : "=f"(r) : "f"(x)); return r;
}
// ---------------- packed f32x2 helpers ----------------
__device__ __forceinline__ u64 pk2(float lo, float hi) {
    u64 r; asm("mov.b64 %0, {%1, %2};" : "=l"(r) : "f"(lo), "f"(hi)); return r;
}
__device__ __forceinline__ void upk2(u64 v, float& lo, float& hi) {
    asm("mov.b64 {%0, %1}, %2;" : "=f"(lo), "=f"(hi) : "l"(v));
}
__device__ __forceinline__ u64 fma2(u64 a, u64 b, u64 c) {
    u64 d; asm("fma.rn.f32x2 %0, %1, %2, %3;" : "=l"(d) : "l"(a), "l"(b), "l"(c));
    return d;
}
// ---------------- padded float4 smem swizzles (stride-matched) -------------
// lane stride 128 floats: pad 16B per 128 -> bank stride 132 (4 mod 32, odd*4)
__device__ __forceinline__ int jA(int i) { return i + 4 * (i >> 7); }
// lane stride 256 floats: pad 16B per 256 -> bank stride 260 (4 mod 32, odd*4)
__device__ __forceinline__ int jB(int i) { return i + 4 * (i >> 8); }

__device__ __forceinline__ float4 ld4A(const float* s, int i) {
    return *reinterpret_cast<const float4*>(s + jA(i));
}
__device__ __forceinline__ void st4A(float* s, int i, float4 v) {
    *reinterpret_cast<float4*>(s + jA(i)) = v;
}
__device__ __forceinline__ float ld1A(const float* s, int i) { return s[jA(i)]; }
__device__ __forceinline__ float4 ld4B(const float* s, int i) {
    return *reinterpret_cast<const float4*>(s + jB(i));
}
__device__ __forceinline__ void st4B(float* s, int i, float4 v) {
    *reinterpret_cast<float4*>(s + jB(i)) = v;
}

// ---------------- deterministic variance reduction (MLP=4 unrolled) -------
__global__ void __launch_bounds__(RED_THREADS)
k_reduce(const float4* __restrict__ y4) {
    const int tid = blockIdx.x * RED_THREADS + threadIdx.x;
    const int stride = RED_BLOCKS * RED_THREADS;
    float4 v0 = y4[tid];
    float4 v1 = y4[tid + stride];
    float4 v2 = y4[tid + 2 * stride];
    float4 v3 = y4[tid + 3 * stride];
    float s0 = (v0.x + v0.y) + (v0.z + v0.w);
    float s1 = (v1.x + v1.y) + (v1.z + v1.w);
    float s2 = (v2.x + v2.y) + (v2.z + v2.w);
    float s3 = (v3.x + v3.y) + (v3.z + v3.w);
    float q0 = fmaf(v0.x, v0.x, v0.y * v0.y) + fmaf(v0.z, v0.z, v0.w * v0.w);
    float q1 = fmaf(v1.x, v1.x, v1.y * v1.y) + fmaf(v1.z, v1.z, v1.w * v1.w);
    float q2 = fmaf(v2.x, v2.x, v2.y * v2.y) + fmaf(v2.z, v2.z, v2.w * v2.w);
    float q3 = fmaf(v3.x, v3.x, v3.y * v3.y) + fmaf(v3.z, v3.z, v3.w * v3.w);
    float ss = (s0 + s1) + (s2 + s3);
    float qq = (q0 + q1) + (q2 + q3);
    #pragma unroll
    for (int o = 16; o > 0; o >>= 1) {
        ss += __shfl_down_sync(0xffffffffu, ss, o);
        qq += __shfl_down_sync(0xffffffffu, qq, o);
    }
    __shared__ float sw[RED_THREADS / 32], qw[RED_THREADS / 32];
    int lane = threadIdx.x & 31, wid = threadIdx.x >> 5;
    if (lane == 0) { sw[wid] = ss; qw[wid] = qq; }
    __syncthreads();
    if (wid == 0) {
        float a = (lane < RED_THREADS / 32) ? sw[lane] : 0.f;
        float b = (lane < RED_THREADS / 32) ? qw[lane] : 0.f;
        #pragma unroll
        for (int o = 4; o > 0; o >>= 1) {
            a += __shfl_down_sync(0xffffffffu, a, o);
            b += __shfl_down_sync(0xffffffffu, b, o);
        }
        if (lane == 0) { g_psum[blockIdx.x] = (double)a; g_psq[blockIdx.x] = (double)b; }
    }
}

// ---------------- stage-2 reduce + constant prep ----------------
__global__ void __launch_bounds__(RED_THREADS)
k_setup(
    const float* y,
    const float* Wi, const float* Ui, const float* bi,
    const float* Wf, const float* Uf, const float* bf,
    const float* Wo, const float* Uo, const float* bo,
    const float* Wc, const float* Uc, const float* bc,
    const float* omega, const float* alpha, const float* phi,
    const float* lam, const float* gam) {
    __shared__ double ds[RED_THREADS], dq[RED_THREADS];
    int t = threadIdx.x;
    double a = 0.0, b = 0.0;
    #pragma unroll
    for (int k = 0; k < RED_BLOCKS / RED_THREADS; k++) {
        a += g_psum[t + k * RED_THREADS];
        b += g_psq[t + k * RED_THREADS];
    }
    ds[t] = a; dq[t] = b;
    __syncthreads();
    for (int s = RED_THREADS / 2; s > 0; s >>= 1) {
        if (t < s) { ds[t] += ds[t + s]; dq[t] += dq[t + s]; }
        __syncthreads();
    }
    if (t != 0) return;

    double mean = ds[0] / (double)T_TOTAL;
    double var  = dq[0] / (double)T_TOTAL - mean * mean;

    float W[4][4], U[4], B[4];
    for (int k = 0; k < 4; k++) {
        W[0][k] = Wi[k]; W[1][k] = Wf[k]; W[2][k] = Wo[k]; W[3][k] = Wc[k];
    }
    U[0] = Ui[0]; U[1] = Uf[0]; U[2] = Uo[0]; U[3] = Uc[0];
    B[0] = bi[0]; B[1] = bf[0]; B[2] = bo[0]; B[3] = bc[0];

    // sigmoid(x) = 0.5*tanh(0.5x)+0.5 -> scale i,f,o pre-activations by 0.5
    float sc[4] = {0.5f, 0.5f, 0.5f, 1.0f};
    float A[4], C[4], Y[4], R[4], Bb[4];
    for (int g = 0; g < 4; g++) {
        A[g]  = sc[g] * (W[g][0] + U[g]);
        Y[g]  = sc[g] * W[g][1];
        R[g]  = sc[g] * W[g][2];
        C[g]  = sc[g] * W[g][3];
        Bb[g] = sc[g] * B[g];
    }
    Consts cs;
    union PF { float2 f2; u64 u; } p;
    p.f2 = make_float2(A[0], A[1]);  cs.AA01 = p.u;
    p.f2 = make_float2(A[2], A[3]);  cs.AA23 = p.u;
    p.f2 = make_float2(C[0], C[1]);  cs.CC01 = p.u;
    p.f2 = make_float2(C[2], C[3]);  cs.CC23 = p.u;
    p.f2 = make_float2(Y[0], Y[1]);  cs.YY01 = p.u;
    p.f2 = make_float2(Y[2], Y[3]);  cs.YY23 = p.u;
    p.f2 = make_float2(R[0], R[1]);  cs.RR01 = p.u;
    p.f2 = make_float2(R[2], R[3]);  cs.RR23 = p.u;
    p.f2 = make_float2(Bb[0], Bb[1]); cs.BB01 = p.u;
    p.f2 = make_float2(Bb[2], Bb[3]); cs.BB23 = p.u;
    cs.H0 = omega[0] * (1.0f - phi[0]) - alpha[0];
    cs.nK2 = -2.0f * alpha[0] * gam[0];
    cs.phi = phi[0]; cs.alpha = alpha[0]; cs.lam = lam[0];
    cs.omega = omega[0];
    cs.eta0 = (float)var;
    cs.h0   = (float)var;
    double se = sqrt(var);
    cs.z0  = (float)(((double)y[0] - (double)lam[0] * var) / se);
    cs.rs0 = (float)(1.0 / se);
    g_cs = cs;
}

// one LSTM step: updates (eta, c, z).
__device__ __forceinline__ void stepz(const Consts& cs,
                                      float yp, float rvp, float yt,
                                      float& eta, float& c, float& z) {
    u64 yy = pk2(yp, yp), rr = pk2(rvp, rvp);
    u64 D01 = fma2(cs.RR01, rr, fma2(cs.YY01, yy, cs.BB01));
    u64 D23 = fma2(cs.RR23, rr, fma2(cs.YY23, yy, cs.BB23));
    u64 ee = pk2(eta, eta), zz2 = pk2(z, z);
    u64 a01 = fma2(cs.AA01, ee, fma2(cs.CC01, zz2, D01));
    u64 a23 = fma2(cs.AA23, ee, fma2(cs.CC23, zz2, D23));
    float a0, a1, a2, a3;
    upk2(a01, a0, a1); upk2(a23, a2, a3);
    float ti = tanha(a0), tf = tanha(a1), to = tanha(a2), gg = tanha(a3);
    float cf = fmaf(tf, c, c);
    float cg = fmaf(ti, gg, gg);
    c = 0.5f * (cf + cg);
    float tc = tanha(c);
    float w = fmaf(to, tc, tc);
    float v = w * w;
    float q = fmaf(fmaf(5.4253472e-6f, v, -3.2552083e-4f), v, 0.03125f);
    eta = fmaf(v, q, fmaf(0.25f, w, 0.69314718056f));
    z = fmaf(-cs.lam, eta, yt) * rsqf(eta);
}

struct ZC {
    float eta, c, z, yp, rvp;
    float4 ycur, ynxt;          // 2-deep y pipeline
    int gb, rrel;               // rrel = gb - lo (smem rv rel index, 4-aligned)
};

// fast path, MODE: 0 = warm (no store, no clamp), 1 = emit (store, clamp)
template<int MODE>
__device__ __forceinline__ void z_iter(const Consts& cs, ZC& S,
    const float* __restrict__ y, const float* __restrict__ srv,
    float* __restrict__ zo, int tend) {
    int nb = S.gb + 8;
    if (MODE == 1) nb = (nb < tend) ? nb : S.gb;
    float4 yn2 = *reinterpret_cast<const float4*>(y + nb);
    float4 rq = ld4A(srv, S.rrel);                 // rv[gb..gb+3]
    float4 zz;
    stepz(cs, S.yp,     S.rvp, S.ycur.x, S.eta, S.c, S.z); zz.x = S.z;
    stepz(cs, S.ycur.x, rq.x,  S.ycur.y, S.eta, S.c, S.z); zz.y = S.z;
    stepz(cs, S.ycur.y, rq.y,  S.ycur.z, S.eta, S.c, S.z); zz.z = S.z;
    stepz(cs, S.ycur.z, rq.z,  S.ycur.w, S.eta, S.c, S.z); zz.w = S.z;
    if (MODE == 1)
        *reinterpret_cast<float4*>(zo + S.gb) = zz;
    S.yp = S.ycur.w; S.rvp = rq.w;
    S.ycur = S.ynxt; S.ynxt = yn2;
    S.gb += 4; S.rrel += 4;
}

// predicated slow path (block 0 only), 1-deep pipeline
__device__ __forceinline__ void z_iter_pred(const Consts& cs, ZC& S,
    const float* __restrict__ y, const float* __restrict__ srv,
    float* __restrict__ zo, int t0, int tend) {
    int nb = S.gb + 4;
    nb = (nb < tend) ? nb : S.gb;
    float4 yn = *reinterpret_cast<const float4*>(y + nb);
    float4 rq = ld4A(srv, S.rrel);
    float4 zz;
    stepz(cs, S.yp,     S.rvp, S.ycur.x, S.eta, S.c, S.z); zz.x = S.z;
    stepz(cs, S.ycur.x, rq.x,  S.ycur.y, S.eta, S.c, S.z); zz.y = S.z;
    stepz(cs, S.ycur.y, rq.y,  S.ycur.z, S.eta, S.c, S.z); zz.z = S.z;
    stepz(cs, S.ycur.z, rq.z,  S.ycur.w, S.eta, S.c, S.z); zz.w = S.z;
    if (S.gb >= t0 && S.gb < tend)
        *reinterpret_cast<float4*>(zo + S.gb) = zz;
    S.yp = S.ycur.w; S.rvp = rq.w;
    S.ycur = yn;
    S.gb += 4; S.rrel += 4;
}

__device__ __forceinline__ void z_seed(const Consts& cs, ZC& S,
    const float* __restrict__ y, const float* __restrict__ srv,
    int t0, int lo) {
    S.eta = cs.eta0; S.c = 0.0f;
    int g0 = t0 - (WARM_A + 1);
    S.yp = y[g0];
    S.rvp = ld1A(srv, g0 - lo);
    S.z = fmaf(-cs.lam, cs.eta0, S.yp) * cs.rs0;
    S.gb = g0 + 1;                 // == t0 - WARM_A, 4-aligned
    S.rrel = S.gb - lo;
    S.ycur = *reinterpret_cast<const float4*>(y + S.gb);
    S.ynxt = *reinterpret_cast<const float4*>(y + S.gb + 4);
}

// exact-capable init (block 0 only; lo == 0 there); 1-deep (pred path)
__device__ __forceinline__ void z_init_any(const Consts& cs, ZC& S,
    const float* __restrict__ y, const float* __restrict__ srv,
    float* __restrict__ zo, int t0) {
    if (t0 > WARM_A) {
        z_seed(cs, S, y, srv, t0, 0);
        return;
    }
    S.eta = cs.eta0; S.c = 0.0f;
    S.yp = y[0]; S.rvp = srv[0]; S.z = cs.z0;
    float z1, z2, z3, yt;
    yt = y[1]; stepz(cs, S.yp, S.rvp, yt, S.eta, S.c, S.z); z1 = S.z; S.yp = yt; S.rvp = ld1A(srv, 1);
    yt = y[2]; stepz(cs, S.yp, S.rvp, yt, S.eta, S.c, S.z); z2 = S.z; S.yp = yt; S.rvp = ld1A(srv, 2);
    yt = y[3]; stepz(cs, S.yp, S.rvp, yt, S.eta, S.c, S.z); z3 = S.z; S.yp = yt; S.rvp = ld1A(srv, 3);
    if (t0 == 0) {
        float4 v; v.x = cs.z0; v.y = z1; v.z = z2; v.w = z3;
        *reinterpret_cast<float4*>(zo) = v;
    }
    S.gb = 4; S.rrel = 4;
    S.ycur = *reinterpret_cast<const float4*>(y + 4);
    S.ynxt = S.ycur;   // unused on pred path
}

__global__ void __launch_bounds__(BLOCK_A)
k_main(const float* __restrict__ y, const float* __restrict__ rv,
       float* __restrict__ zo) {
    __shared__ alignas(16) float srv[PAD_A];
    const Consts cs = g_cs;
    const int blk0 = blockIdx.x * SPAN_A;
    int lo = blk0 - PROL_A; if (lo < 0) lo = 0;
    const int n = blk0 + SPAN_A - lo;
    for (int i = threadIdx.x * 4; i < n; i += BLOCK_A * 4) {
        float4 v = *reinterpret_cast<const float4*>(rv + lo + i);
        st4A(srv, i, v);
    }
    __syncwarp();

    int t0A = blk0 + threadIdx.x * (2 * CHUNK_A);
    int t0B = t0A + CHUNK_A;
    ZC A, B;
    if (blockIdx.x != 0) {
        z_seed(cs, A, y, srv, t0A, lo);
        z_seed(cs, B, y, srv, t0B, lo);
        #pragma unroll 2
        for (int it = 0; it < WITER_A; ++it) {
            z_iter<0>(cs, A, y, srv, zo, t0A + CHUNK_A);
            z_iter<0>(cs, B, y, srv, zo, t0B + CHUNK_A);
        }
        #pragma unroll 2
        for (int it = 0; it < EITER_A; ++it) {
            z_iter<1>(cs, A, y, srv, zo, t0A + CHUNK_A);
            z_iter<1>(cs, B, y, srv, zo, t0B + CHUNK_A);
        }
    } else {
        z_init_any(cs, A, y, srv, zo, t0A);
        z_init_any(cs, B, y, srv, zo, t0B);
        for (int it = 0; it < TRIPS_A; ++it) {
            z_iter_pred(cs, A, y, srv, zo, t0A, t0A + CHUNK_A);
            z_iter_pred(cs, B, y, srv, zo, t0B, t0B + CHUNK_A);
        }
    }
}

// one GARCH h step: h' = phi*h + H0 + alpha*z^2 + nK2*z*sqrt(h)
__device__ __forceinline__ void steph(const Consts& cs, float zp, float& h) {
    float u = fmaf(cs.alpha * zp, zp, cs.H0);
    h = fmaf(cs.phi, h, fmaf(cs.nK2 * zp, sqtf(h), u));
}

struct HC {
    float h, zprev;     // zprev = z[gb-1]
    float4 cur;         // z[gb..gb+3]
    int gb, rel;        // rel = gb - lo (4-aligned)
};

template<int MODE>   // 0 warm, 1 emit, 2 predicated
__device__ __forceinline__ void h_iter(const Consts& cs, HC& S,
    const float* __restrict__ sz, float* __restrict__ ho,
    int t0, int tend) {
    int nrel = S.rel + 4;
    if (MODE != 0) nrel = (S.gb + 4 < tend) ? nrel : S.rel;
    float4 nxt = ld4B(sz, nrel);
    float4 hh;
    steph(cs, S.zprev, S.h); hh.x = S.h;   // step gb   uses z[gb-1]
    steph(cs, S.cur.x, S.h); hh.y = S.h;
    steph(cs, S.cur.y, S.h); hh.z = S.h;
    steph(cs, S.cur.z, S.h); hh.w = S.h;
    if (MODE == 1)
        *reinterpret_cast<float4*>(ho + S.gb) = hh;
    if (MODE == 2) {
        if (S.gb >= t0 && S.gb < tend)
            *reinterpret_cast<float4*>(ho + S.gb) = hh;
    }
    S.zprev = S.cur.w;
    S.cur = nxt;
    S.rel = nrel;
    S.gb += 4;
}

__device__ __forceinline__ void h_seed(const Consts& cs, HC& S,
    const float* __restrict__ sz, int t0, int lo) {
    int g0 = t0 - WARM_B;          // 4-aligned
    S.h = cs.omega;
    int rel0 = g0 - lo;            // 4-aligned
    float4 q0 = ld4B(sz, rel0);    // z[g0..g0+3]
    steph(cs, q0.x, S.h);
    steph(cs, q0.y, S.h);
    steph(cs, q0.z, S.h);
    S.zprev = q0.w;
    S.gb = g0 + 4;
    S.rel = rel0 + 4;
    S.cur = ld4B(sz, S.rel);
}

__device__ __forceinline__ void h_init_any(const Consts& cs, HC& S,
    const float* __restrict__ sz, float* __restrict__ ho, int t0) {
    if (t0 > WARM_B) { h_seed(cs, S, sz, t0, 0); return; }
    S.h = cs.h0;
    float4 q0 = ld4B(sz, 0);
    float h1, h2, h3;
    steph(cs, q0.x, S.h); h1 = S.h;
    steph(cs, q0.y, S.h); h2 = S.h;
    steph(cs, q0.z, S.h); h3 = S.h;
    if (t0 == 0) {
        float4 v; v.x = cs.h0; v.y = h1; v.z = h2; v.w = h3;
        *reinterpret_cast<float4*>(ho) = v;
    }
    S.zprev = q0.w;
    S.gb = 4;
    S.rel = 4;
    S.cur = ld4B(sz, 4);
}

__global__ void __launch_bounds__(BLOCK_B)
k_hvol(const float* __restrict__ zo, float* __restrict__ ho) {
    __shared__ alignas(16) float sz[PAD_B];
    const Consts cs = g_cs;
    const int blk0 = blockIdx.x * SPAN_B;
    int lo = blk0 - WARM_B; if (lo < 0) lo = 0;
    const int n = blk0 + SPAN_B - lo;
    for (int i = threadIdx.x * 4; i < n; i += BLOCK_B * 4) {
        float4 v = *reinterpret_cast<const float4*>(zo + lo + i);
        st4B(sz, i, v);
    }
    __syncwarp();

    // 4 chains per thread (ILP=4)
    int t0A = blk0 + threadIdx.x * (4 * CHUNK_B);
    int t0B = t0A + CHUNK_B;
    int t0C = t0B + CHUNK_B;
    int t0D = t0C + CHUNK_B;
    HC A, B, C, D;
    if (blockIdx.x != 0) {
        h_seed(cs, A, sz, t0A, lo);
        h_seed(cs, B, sz, t0B, lo);
        h_seed(cs, C, sz, t0C, lo);
        h_seed(cs, D, sz, t0D, lo);
        #pragma unroll 2
        for (int it = 0; it < WITER_B; ++it) {
            h_iter<0>(cs, A, sz, ho, t0A, t0A + CHUNK_B);
            h_iter<0>(cs, B, sz, ho, t0B, t0B + CHUNK_B);
            h_iter<0>(cs, C, sz, ho, t0C, t0C + CHUNK_B);
            h_iter<0>(cs, D, sz, ho, t0D, t0D + CHUNK_B);
        }
        #pragma unroll 2
        for (int it = 0; it < EITER_B; ++it) {
            h_iter<1>(cs, A, sz, ho, t0A, t0A + CHUNK_B);
            h_iter<1>(cs, B, sz, ho, t0B, t0B + CHUNK_B);
            h_iter<1>(cs, C, sz, ho, t0C, t0C + CHUNK_B);
            h_iter<1>(cs, D, sz, ho, t0D, t0D + CHUNK_B);
        }
    } else {
        h_init_any(cs, A, sz, ho, t0A);
        h_init_any(cs, B, sz, ho, t0B);
        h_init_any(cs, C, sz, ho, t0C);
        h_init_any(cs, D, sz, ho, t0D);
        for (int it = 0; it < TRIPS_B; ++it) {
            h_iter<2>(cs, A, sz, ho, t0A, t0A + CHUNK_B);
            h_iter<2>(cs, B, sz, ho, t0B, t0B + CHUNK_B);
            h_iter<2>(cs, C, sz, ho, t0C, t0C + CHUNK_B);
            h_iter<2>(cs, D, sz, ho, t0D, t0D + CHUNK_B);
        }
    }
}

extern "C" void kernel_launch(void* const* d_in, const int* in_sizes, int n_in,
                              void* d_out, int out_size) {
    const float* y  = (const float*)d_in[0];
    const float* rv = (const float*)d_in[1];
    float* zo = (float*)d_out;
    float* ho = zo + T_TOTAL;

    k_reduce<<<RED_BLOCKS, RED_THREADS>>>((const float4*)y);
    k_setup<<<1, RED_THREADS>>>(y,
        (const float*)d_in[2],  (const float*)d_in[3],  (const float*)d_in[4],
        (const float*)d_in[5],  (const float*)d_in[6],  (const float*)d_in[7],
        (const float*)d_in[8],  (const float*)d_in[9],  (const float*)d_in[10],
        (const float*)d_in[11], (const float*)d_in[12], (const float*)d_in[13],
        (const float*)d_in[14], (const float*)d_in[15], (const float*)d_in[16],
        (const float*)d_in[17], (const float*)d_in[18]);
    k_main<<<NBLK_A, BLOCK_A>>>(y, rv, zo);
    k_hvol<<<NBLK_B, BLOCK_B>>>(zo, ho);
}

// round 13
// speedup vs baseline: 4.8284x; 1.1429x over previous
#include <cuda_runtime.h>

#define T_TOTAL 4194304
// ---- kernel A (LSTM z-chain): ILP=2 chains/thread, rv smem-staged ----
#define CHUNK_A  64
#define WARM_A   96
#define BLOCK_A  32
#define SPAN_A   (BLOCK_A * 2 * CHUNK_A)       // 4096
#define NBLK_A   (T_TOTAL / SPAN_A)            // 1024
#define PROL_A   100                           // staged lead (>= WARM_A+1, 4-aligned)
#define NSTG_A   (SPAN_A + PROL_A)             // 4196
#define PAD_A    (NSTG_A + 4 * (NSTG_A >> 7))  // lane stride 128 -> >>7 pad
#define WITER_A  (WARM_A / 4)                  // 24
#define EITER_A  (CHUNK_A / 4)                 // 16
#define TRIPS_A  (WITER_A + EITER_A)           // 40
// ---- kernel B (GARCH h-chain): ILP=2, z smem-staged, MUFU sqrt ----
#define CHUNK_B  64
#define WARM_B   384
#define BLOCK_B  32
#define SPAN_B   (BLOCK_B * 2 * CHUNK_B)       // 4096
#define NBLK_B   (T_TOTAL / SPAN_B)            // 1024
#define NSTG_B   (SPAN_B + WARM_B)             // 4480
#define PAD_B    (NSTG_B + 4 * (NSTG_B >> 7))  // lane stride 128 -> >>7 pad
#define WITER_B  ((WARM_B - 4) / 4)            // 95
#define EITER_B  (CHUNK_B / 4)                 // 16
#define TRIPS_B  (WITER_B + EITER_B)           // 111
// ---- reduction ----
#define RED_BLOCKS  1024
#define RED_THREADS 256

typedef unsigned long long u64;

struct Consts {
    u64 AA01, AA23;   // eta coeff pairs (scaled)
    u64 CC01, CC23;   // z coeff pairs
    u64 YY01, YY23;   // y_prev coeff pairs
    u64 RR01, RR23;   // rv_prev coeff pairs
    u64 BB01, BB23;   // bias pairs
    float H0, nK2, phi, alpha;
    float lam, eta0, h0, z0, rs0, omega;
};

__device__ Consts g_cs;
__device__ double g_psum[RED_BLOCKS];
__device__ double g_psq[RED_BLOCKS];

// ---------------- fast approx intrinsics ----------------
__device__ __forceinline__ float tanha(float x) {
    float r; asm("tanh.approx.f32 %0, %1;" : "=f"(r) : "f"(x)); return r;
}
__device__ __forceinline__ float rsqf(float x) {
    float r; asm("rsqrt.approx.f32 %0, %1;" : "=f"(r) : "f"(x)); return r;
}
__device__ __forceinline__ float sqtf(float x) {
    float r; asm("sqrt.approx.f32 %0, %1;" : "=f"(r) : "f"(x)); return r;
}
// ---------------- packed f32x2 helpers ----------------
__device__ __forceinline__ u64 pk2(float lo, float hi) {
    u64 r; asm("mov.b64 %0, {%1, %2};" : "=l"(r) : "f"(lo), "f"(hi)); return r;
}
__device__ __forceinline__ void upk2(u64 v, float& lo, float& hi) {
    asm("mov.b64 {%0, %1}, %2;" : "=f"(lo), "=f"(hi) : "l"(v));
}
__device__ __forceinline__ u64 fma2(u64 a, u64 b, u64 c) {
    u64 d; asm("fma.rn.f32x2 %0, %1, %2, %3;" : "=l"(d) : "l"(a), "l"(b), "l"(c));
    return d;
}
// ---------------- padded float4 smem swizzle (lane stride 128 floats) ------
__device__ __forceinline__ int jA(int i) { return i + 4 * (i >> 7); }
__device__ __forceinline__ float4 ld4A(const float* s, int i) {
    return *reinterpret_cast<const float4*>(s + jA(i));
}
__device__ __forceinline__ void st4A(float* s, int i, float4 v) {
    *reinterpret_cast<float4*>(s + jA(i)) = v;
}
__device__ __forceinline__ float ld1A(const float* s, int i) { return s[jA(i)]; }

// ---------------- deterministic variance reduction (MLP=4 unrolled) -------
__global__ void __launch_bounds__(RED_THREADS)
k_reduce(const float4* __restrict__ y4) {
    const int tid = blockIdx.x * RED_THREADS + threadIdx.x;
    const int stride = RED_BLOCKS * RED_THREADS;
    float4 v0 = y4[tid];
    float4 v1 = y4[tid + stride];
    float4 v2 = y4[tid + 2 * stride];
    float4 v3 = y4[tid + 3 * stride];
    float s0 = (v0.x + v0.y) + (v0.z + v0.w);
    float s1 = (v1.x + v1.y) + (v1.z + v1.w);
    float s2 = (v2.x + v2.y) + (v2.z + v2.w);
    float s3 = (v3.x + v3.y) + (v3.z + v3.w);
    float q0 = fmaf(v0.x, v0.x, v0.y * v0.y) + fmaf(v0.z, v0.z, v0.w * v0.w);
    float q1 = fmaf(v1.x, v1.x, v1.y * v1.y) + fmaf(v1.z, v1.z, v1.w * v1.w);
    float q2 = fmaf(v2.x, v2.x, v2.y * v2.y) + fmaf(v2.z, v2.z, v2.w * v2.w);
    float q3 = fmaf(v3.x, v3.x, v3.y * v3.y) + fmaf(v3.z, v3.z, v3.w * v3.w);
    float ss = (s0 + s1) + (s2 + s3);
    float qq = (q0 + q1) + (q2 + q3);
    #pragma unroll
    for (int o = 16; o > 0; o >>= 1) {
        ss += __shfl_down_sync(0xffffffffu, ss, o);
        qq += __shfl_down_sync(0xffffffffu, qq, o);
    }
    __shared__ float sw[RED_THREADS / 32], qw[RED_THREADS / 32];
    int lane = threadIdx.x & 31, wid = threadIdx.x >> 5;
    if (lane == 0) { sw[wid] = ss; qw[wid] = qq; }
    __syncthreads();
    if (wid == 0) {
        float a = (lane < RED_THREADS / 32) ? sw[lane] : 0.f;
        float b = (lane < RED_THREADS / 32) ? qw[lane] : 0.f;
        #pragma unroll
        for (int o = 4; o > 0; o >>= 1) {
            a += __shfl_down_sync(0xffffffffu, a, o);
            b += __shfl_down_sync(0xffffffffu, b, o);
        }
        if (lane == 0) { g_psum[blockIdx.x] = (double)a; g_psq[blockIdx.x] = (double)b; }
    }
}

// ---------------- stage-2 reduce + constant prep ----------------
__global__ void __launch_bounds__(RED_THREADS)
k_setup(
    const float* y,
    const float* Wi, const float* Ui, const float* bi,
    const float* Wf, const float* Uf, const float* bf,
    const float* Wo, const float* Uo, const float* bo,
    const float* Wc, const float* Uc, const float* bc,
    const float* omega, const float* alpha, const float* phi,
    const float* lam, const float* gam) {
    __shared__ double ds[RED_THREADS], dq[RED_THREADS];
    int t = threadIdx.x;
    double a = 0.0, b = 0.0;
    #pragma unroll
    for (int k = 0; k < RED_BLOCKS / RED_THREADS; k++) {
        a += g_psum[t + k * RED_THREADS];
        b += g_psq[t + k * RED_THREADS];
    }
    ds[t] = a; dq[t] = b;
    __syncthreads();
    for (int s = RED_THREADS / 2; s > 0; s >>= 1) {
        if (t < s) { ds[t] += ds[t + s]; dq[t] += dq[t + s]; }
        __syncthreads();
    }
    if (t != 0) return;

    double mean = ds[0] / (double)T_TOTAL;
    double var  = dq[0] / (double)T_TOTAL - mean * mean;

    float W[4][4], U[4], B[4];
    for (int k = 0; k < 4; k++) {
        W[0][k] = Wi[k]; W[1][k] = Wf[k]; W[2][k] = Wo[k]; W[3][k] = Wc[k];
    }
    U[0] = Ui[0]; U[1] = Uf[0]; U[2] = Uo[0]; U[3] = Uc[0];
    B[0] = bi[0]; B[1] = bf[0]; B[2] = bo[0]; B[3] = bc[0];

    // sigmoid(x) = 0.5*tanh(0.5x)+0.5 -> scale i,f,o pre-activations by 0.5
    float sc[4] = {0.5f, 0.5f, 0.5f, 1.0f};
    float A[4], C[4], Y[4], R[4], Bb[4];
    for (int g = 0; g < 4; g++) {
        A[g]  = sc[g] * (W[g][0] + U[g]);
        Y[g]  = sc[g] * W[g][1];
        R[g]  = sc[g] * W[g][2];
        C[g]  = sc[g] * W[g][3];
        Bb[g] = sc[g] * B[g];
    }
    Consts cs;
    union PF { float2 f2; u64 u; } p;
    p.f2 = make_float2(A[0], A[1]);  cs.AA01 = p.u;
    p.f2 = make_float2(A[2], A[3]);  cs.AA23 = p.u;
    p.f2 = make_float2(C[0], C[1]);  cs.CC01 = p.u;
    p.f2 = make_float2(C[2], C[3]);  cs.CC23 = p.u;
    p.f2 = make_float2(Y[0], Y[1]);  cs.YY01 = p.u;
    p.f2 = make_float2(Y[2], Y[3]);  cs.YY23 = p.u;
    p.f2 = make_float2(R[0], R[1]);  cs.RR01 = p.u;
    p.f2 = make_float2(R[2], R[3]);  cs.RR23 = p.u;
    p.f2 = make_float2(Bb[0], Bb[1]); cs.BB01 = p.u;
    p.f2 = make_float2(Bb[2], Bb[3]); cs.BB23 = p.u;
    cs.H0 = omega[0] * (1.0f - phi[0]) - alpha[0];
    cs.nK2 = -2.0f * alpha[0] * gam[0];
    cs.phi = phi[0]; cs.alpha = alpha[0]; cs.lam = lam[0];
    cs.omega = omega[0];
    cs.eta0 = (float)var;
    cs.h0   = (float)var;
    double se = sqrt(var);
    cs.z0  = (float)(((double)y[0] - (double)lam[0] * var) / se);
    cs.rs0 = (float)(1.0 / se);
    g_cs = cs;
}

// one LSTM step: updates (eta, c, z).
__device__ __forceinline__ void stepz(const Consts& cs,
                                      float yp, float rvp, float yt,
                                      float& eta, float& c, float& z) {
    u64 yy = pk2(yp, yp), rr = pk2(rvp, rvp);
    u64 D01 = fma2(cs.RR01, rr, fma2(cs.YY01, yy, cs.BB01));
    u64 D23 = fma2(cs.RR23, rr, fma2(cs.YY23, yy, cs.BB23));
    u64 ee = pk2(eta, eta), zz2 = pk2(z, z);
    u64 a01 = fma2(cs.AA01, ee, fma2(cs.CC01, zz2, D01));
    u64 a23 = fma2(cs.AA23, ee, fma2(cs.CC23, zz2, D23));
    float a0, a1, a2, a3;
    upk2(a01, a0, a1); upk2(a23, a2, a3);
    float ti = tanha(a0), tf = tanha(a1), to = tanha(a2), gg = tanha(a3);
    float cf = fmaf(tf, c, c);
    float cg = fmaf(ti, gg, gg);
    c = 0.5f * (cf + cg);
    float tc = tanha(c);
    float w = fmaf(to, tc, tc);
    float v = w * w;
    float q = fmaf(fmaf(5.4253472e-6f, v, -3.2552083e-4f), v, 0.03125f);
    eta = fmaf(v, q, fmaf(0.25f, w, 0.69314718056f));
    z = fmaf(-cs.lam, eta, yt) * rsqf(eta);
}

struct ZC {
    float eta, c, z, yp, rvp;
    float4 ycur, ynxt;          // 2-deep y pipeline
    int gb, rrel;               // rrel = gb - lo (smem rv rel index, 4-aligned)
};

// fast path, MODE: 0 = warm (no store, no clamp), 1 = emit (store, clamp)
template<int MODE>
__device__ __forceinline__ void z_iter(const Consts& cs, ZC& S,
    const float* __restrict__ y, const float* __restrict__ srv,
    float* __restrict__ zo, int tend) {
    int nb = S.gb + 8;
    if (MODE == 1) nb = (nb < tend) ? nb : S.gb;
    float4 yn2 = *reinterpret_cast<const float4*>(y + nb);
    float4 rq = ld4A(srv, S.rrel);                 // rv[gb..gb+3]
    float4 zz;
    stepz(cs, S.yp,     S.rvp, S.ycur.x, S.eta, S.c, S.z); zz.x = S.z;
    stepz(cs, S.ycur.x, rq.x,  S.ycur.y, S.eta, S.c, S.z); zz.y = S.z;
    stepz(cs, S.ycur.y, rq.y,  S.ycur.z, S.eta, S.c, S.z); zz.z = S.z;
    stepz(cs, S.ycur.z, rq.z,  S.ycur.w, S.eta, S.c, S.z); zz.w = S.z;
    if (MODE == 1)
        *reinterpret_cast<float4*>(zo + S.gb) = zz;
    S.yp = S.ycur.w; S.rvp = rq.w;
    S.ycur = S.ynxt; S.ynxt = yn2;
    S.gb += 4; S.rrel += 4;
}

// predicated slow path (block 0 only), 1-deep pipeline
__device__ __forceinline__ void z_iter_pred(const Consts& cs, ZC& S,
    const float* __restrict__ y, const float* __restrict__ srv,
    float* __restrict__ zo, int t0, int tend) {
    int nb = S.gb + 4;
    nb = (nb < tend) ? nb : S.gb;
    float4 yn = *reinterpret_cast<const float4*>(y + nb);
    float4 rq = ld4A(srv, S.rrel);
    float4 zz;
    stepz(cs, S.yp,     S.rvp, S.ycur.x, S.eta, S.c, S.z); zz.x = S.z;
    stepz(cs, S.ycur.x, rq.x,  S.ycur.y, S.eta, S.c, S.z); zz.y = S.z;
    stepz(cs, S.ycur.y, rq.y,  S.ycur.z, S.eta, S.c, S.z); zz.z = S.z;
    stepz(cs, S.ycur.z, rq.z,  S.ycur.w, S.eta, S.c, S.z); zz.w = S.z;
    if (S.gb >= t0 && S.gb < tend)
        *reinterpret_cast<float4*>(zo + S.gb) = zz;
    S.yp = S.ycur.w; S.rvp = rq.w;
    S.ycur = yn;
    S.gb += 4; S.rrel += 4;
}

__device__ __forceinline__ void z_seed(const Consts& cs, ZC& S,
    const float* __restrict__ y, const float* __restrict__ srv,
    int t0, int lo) {
    S.eta = cs.eta0; S.c = 0.0f;
    int g0 = t0 - (WARM_A + 1);
    S.yp = y[g0];
    S.rvp = ld1A(srv, g0 - lo);
    S.z = fmaf(-cs.lam, cs.eta0, S.yp) * cs.rs0;
    S.gb = g0 + 1;                 // == t0 - WARM_A, 4-aligned
    S.rrel = S.gb - lo;
    S.ycur = *reinterpret_cast<const float4*>(y + S.gb);
    S.ynxt = *reinterpret_cast<const float4*>(y + S.gb + 4);
}

// exact-capable init (block 0 only; lo == 0 there); 1-deep (pred path)
__device__ __forceinline__ void z_init_any(const Consts& cs, ZC& S,
    const float* __restrict__ y, const float* __restrict__ srv,
    float* __restrict__ zo, int t0) {
    if (t0 > WARM_A) {
        z_seed(cs, S, y, srv, t0, 0);
        return;
    }
    S.eta = cs.eta0; S.c = 0.0f;
    S.yp = y[0]; S.rvp = srv[0]; S.z = cs.z0;
    float z1, z2, z3, yt;
    yt = y[1]; stepz(cs, S.yp, S.rvp, yt, S.eta, S.c, S.z); z1 = S.z; S.yp = yt; S.rvp = ld1A(srv, 1);
    yt = y[2]; stepz(cs, S.yp, S.rvp, yt, S.eta, S.c, S.z); z2 = S.z; S.yp = yt; S.rvp = ld1A(srv, 2);
    yt = y[3]; stepz(cs, S.yp, S.rvp, yt, S.eta, S.c, S.z); z3 = S.z; S.yp = yt; S.rvp = ld1A(srv, 3);
    if (t0 == 0) {
        float4 v; v.x = cs.z0; v.y = z1; v.z = z2; v.w = z3;
        *reinterpret_cast<float4*>(zo) = v;
    }
    S.gb = 4; S.rrel = 4;
    S.ycur = *reinterpret_cast<const float4*>(y + 4);
    S.ynxt = S.ycur;   // unused on pred path
}

__global__ void __launch_bounds__(BLOCK_A)
k_main(const float* __restrict__ y, const float* __restrict__ rv,
       float* __restrict__ zo) {
    __shared__ alignas(16) float srv[PAD_A];
    const Consts cs = g_cs;
    const int blk0 = blockIdx.x * SPAN_A;
    int lo = blk0 - PROL_A; if (lo < 0) lo = 0;
    const int n = blk0 + SPAN_A - lo;
    for (int i = threadIdx.x * 4; i < n; i += BLOCK_A * 4) {
        float4 v = *reinterpret_cast<const float4*>(rv + lo + i);
        st4A(srv, i, v);
    }
    __syncwarp();

    int t0A = blk0 + threadIdx.x * (2 * CHUNK_A);
    int t0B = t0A + CHUNK_A;
    ZC A, B;
    if (blockIdx.x != 0) {
        z_seed(cs, A, y, srv, t0A, lo);
        z_seed(cs, B, y, srv, t0B, lo);
        #pragma unroll 2
        for (int it = 0; it < WITER_A; ++it) {
            z_iter<0>(cs, A, y, srv, zo, t0A + CHUNK_A);
            z_iter<0>(cs, B, y, srv, zo, t0B + CHUNK_A);
        }
        #pragma unroll 2
        for (int it = 0; it < EITER_A; ++it) {
            z_iter<1>(cs, A, y, srv, zo, t0A + CHUNK_A);
            z_iter<1>(cs, B, y, srv, zo, t0B + CHUNK_A);
        }
    } else {
        z_init_any(cs, A, y, srv, zo, t0A);
        z_init_any(cs, B, y, srv, zo, t0B);
        for (int it = 0; it < TRIPS_A; ++it) {
            z_iter_pred(cs, A, y, srv, zo, t0A, t0A + CHUNK_A);
            z_iter_pred(cs, B, y, srv, zo, t0B, t0B + CHUNK_A);
        }
    }
}

// one GARCH h step (MUFU sqrt — unconditionally stable):
// h' = phi*h + H0 + alpha*z^2 + nK2*z*sqrt(h)
__device__ __forceinline__ void steph(const Consts& cs, float zp, float& h) {
    float u = fmaf(cs.alpha * zp, zp, cs.H0);
    h = fmaf(cs.phi, h, fmaf(cs.nK2 * zp, sqtf(h), u));
}

struct HC {
    float h, zprev;     // zprev = z[gb-1]
    float4 cur;         // z[gb..gb+3]
    int gb, rel;        // rel = gb - lo (4-aligned)
};

template<int MODE>   // 0 warm, 1 emit, 2 predicated
__device__ __forceinline__ void h_iter(const Consts& cs, HC& S,
    const float* __restrict__ sz, float* __restrict__ ho,
    int t0, int tend) {
    int nrel = S.rel + 4;
    if (MODE != 0) nrel = (S.gb + 4 < tend) ? nrel : S.rel;
    float4 nxt = ld4A(sz, nrel);
    float4 hh;
    steph(cs, S.zprev, S.h); hh.x = S.h;   // step gb uses z[gb-1]
    steph(cs, S.cur.x, S.h); hh.y = S.h;
    steph(cs, S.cur.y, S.h); hh.z = S.h;
    steph(cs, S.cur.z, S.h); hh.w = S.h;
    if (MODE == 1)
        *reinterpret_cast<float4*>(ho + S.gb) = hh;
    if (MODE == 2) {
        if (S.gb >= t0 && S.gb < tend)
            *reinterpret_cast<float4*>(ho + S.gb) = hh;
    }
    S.zprev = S.cur.w;
    S.cur = nxt;
    S.rel = nrel;
    S.gb += 4;
}

__device__ __forceinline__ void h_seed(const Consts& cs, HC& S,
    const float* __restrict__ sz, int t0, int lo) {
    int g0 = t0 - WARM_B;          // 4-aligned
    S.h = cs.omega;
    int rel0 = g0 - lo;            // 4-aligned
    float4 q0 = ld4A(sz, rel0);    // z[g0..g0+3]
    steph(cs, q0.x, S.h);
    steph(cs, q0.y, S.h);
    steph(cs, q0.z, S.h);
    S.zprev = q0.w;
    S.gb = g0 + 4;
    S.rel = rel0 + 4;
    S.cur = ld4A(sz, S.rel);
}

__device__ __forceinline__ void h_init_any(const Consts& cs, HC& S,
    const float* __restrict__ sz, float* __restrict__ ho, int t0) {
    if (t0 > WARM_B) { h_seed(cs, S, sz, t0, 0); return; }
    S.h = cs.h0;
    float4 q0 = ld4A(sz, 0);
    float h1, h2, h3;
    steph(cs, q0.x, S.h); h1 = S.h;
    steph(cs, q0.y, S.h); h2 = S.h;
    steph(cs, q0.z, S.h); h3 = S.h;
    if (t0 == 0) {
        float4 v; v.x = cs.h0; v.y = h1; v.z = h2; v.w = h3;
        *reinterpret_cast<float4*>(ho) = v;
    }
    S.zprev = q0.w;
    S.gb = 4;
    S.rel = 4;
    S.cur = ld4A(sz, 4);
}

__global__ void __launch_bounds__(BLOCK_B)
k_hvol(const float* __restrict__ zo, float* __restrict__ ho) {
    __shared__ alignas(16) float sz[PAD_B];
    const Consts cs = g_cs;
    const int blk0 = blockIdx.x * SPAN_B;
    int lo = blk0 - WARM_B; if (lo < 0) lo = 0;
    const int n = blk0 + SPAN_B - lo;
    for (int i = threadIdx.x * 4; i < n; i += BLOCK_B * 4) {
        float4 v = *reinterpret_cast<const float4*>(zo + lo + i);
        st4A(sz, i, v);
    }
    __syncwarp();

    int t0A = blk0 + threadIdx.x * (2 * CHUNK_B);
    int t0B = t0A + CHUNK_B;
    HC A, B;
    if (blockIdx.x != 0) {
        h_seed(cs, A, sz, t0A, lo);
        h_seed(cs, B, sz, t0B, lo);
        #pragma unroll 4
        for (int it = 0; it < WITER_B; ++it) {
            h_iter<0>(cs, A, sz, ho, t0A, t0A + CHUNK_B);
            h_iter<0>(cs, B, sz, ho, t0B, t0B + CHUNK_B);
        }
        #pragma unroll 4
        for (int it = 0; it < EITER_B; ++it) {
            h_iter<1>(cs, A, sz, ho, t0A, t0A + CHUNK_B);
            h_iter<1>(cs, B, sz, ho, t0B, t0B + CHUNK_B);
        }
    } else {
        h_init_any(cs, A, sz, ho, t0A);
        h_init_any(cs, B, sz, ho, t0B);
        for (int it = 0; it < TRIPS_B; ++it) {
            h_iter<2>(cs, A, sz, ho, t0A, t0A + CHUNK_B);
            h_iter<2>(cs, B, sz, ho, t0B, t0B + CHUNK_B);
        }
    }
}

extern "C" void kernel_launch(void* const* d_in, const int* in_sizes, int n_in,
                              void* d_out, int out_size) {
    const float* y  = (const float*)d_in[0];
    const float* rv = (const float*)d_in[1];
    float* zo = (float*)d_out;
    float* ho = zo + T_TOTAL;

    k_reduce<<<RED_BLOCKS, RED_THREADS>>>((const float4*)y);
    k_setup<<<1, RED_THREADS>>>(y,
        (const float*)d_in[2],  (const float*)d_in[3],  (const float*)d_in[4],
        (const float*)d_in[5],  (const float*)d_in[6],  (const float*)d_in[7],
        (const float*)d_in[8],  (const float*)d_in[9],  (const float*)d_in[10],
        (const float*)d_in[11], (const float*)d_in[12], (const float*)d_in[13],
        (const float*)d_in[14], (const float*)d_in[15], (const float*)d_in[16],
        (const float*)d_in[17], (const float*)d_in[18]);
    k_main<<<NBLK_A, BLOCK_A>>>(y, rv, zo);
    k_hvol<<<NBLK_B, BLOCK_B>>>(zo, ho);
}

// round 14
// speedup vs baseline: 4.9715x; 1.0296x over previous
#include <cuda_runtime.h>

#define T_TOTAL 4194304
// ---- kernel A (LSTM z-chain): ILP=2 chains/thread, rv smem-staged ----
#define CHUNK_A  32
#define WARM_A   48
#define BLOCK_A  32
#define SPAN_A   (BLOCK_A * 2 * CHUNK_A)       // 2048
#define NBLK_A   (T_TOTAL / SPAN_A)            // 2048
#define PROL_A   52                            // staged lead (>= WARM_A+1, 4-aligned)
#define NSTG_A   (SPAN_A + PROL_A)             // 2100
#define PAD_A    (NSTG_A + 4 * (NSTG_A >> 6))  // lane stride 64 -> >>6 pad
#define WITER_A  (WARM_A / 4)                  // 12
#define EITER_A  (CHUNK_A / 4)                 // 8
#define TRIPS_A  (WITER_A + EITER_A)           // 20
// ---- kernel B (GARCH h-chain): ILP=2, z smem-staged, MUFU sqrt ----
#define CHUNK_B  64
#define WARM_B   384
#define BLOCK_B  32
#define SPAN_B   (BLOCK_B * 2 * CHUNK_B)       // 4096
#define NBLK_B   (T_TOTAL / SPAN_B)            // 1024
#define NSTG_B   (SPAN_B + WARM_B)             // 4480
#define PAD_B    (NSTG_B + 4 * (NSTG_B >> 7))  // lane stride 128 -> >>7 pad
#define WITER_B  ((WARM_B - 4) / 4)            // 95
#define EITER_B  (CHUNK_B / 4)                 // 16
#define TRIPS_B  (WITER_B + EITER_B)           // 111
// ---- reduction ----
#define RED_BLOCKS  1024
#define RED_THREADS 256

typedef unsigned long long u64;

struct Consts {
    u64 AA01, AA23;   // eta coeff pairs (scaled)
    u64 CC01, CC23;   // z coeff pairs
    u64 YY01, YY23;   // y_prev coeff pairs
    u64 RR01, RR23;   // rv_prev coeff pairs
    u64 BB01, BB23;   // bias pairs
    float H0, nK2, phi, alpha;
    float lam, eta0, h0, z0, rs0, omega;
};

__device__ Consts g_cs;
__device__ double g_psum[RED_BLOCKS];
__device__ double g_psq[RED_BLOCKS];

// ---------------- fast approx intrinsics ----------------
__device__ __forceinline__ float tanha(float x) {
    float r; asm("tanh.approx.f32 %0, %1;" : "=f"(r) : "f"(x)); return r;
}
__device__ __forceinline__ float rsqf(float x) {
    float r; asm("rsqrt.approx.f32 %0, %1;" : "=f"(r) : "f"(x)); return r;
}
__device__ __forceinline__ float sqtf(float x) {
    float r; asm("sqrt.approx.f32 %0, %1;" : "=f"(r) : "f"(x)); return r;
}
// ---------------- packed f32x2 helpers ----------------
__device__ __forceinline__ u64 pk2(float lo, float hi) {
    u64 r; asm("mov.b64 %0, {%1, %2};" : "=l"(r) : "f"(lo), "f"(hi)); return r;
}
__device__ __forceinline__ void upk2(u64 v, float& lo, float& hi) {
    asm("mov.b64 {%0, %1}, %2;" : "=f"(lo), "=f"(hi) : "l"(v));
}
__device__ __forceinline__ u64 fma2(u64 a, u64 b, u64 c) {
    u64 d; asm("fma.rn.f32x2 %0, %1, %2, %3;" : "=l"(d) : "l"(a), "l"(b), "l"(c));
    return d;
}
// ---------------- padded float4 smem swizzles (stride-matched) -------------
// kernel A: lane stride 64 floats -> pad 16B per 64 (bank stride 68 = 4 mod 32)
__device__ __forceinline__ int jA(int i) { return i + 4 * (i >> 6); }
__device__ __forceinline__ float4 ld4A(const float* s, int i) {
    return *reinterpret_cast<const float4*>(s + jA(i));
}
__device__ __forceinline__ void st4A(float* s, int i, float4 v) {
    *reinterpret_cast<float4*>(s + jA(i)) = v;
}
__device__ __forceinline__ float ld1A(const float* s, int i) { return s[jA(i)]; }
// kernel B: lane stride 128 floats -> pad 16B per 128 (bank stride 132)
__device__ __forceinline__ int jB(int i) { return i + 4 * (i >> 7); }
__device__ __forceinline__ float4 ld4B(const float* s, int i) {
    return *reinterpret_cast<const float4*>(s + jB(i));
}
__device__ __forceinline__ void st4B(float* s, int i, float4 v) {
    *reinterpret_cast<float4*>(s + jB(i)) = v;
}

// ---------------- deterministic variance reduction (MLP=4 unrolled) -------
__global__ void __launch_bounds__(RED_THREADS)
k_reduce(const float4* __restrict__ y4) {
    const int tid = blockIdx.x * RED_THREADS + threadIdx.x;
    const int stride = RED_BLOCKS * RED_THREADS;
    float4 v0 = y4[tid];
    float4 v1 = y4[tid + stride];
    float4 v2 = y4[tid + 2 * stride];
    float4 v3 = y4[tid + 3 * stride];
    float s0 = (v0.x + v0.y) + (v0.z + v0.w);
    float s1 = (v1.x + v1.y) + (v1.z + v1.w);
    float s2 = (v2.x + v2.y) + (v2.z + v2.w);
    float s3 = (v3.x + v3.y) + (v3.z + v3.w);
    float q0 = fmaf(v0.x, v0.x, v0.y * v0.y) + fmaf(v0.z, v0.z, v0.w * v0.w);
    float q1 = fmaf(v1.x, v1.x, v1.y * v1.y) + fmaf(v1.z, v1.z, v1.w * v1.w);
    float q2 = fmaf(v2.x, v2.x, v2.y * v2.y) + fmaf(v2.z, v2.z, v2.w * v2.w);
    float q3 = fmaf(v3.x, v3.x, v3.y * v3.y) + fmaf(v3.z, v3.z, v3.w * v3.w);
    float ss = (s0 + s1) + (s2 + s3);
    float qq = (q0 + q1) + (q2 + q3);
    #pragma unroll
    for (int o = 16; o > 0; o >>= 1) {
        ss += __shfl_down_sync(0xffffffffu, ss, o);
        qq += __shfl_down_sync(0xffffffffu, qq, o);
    }
    __shared__ float sw[RED_THREADS / 32], qw[RED_THREADS / 32];
    int lane = threadIdx.x & 31, wid = threadIdx.x >> 5;
    if (lane == 0) { sw[wid] = ss; qw[wid] = qq; }
    __syncthreads();
    if (wid == 0) {
        float a = (lane < RED_THREADS / 32) ? sw[lane] : 0.f;
        float b = (lane < RED_THREADS / 32) ? qw[lane] : 0.f;
        #pragma unroll
        for (int o = 4; o > 0; o >>= 1) {
            a += __shfl_down_sync(0xffffffffu, a, o);
            b += __shfl_down_sync(0xffffffffu, b, o);
        }
        if (lane == 0) { g_psum[blockIdx.x] = (double)a; g_psq[blockIdx.x] = (double)b; }
    }
}

// ---------------- stage-2 reduce + constant prep ----------------
__global__ void __launch_bounds__(RED_THREADS)
k_setup(
    const float* y,
    const float* Wi, const float* Ui, const float* bi,
    const float* Wf, const float* Uf, const float* bf,
    const float* Wo, const float* Uo, const float* bo,
    const float* Wc, const float* Uc, const float* bc,
    const float* omega, const float* alpha, const float* phi,
    const float* lam, const float* gam) {
    __shared__ double ds[RED_THREADS], dq[RED_THREADS];
    int t = threadIdx.x;
    double a = 0.0, b = 0.0;
    #pragma unroll
    for (int k = 0; k < RED_BLOCKS / RED_THREADS; k++) {
        a += g_psum[t + k * RED_THREADS];
        b += g_psq[t + k * RED_THREADS];
    }
    ds[t] = a; dq[t] = b;
    __syncthreads();
    for (int s = RED_THREADS / 2; s > 0; s >>= 1) {
        if (t < s) { ds[t] += ds[t + s]; dq[t] += dq[t + s]; }
        __syncthreads();
    }
    if (t != 0) return;

    double mean = ds[0] / (double)T_TOTAL;
    double var  = dq[0] / (double)T_TOTAL - mean * mean;

    float W[4][4], U[4], B[4];
    for (int k = 0; k < 4; k++) {
        W[0][k] = Wi[k]; W[1][k] = Wf[k]; W[2][k] = Wo[k]; W[3][k] = Wc[k];
    }
    U[0] = Ui[0]; U[1] = Uf[0]; U[2] = Uo[0]; U[3] = Uc[0];
    B[0] = bi[0]; B[1] = bf[0]; B[2] = bo[0]; B[3] = bc[0];

    // sigmoid(x) = 0.5*tanh(0.5x)+0.5 -> scale i,f,o pre-activations by 0.5
    float sc[4] = {0.5f, 0.5f, 0.5f, 1.0f};
    float A[4], C[4], Y[4], R[4], Bb[4];
    for (int g = 0; g < 4; g++) {
        A[g]  = sc[g] * (W[g][0] + U[g]);
        Y[g]  = sc[g] * W[g][1];
        R[g]  = sc[g] * W[g][2];
        C[g]  = sc[g] * W[g][3];
        Bb[g] = sc[g] * B[g];
    }
    Consts cs;
    union PF { float2 f2; u64 u; } p;
    p.f2 = make_float2(A[0], A[1]);  cs.AA01 = p.u;
    p.f2 = make_float2(A[2], A[3]);  cs.AA23 = p.u;
    p.f2 = make_float2(C[0], C[1]);  cs.CC01 = p.u;
    p.f2 = make_float2(C[2], C[3]);  cs.CC23 = p.u;
    p.f2 = make_float2(Y[0], Y[1]);  cs.YY01 = p.u;
    p.f2 = make_float2(Y[2], Y[3]);  cs.YY23 = p.u;
    p.f2 = make_float2(R[0], R[1]);  cs.RR01 = p.u;
    p.f2 = make_float2(R[2], R[3]);  cs.RR23 = p.u;
    p.f2 = make_float2(Bb[0], Bb[1]); cs.BB01 = p.u;
    p.f2 = make_float2(Bb[2], Bb[3]); cs.BB23 = p.u;
    cs.H0 = omega[0] * (1.0f - phi[0]) - alpha[0];
    cs.nK2 = -2.0f * alpha[0] * gam[0];
    cs.phi = phi[0]; cs.alpha = alpha[0]; cs.lam = lam[0];
    cs.omega = omega[0];
    cs.eta0 = (float)var;
    cs.h0   = (float)var;
    double se = sqrt(var);
    cs.z0  = (float)(((double)y[0] - (double)lam[0] * var) / se);
    cs.rs0 = (float)(1.0 / se);
    g_cs = cs;
}

// one LSTM step: updates (eta, c, z).
__device__ __forceinline__ void stepz(const Consts& cs,
                                      float yp, float rvp, float yt,
                                      float& eta, float& c, float& z) {
    u64 yy = pk2(yp, yp), rr = pk2(rvp, rvp);
    u64 D01 = fma2(cs.RR01, rr, fma2(cs.YY01, yy, cs.BB01));
    u64 D23 = fma2(cs.RR23, rr, fma2(cs.YY23, yy, cs.BB23));
    u64 ee = pk2(eta, eta), zz2 = pk2(z, z);
    u64 a01 = fma2(cs.AA01, ee, fma2(cs.CC01, zz2, D01));
    u64 a23 = fma2(cs.AA23, ee, fma2(cs.CC23, zz2, D23));
    float a0, a1, a2, a3;
    upk2(a01, a0, a1); upk2(a23, a2, a3);
    float ti = tanha(a0), tf = tanha(a1), to = tanha(a2), gg = tanha(a3);
    float cf = fmaf(tf, c, c);
    float cg = fmaf(ti, gg, gg);
    c = 0.5f * (cf + cg);
    float tc = tanha(c);
    float w = fmaf(to, tc, tc);
    float v = w * w;
    float q = fmaf(fmaf(5.4253472e-6f, v, -3.2552083e-4f), v, 0.03125f);
    eta = fmaf(v, q, fmaf(0.25f, w, 0.69314718056f));
    z = fmaf(-cs.lam, eta, yt) * rsqf(eta);
}

struct ZC {
    float eta, c, z, yp, rvp;
    float4 ycur, ynxt;          // 2-deep y pipeline
    int gb, rrel;               // rrel = gb - lo (smem rv rel index, 4-aligned)
};

// fast path, MODE: 0 = warm (no store, no clamp), 1 = emit (store, clamp)
template<int MODE>
__device__ __forceinline__ void z_iter(const Consts& cs, ZC& S,
    const float* __restrict__ y, const float* __restrict__ srv,
    float* __restrict__ zo, int tend) {
    int nb = S.gb + 8;
    if (MODE == 1) nb = (nb < tend) ? nb : S.gb;
    float4 yn2 = *reinterpret_cast<const float4*>(y + nb);
    float4 rq = ld4A(srv, S.rrel);                 // rv[gb..gb+3]
    float4 zz;
    stepz(cs, S.yp,     S.rvp, S.ycur.x, S.eta, S.c, S.z); zz.x = S.z;
    stepz(cs, S.ycur.x, rq.x,  S.ycur.y, S.eta, S.c, S.z); zz.y = S.z;
    stepz(cs, S.ycur.y, rq.y,  S.ycur.z, S.eta, S.c, S.z); zz.z = S.z;
    stepz(cs, S.ycur.z, rq.z,  S.ycur.w, S.eta, S.c, S.z); zz.w = S.z;
    if (MODE == 1)
        *reinterpret_cast<float4*>(zo + S.gb) = zz;
    S.yp = S.ycur.w; S.rvp = rq.w;
    S.ycur = S.ynxt; S.ynxt = yn2;
    S.gb += 4; S.rrel += 4;
}

// predicated slow path (block 0 only), 1-deep pipeline
__device__ __forceinline__ void z_iter_pred(const Consts& cs, ZC& S,
    const float* __restrict__ y, const float* __restrict__ srv,
    float* __restrict__ zo, int t0, int tend) {
    int nb = S.gb + 4;
    nb = (nb < tend) ? nb : S.gb;
    float4 yn = *reinterpret_cast<const float4*>(y + nb);
    float4 rq = ld4A(srv, S.rrel);
    float4 zz;
    stepz(cs, S.yp,     S.rvp, S.ycur.x, S.eta, S.c, S.z); zz.x = S.z;
    stepz(cs, S.ycur.x, rq.x,  S.ycur.y, S.eta, S.c, S.z); zz.y = S.z;
    stepz(cs, S.ycur.y, rq.y,  S.ycur.z, S.eta, S.c, S.z); zz.z = S.z;
    stepz(cs, S.ycur.z, rq.z,  S.ycur.w, S.eta, S.c, S.z); zz.w = S.z;
    if (S.gb >= t0 && S.gb < tend)
        *reinterpret_cast<float4*>(zo + S.gb) = zz;
    S.yp = S.ycur.w; S.rvp = rq.w;
    S.ycur = yn;
    S.gb += 4; S.rrel += 4;
}

__device__ __forceinline__ void z_seed(const Consts& cs, ZC& S,
    const float* __restrict__ y, const float* __restrict__ srv,
    int t0, int lo) {
    S.eta = cs.eta0; S.c = 0.0f;
    int g0 = t0 - (WARM_A + 1);
    S.yp = y[g0];
    S.rvp = ld1A(srv, g0 - lo);
    S.z = fmaf(-cs.lam, cs.eta0, S.yp) * cs.rs0;
    S.gb = g0 + 1;                 // == t0 - WARM_A, 4-aligned
    S.rrel = S.gb - lo;
    S.ycur = *reinterpret_cast<const float4*>(y + S.gb);
    S.ynxt = *reinterpret_cast<const float4*>(y + S.gb + 4);
}

// exact-capable init (block 0 only; lo == 0 there); 1-deep (pred path)
__device__ __forceinline__ void z_init_any(const Consts& cs, ZC& S,
    const float* __restrict__ y, const float* __restrict__ srv,
    float* __restrict__ zo, int t0) {
    if (t0 > WARM_A) {
        z_seed(cs, S, y, srv, t0, 0);
        return;
    }
    S.eta = cs.eta0; S.c = 0.0f;
    S.yp = y[0]; S.rvp = srv[0]; S.z = cs.z0;
    float z1, z2, z3, yt;
    yt = y[1]; stepz(cs, S.yp, S.rvp, yt, S.eta, S.c, S.z); z1 = S.z; S.yp = yt; S.rvp = ld1A(srv, 1);
    yt = y[2]; stepz(cs, S.yp, S.rvp, yt, S.eta, S.c, S.z); z2 = S.z; S.yp = yt; S.rvp = ld1A(srv, 2);
    yt = y[3]; stepz(cs, S.yp, S.rvp, yt, S.eta, S.c, S.z); z3 = S.z; S.yp = yt; S.rvp = ld1A(srv, 3);
    if (t0 == 0) {
        float4 v; v.x = cs.z0; v.y = z1; v.z = z2; v.w = z3;
        *reinterpret_cast<float4*>(zo) = v;
    }
    S.gb = 4; S.rrel = 4;
    S.ycur = *reinterpret_cast<const float4*>(y + 4);
    S.ynxt = S.ycur;   // unused on pred path
}

__global__ void __launch_bounds__(BLOCK_A)
k_main(const float* __restrict__ y, const float* __restrict__ rv,
       float* __restrict__ zo) {
    __shared__ alignas(16) float srv[PAD_A];
    const Consts cs = g_cs;
    const int blk0 = blockIdx.x * SPAN_A;
    int lo = blk0 - PROL_A; if (lo < 0) lo = 0;
    const int n = blk0 + SPAN_A - lo;
    for (int i = threadIdx.x * 4; i < n; i += BLOCK_A * 4) {
        float4 v = *reinterpret_cast<const float4*>(rv + lo + i);
        st4A(srv, i, v);
    }
    __syncwarp();

    int t0A = blk0 + threadIdx.x * (2 * CHUNK_A);
    int t0B = t0A + CHUNK_A;
    ZC A, B;
    if (blockIdx.x != 0) {
        z_seed(cs, A, y, srv, t0A, lo);
        z_seed(cs, B, y, srv, t0B, lo);
        #pragma unroll 2
        for (int it = 0; it < WITER_A; ++it) {
            z_iter<0>(cs, A, y, srv, zo, t0A + CHUNK_A);
            z_iter<0>(cs, B, y, srv, zo, t0B + CHUNK_A);
        }
        #pragma unroll 2
        for (int it = 0; it < EITER_A; ++it) {
            z_iter<1>(cs, A, y, srv, zo, t0A + CHUNK_A);
            z_iter<1>(cs, B, y, srv, zo, t0B + CHUNK_A);
        }
    } else {
        z_init_any(cs, A, y, srv, zo, t0A);
        z_init_any(cs, B, y, srv, zo, t0B);
        for (int it = 0; it < TRIPS_A; ++it) {
            z_iter_pred(cs, A, y, srv, zo, t0A, t0A + CHUNK_A);
            z_iter_pred(cs, B, y, srv, zo, t0B, t0B + CHUNK_A);
        }
    }
}

// one GARCH h step (MUFU sqrt — unconditionally stable):
// h' = phi*h + H0 + alpha*z^2 + nK2*z*sqrt(h)
__device__ __forceinline__ void steph(const Consts& cs, float zp, float& h) {
    float u = fmaf(cs.alpha * zp, zp, cs.H0);
    h = fmaf(cs.phi, h, fmaf(cs.nK2 * zp, sqtf(h), u));
}

struct HC {
    float h, zprev;     // zprev = z[gb-1]
    float4 cur;         // z[gb..gb+3]
    int gb, rel;        // rel = gb - lo (4-aligned)
};

template<int MODE>   // 0 warm, 1 emit, 2 predicated
__device__ __forceinline__ void h_iter(const Consts& cs, HC& S,
    const float* __restrict__ sz, float* __restrict__ ho,
    int t0, int tend) {
    int nrel = S.rel + 4;
    if (MODE != 0) nrel = (S.gb + 4 < tend) ? nrel : S.rel;
    float4 nxt = ld4B(sz, nrel);
    float4 hh;
    steph(cs, S.zprev, S.h); hh.x = S.h;   // step gb uses z[gb-1]
    steph(cs, S.cur.x, S.h); hh.y = S.h;
    steph(cs, S.cur.y, S.h); hh.z = S.h;
    steph(cs, S.cur.z, S.h); hh.w = S.h;
    if (MODE == 1)
        *reinterpret_cast<float4*>(ho + S.gb) = hh;
    if (MODE == 2) {
        if (S.gb >= t0 && S.gb < tend)
            *reinterpret_cast<float4*>(ho + S.gb) = hh;
    }
    S.zprev = S.cur.w;
    S.cur = nxt;
    S.rel = nrel;
    S.gb += 4;
}

__device__ __forceinline__ void h_seed(const Consts& cs, HC& S,
    const float* __restrict__ sz, int t0, int lo) {
    int g0 = t0 - WARM_B;          // 4-aligned
    S.h = cs.omega;
    int rel0 = g0 - lo;            // 4-aligned
    float4 q0 = ld4B(sz, rel0);    // z[g0..g0+3]
    steph(cs, q0.x, S.h);
    steph(cs, q0.y, S.h);
    steph(cs, q0.z, S.h);
    S.zprev = q0.w;
    S.gb = g0 + 4;
    S.rel = rel0 + 4;
    S.cur = ld4B(sz, S.rel);
}

__device__ __forceinline__ void h_init_any(const Consts& cs, HC& S,
    const float* __restrict__ sz, float* __restrict__ ho, int t0) {
    if (t0 > WARM_B) { h_seed(cs, S, sz, t0, 0); return; }
    S.h = cs.h0;
    float4 q0 = ld4B(sz, 0);
    float h1, h2, h3;
    steph(cs, q0.x, S.h); h1 = S.h;
    steph(cs, q0.y, S.h); h2 = S.h;
    steph(cs, q0.z, S.h); h3 = S.h;
    if (t0 == 0) {
        float4 v; v.x = cs.h0; v.y = h1; v.z = h2; v.w = h3;
        *reinterpret_cast<float4*>(ho) = v;
    }
    S.zprev = q0.w;
    S.gb = 4;
    S.rel = 4;
    S.cur = ld4B(sz, 4);
}

__global__ void __launch_bounds__(BLOCK_B)
k_hvol(const float* __restrict__ zo, float* __restrict__ ho) {
    __shared__ alignas(16) float sz[PAD_B];
    const Consts cs = g_cs;
    const int blk0 = blockIdx.x * SPAN_B;
    int lo = blk0 - WARM_B; if (lo < 0) lo = 0;
    const int n = blk0 + SPAN_B - lo;
    for (int i = threadIdx.x * 4; i < n; i += BLOCK_B * 4) {
        float4 v = *reinterpret_cast<const float4*>(zo + lo + i);
        st4B(sz, i, v);
    }
    __syncwarp();

    int t0A = blk0 + threadIdx.x * (2 * CHUNK_B);
    int t0B = t0A + CHUNK_B;
    HC A, B;
    if (blockIdx.x != 0) {
        h_seed(cs, A, sz, t0A, lo);
        h_seed(cs, B, sz, t0B, lo);
        #pragma unroll 4
        for (int it = 0; it < WITER_B; ++it) {
            h_iter<0>(cs, A, sz, ho, t0A, t0A + CHUNK_B);
            h_iter<0>(cs, B, sz, ho, t0B, t0B + CHUNK_B);
        }
        #pragma unroll 4
        for (int it = 0; it < EITER_B; ++it) {
            h_iter<1>(cs, A, sz, ho, t0A, t0A + CHUNK_B);
            h_iter<1>(cs, B, sz, ho, t0B, t0B + CHUNK_B);
        }
    } else {
        h_init_any(cs, A, sz, ho, t0A);
        h_init_any(cs, B, sz, ho, t0B);
        for (int it = 0; it < TRIPS_B; ++it) {
            h_iter<2>(cs, A, sz, ho, t0A, t0A + CHUNK_B);
            h_iter<2>(cs, B, sz, ho, t0B, t0B + CHUNK_B);
        }
    }
}

extern "C" void kernel_launch(void* const* d_in, const int* in_sizes, int n_in,
                              void* d_out, int out_size) {
    const float* y  = (const float*)d_in[0];
    const float* rv = (const float*)d_in[1];
    float* zo = (float*)d_out;
    float* ho = zo + T_TOTAL;

    k_reduce<<<RED_BLOCKS, RED_THREADS>>>((const float4*)y);
    k_setup<<<1, RED_THREADS>>>(y,
        (const float*)d_in[2],  (const float*)d_in[3],  (const float*)d_in[4],
        (const float*)d_in[5],  (const float*)d_in[6],  (const float*)d_in[7],
        (const float*)d_in[8],  (const float*)d_in[9],  (const float*)d_in[10],
        (const float*)d_in[11], (const float*)d_in[12], (const float*)d_in[13],
        (const float*)d_in[14], (const float*)d_in[15], (const float*)d_in[16],
        (const float*)d_in[17], (const float*)d_in[18]);
    k_main<<<NBLK_A, BLOCK_A>>>(y, rv, zo);
    k_hvol<<<NBLK_B, BLOCK_B>>>(zo, ho);
}

// round 15
// speedup vs baseline: 5.2091x; 1.0478x over previous
#include <cuda_runtime.h>

#define T_TOTAL 4194304
// ---- kernel A (LSTM z-chain): ILP=1, rv smem-staged ----
#define CHUNK_A  32
#define WARM_A   48
#define BLOCK_A  32
#define SPAN_A   (BLOCK_A * CHUNK_A)           // 1024
#define NBLK_A   (T_TOTAL / SPAN_A)            // 4096
#define PROL_A   52                            // staged lead (>= WARM_A+1, 4-aligned)
#define NSTG_A   (SPAN_A + PROL_A)             // 1076
#define PAD_A    (NSTG_A + 4 * (NSTG_A >> 5))  // lane stride 32 -> >>5 pad
#define WITER_A  (WARM_A / 4)                  // 12
#define EITER_A  (CHUNK_A / 4)                 // 8
#define TRIPS_A  (WITER_A + EITER_A)           // 20
// ---- kernel B (GARCH h-chain): ILP=1, z smem-staged, MUFU sqrt ----
#define CHUNK_B  64
#define WARM_B   384
#define BLOCK_B  32
#define SPAN_B   (BLOCK_B * CHUNK_B)           // 2048
#define NBLK_B   (T_TOTAL / SPAN_B)            // 2048
#define NSTG_B   (SPAN_B + WARM_B)             // 2432
#define PAD_B    (NSTG_B + 4 * (NSTG_B >> 6))  // lane stride 64 -> >>6 pad
#define WITER_B  ((WARM_B - 4) / 4)            // 95
#define EITER_B  (CHUNK_B / 4)                 // 16
#define TRIPS_B  (WITER_B + EITER_B)           // 111
// ---- reduction ----
#define RED_BLOCKS  1024
#define RED_THREADS 256

typedef unsigned long long u64;

struct Consts {
    u64 AA01, AA23;   // eta coeff pairs (scaled)
    u64 CC01, CC23;   // z coeff pairs
    u64 YY01, YY23;   // y_prev coeff pairs
    u64 RR01, RR23;   // rv_prev coeff pairs
    u64 BB01, BB23;   // bias pairs
    float H0, nK2, phi, alpha;
    float lam, eta0, h0, z0, rs0, omega;
};

__device__ Consts g_cs;
__device__ double g_psum[RED_BLOCKS];
__device__ double g_psq[RED_BLOCKS];

// ---------------- fast approx intrinsics ----------------
__device__ __forceinline__ float tanha(float x) {
    float r; asm("tanh.approx.f32 %0, %1;" : "=f"(r) : "f"(x)); return r;
}
__device__ __forceinline__ float rsqf(float x) {
    float r; asm("rsqrt.approx.f32 %0, %1;" : "=f"(r) : "f"(x)); return r;
}
__device__ __forceinline__ float sqtf(float x) {
    float r; asm("sqrt.approx.f32 %0, %1;" : "=f"(r) : "f"(x)); return r;
}
// ---------------- packed f32x2 helpers ----------------
__device__ __forceinline__ u64 pk2(float lo, float hi) {
    u64 r; asm("mov.b64 %0, {%1, %2};" : "=l"(r) : "f"(lo), "f"(hi)); return r;
}
__device__ __forceinline__ void upk2(u64 v, float& lo, float& hi) {
    asm("mov.b64 {%0, %1}, %2;" : "=f"(lo), "=f"(hi) : "l"(v));
}
__device__ __forceinline__ u64 fma2(u64 a, u64 b, u64 c) {
    u64 d; asm("fma.rn.f32x2 %0, %1, %2, %3;" : "=l"(d) : "l"(a), "l"(b), "l"(c));
    return d;
}
// ---------------- padded float4 smem swizzles (stride-matched) -------------
// kernel A: lane stride 32 floats -> pad 16B per 32 (bank stride 36 = 4 mod 32)
__device__ __forceinline__ int jA(int i) { return i + 4 * (i >> 5); }
__device__ __forceinline__ float4 ld4A(const float* s, int i) {
    return *reinterpret_cast<const float4*>(s + jA(i));
}
__device__ __forceinline__ void st4A(float* s, int i, float4 v) {
    *reinterpret_cast<float4*>(s + jA(i)) = v;
}
__device__ __forceinline__ float ld1A(const float* s, int i) { return s[jA(i)]; }
// kernel B: lane stride 64 floats -> pad 16B per 64 (bank stride 68)
__device__ __forceinline__ int jB(int i) { return i + 4 * (i >> 6); }
__device__ __forceinline__ float4 ld4B(const float* s, int i) {
    return *reinterpret_cast<const float4*>(s + jB(i));
}
__device__ __forceinline__ void st4B(float* s, int i, float4 v) {
    *reinterpret_cast<float4*>(s + jB(i)) = v;
}

// ---------------- deterministic variance reduction (MLP=4 unrolled) -------
__global__ void __launch_bounds__(RED_THREADS)
k_reduce(const float4* __restrict__ y4) {
    const int tid = blockIdx.x * RED_THREADS + threadIdx.x;
    const int stride = RED_BLOCKS * RED_THREADS;
    float4 v0 = y4[tid];
    float4 v1 = y4[tid + stride];
    float4 v2 = y4[tid + 2 * stride];
    float4 v3 = y4[tid + 3 * stride];
    float s0 = (v0.x + v0.y) + (v0.z + v0.w);
    float s1 = (v1.x + v1.y) + (v1.z + v1.w);
    float s2 = (v2.x + v2.y) + (v2.z + v2.w);
    float s3 = (v3.x + v3.y) + (v3.z + v3.w);
    float q0 = fmaf(v0.x, v0.x, v0.y * v0.y) + fmaf(v0.z, v0.z, v0.w * v0.w);
    float q1 = fmaf(v1.x, v1.x, v1.y * v1.y) + fmaf(v1.z, v1.z, v1.w * v1.w);
    float q2 = fmaf(v2.x, v2.x, v2.y * v2.y) + fmaf(v2.z, v2.z, v2.w * v2.w);
    float q3 = fmaf(v3.x, v3.x, v3.y * v3.y) + fmaf(v3.z, v3.z, v3.w * v3.w);
    float ss = (s0 + s1) + (s2 + s3);
    float qq = (q0 + q1) + (q2 + q3);
    #pragma unroll
    for (int o = 16; o > 0; o >>= 1) {
        ss += __shfl_down_sync(0xffffffffu, ss, o);
        qq += __shfl_down_sync(0xffffffffu, qq, o);
    }
    __shared__ float sw[RED_THREADS / 32], qw[RED_THREADS / 32];
    int lane = threadIdx.x & 31, wid = threadIdx.x >> 5;
    if (lane == 0) { sw[wid] = ss; qw[wid] = qq; }
    __syncthreads();
    if (wid == 0) {
        float a = (lane < RED_THREADS / 32) ? sw[lane] : 0.f;
        float b = (lane < RED_THREADS / 32) ? qw[lane] : 0.f;
        #pragma unroll
        for (int o = 4; o > 0; o >>= 1) {
            a += __shfl_down_sync(0xffffffffu, a, o);
            b += __shfl_down_sync(0xffffffffu, b, o);
        }
        if (lane == 0) { g_psum[blockIdx.x] = (double)a; g_psq[blockIdx.x] = (double)b; }
    }
}

// ---------------- stage-2 reduce + constant prep ----------------
__global__ void __launch_bounds__(RED_THREADS)
k_setup(
    const float* y,
    const float* Wi, const float* Ui, const float* bi,
    const float* Wf, const float* Uf, const float* bf,
    const float* Wo, const float* Uo, const float* bo,
    const float* Wc, const float* Uc, const float* bc,
    const float* omega, const float* alpha, const float* phi,
    const float* lam, const float* gam) {
    __shared__ double ds[RED_THREADS], dq[RED_THREADS];
    int t = threadIdx.x;
    double a = 0.0, b = 0.0;
    #pragma unroll
    for (int k = 0; k < RED_BLOCKS / RED_THREADS; k++) {
        a += g_psum[t + k * RED_THREADS];
        b += g_psq[t + k * RED_THREADS];
    }
    ds[t] = a; dq[t] = b;
    __syncthreads();
    for (int s = RED_THREADS / 2; s > 0; s >>= 1) {
        if (t < s) { ds[t] += ds[t + s]; dq[t] += dq[t + s]; }
        __syncthreads();
    }
    if (t != 0) return;

    double mean = ds[0] / (double)T_TOTAL;
    double var  = dq[0] / (double)T_TOTAL - mean * mean;

    float W[4][4], U[4], B[4];
    for (int k = 0; k < 4; k++) {
        W[0][k] = Wi[k]; W[1][k] = Wf[k]; W[2][k] = Wo[k]; W[3][k] = Wc[k];
    }
    U[0] = Ui[0]; U[1] = Uf[0]; U[2] = Uo[0]; U[3] = Uc[0];
    B[0] = bi[0]; B[1] = bf[0]; B[2] = bo[0]; B[3] = bc[0];

    // sigmoid(x) = 0.5*tanh(0.5x)+0.5 -> scale i,f,o pre-activations by 0.5
    float sc[4] = {0.5f, 0.5f, 0.5f, 1.0f};
    float A[4], C[4], Y[4], R[4], Bb[4];
    for (int g = 0; g < 4; g++) {
        A[g]  = sc[g] * (W[g][0] + U[g]);
        Y[g]  = sc[g] * W[g][1];
        R[g]  = sc[g] * W[g][2];
        C[g]  = sc[g] * W[g][3];
        Bb[g] = sc[g] * B[g];
    }
    Consts cs;
    union PF { float2 f2; u64 u; } p;
    p.f2 = make_float2(A[0], A[1]);  cs.AA01 = p.u;
    p.f2 = make_float2(A[2], A[3]);  cs.AA23 = p.u;
    p.f2 = make_float2(C[0], C[1]);  cs.CC01 = p.u;
    p.f2 = make_float2(C[2], C[3]);  cs.CC23 = p.u;
    p.f2 = make_float2(Y[0], Y[1]);  cs.YY01 = p.u;
    p.f2 = make_float2(Y[2], Y[3]);  cs.YY23 = p.u;
    p.f2 = make_float2(R[0], R[1]);  cs.RR01 = p.u;
    p.f2 = make_float2(R[2], R[3]);  cs.RR23 = p.u;
    p.f2 = make_float2(Bb[0], Bb[1]); cs.BB01 = p.u;
    p.f2 = make_float2(Bb[2], Bb[3]); cs.BB23 = p.u;
    cs.H0 = omega[0] * (1.0f - phi[0]) - alpha[0];
    cs.nK2 = -2.0f * alpha[0] * gam[0];
    cs.phi = phi[0]; cs.alpha = alpha[0]; cs.lam = lam[0];
    cs.omega = omega[0];
    cs.eta0 = (float)var;
    cs.h0   = (float)var;
    double se = sqrt(var);
    cs.z0  = (float)(((double)y[0] - (double)lam[0] * var) / se);
    cs.rs0 = (float)(1.0 / se);
    g_cs = cs;
}

// one LSTM step: updates (eta, c, z).
__device__ __forceinline__ void stepz(const Consts& cs,
                                      float yp, float rvp, float yt,
                                      float& eta, float& c, float& z) {
    u64 yy = pk2(yp, yp), rr = pk2(rvp, rvp);
    u64 D01 = fma2(cs.RR01, rr, fma2(cs.YY01, yy, cs.BB01));
    u64 D23 = fma2(cs.RR23, rr, fma2(cs.YY23, yy, cs.BB23));
    u64 ee = pk2(eta, eta), zz2 = pk2(z, z);
    u64 a01 = fma2(cs.AA01, ee, fma2(cs.CC01, zz2, D01));
    u64 a23 = fma2(cs.AA23, ee, fma2(cs.CC23, zz2, D23));
    float a0, a1, a2, a3;
    upk2(a01, a0, a1); upk2(a23, a2, a3);
    float ti = tanha(a0), tf = tanha(a1), to = tanha(a2), gg = tanha(a3);
    float cf = fmaf(tf, c, c);
    float cg = fmaf(ti, gg, gg);
    c = 0.5f * (cf + cg);
    float tc = tanha(c);
    float w = fmaf(to, tc, tc);
    float v = w * w;
    float q = fmaf(fmaf(5.4253472e-6f, v, -3.2552083e-4f), v, 0.03125f);
    eta = fmaf(v, q, fmaf(0.25f, w, 0.69314718056f));
    z = fmaf(-cs.lam, eta, yt) * rsqf(eta);
}

struct ZC {
    float eta, c, z, yp, rvp;
    float4 ycur, ynxt;          // 2-deep y pipeline
    int gb, rrel;               // rrel = gb - lo (smem rv rel index, 4-aligned)
};

// fast path, MODE: 0 = warm (no store, no clamp), 1 = emit (store, clamp)
template<int MODE>
__device__ __forceinline__ void z_iter(const Consts& cs, ZC& S,
    const float* __restrict__ y, const float* __restrict__ srv,
    float* __restrict__ zo, int tend) {
    int nb = S.gb + 8;
    if (MODE == 1) nb = (nb < tend) ? nb : S.gb;
    float4 yn2 = *reinterpret_cast<const float4*>(y + nb);
    float4 rq = ld4A(srv, S.rrel);                 // rv[gb..gb+3]
    float4 zz;
    stepz(cs, S.yp,     S.rvp, S.ycur.x, S.eta, S.c, S.z); zz.x = S.z;
    stepz(cs, S.ycur.x, rq.x,  S.ycur.y, S.eta, S.c, S.z); zz.y = S.z;
    stepz(cs, S.ycur.y, rq.y,  S.ycur.z, S.eta, S.c, S.z); zz.z = S.z;
    stepz(cs, S.ycur.z, rq.z,  S.ycur.w, S.eta, S.c, S.z); zz.w = S.z;
    if (MODE == 1)
        *reinterpret_cast<float4*>(zo + S.gb) = zz;
    S.yp = S.ycur.w; S.rvp = rq.w;
    S.ycur = S.ynxt; S.ynxt = yn2;
    S.gb += 4; S.rrel += 4;
}

// predicated slow path (block 0 only), 1-deep pipeline
__device__ __forceinline__ void z_iter_pred(const Consts& cs, ZC& S,
    const float* __restrict__ y, const float* __restrict__ srv,
    float* __restrict__ zo, int t0, int tend) {
    int nb = S.gb + 4;
    nb = (nb < tend) ? nb : S.gb;
    float4 yn = *reinterpret_cast<const float4*>(y + nb);
    float4 rq = ld4A(srv, S.rrel);
    float4 zz;
    stepz(cs, S.yp,     S.rvp, S.ycur.x, S.eta, S.c, S.z); zz.x = S.z;
    stepz(cs, S.ycur.x, rq.x,  S.ycur.y, S.eta, S.c, S.z); zz.y = S.z;
    stepz(cs, S.ycur.y, rq.y,  S.ycur.z, S.eta, S.c, S.z); zz.z = S.z;
    stepz(cs, S.ycur.z, rq.z,  S.ycur.w, S.eta, S.c, S.z); zz.w = S.z;
    if (S.gb >= t0 && S.gb < tend)
        *reinterpret_cast<float4*>(zo + S.gb) = zz;
    S.yp = S.ycur.w; S.rvp = rq.w;
    S.ycur = yn;
    S.gb += 4; S.rrel += 4;
}

__device__ __forceinline__ void z_seed(const Consts& cs, ZC& S,
    const float* __restrict__ y, const float* __restrict__ srv,
    int t0, int lo) {
    S.eta = cs.eta0; S.c = 0.0f;
    int g0 = t0 - (WARM_A + 1);
    S.yp = y[g0];
    S.rvp = ld1A(srv, g0 - lo);
    S.z = fmaf(-cs.lam, cs.eta0, S.yp) * cs.rs0;
    S.gb = g0 + 1;                 // == t0 - WARM_A, 4-aligned
    S.rrel = S.gb - lo;
    S.ycur = *reinterpret_cast<const float4*>(y + S.gb);
    S.ynxt = *reinterpret_cast<const float4*>(y + S.gb + 4);
}

// exact-capable init (block 0 only; lo == 0 there); 1-deep (pred path)
__device__ __forceinline__ void z_init_any(const Consts& cs, ZC& S,
    const float* __restrict__ y, const float* __restrict__ srv,
    float* __restrict__ zo, int t0) {
    if (t0 > WARM_A) {
        z_seed(cs, S, y, srv, t0, 0);
        return;
    }
    S.eta = cs.eta0; S.c = 0.0f;
    S.yp = y[0]; S.rvp = srv[0]; S.z = cs.z0;
    float z1, z2, z3, yt;
    yt = y[1]; stepz(cs, S.yp, S.rvp, yt, S.eta, S.c, S.z); z1 = S.z; S.yp = yt; S.rvp = ld1A(srv, 1);
    yt = y[2]; stepz(cs, S.yp, S.rvp, yt, S.eta, S.c, S.z); z2 = S.z; S.yp = yt; S.rvp = ld1A(srv, 2);
    yt = y[3]; stepz(cs, S.yp, S.rvp, yt, S.eta, S.c, S.z); z3 = S.z; S.yp = yt; S.rvp = ld1A(srv, 3);
    if (t0 == 0) {
        float4 v; v.x = cs.z0; v.y = z1; v.z = z2; v.w = z3;
        *reinterpret_cast<float4*>(zo) = v;
    }
    S.gb = 4; S.rrel = 4;
    S.ycur = *reinterpret_cast<const float4*>(y + 4);
    S.ynxt = S.ycur;   // unused on pred path
}

__global__ void __launch_bounds__(BLOCK_A)
k_main(const float* __restrict__ y, const float* __restrict__ rv,
       float* __restrict__ zo) {
    __shared__ alignas(16) float srv[PAD_A];
    const Consts cs = g_cs;
    const int blk0 = blockIdx.x * SPAN_A;
    int lo = blk0 - PROL_A; if (lo < 0) lo = 0;
    const int n = blk0 + SPAN_A - lo;
    for (int i = threadIdx.x * 4; i < n; i += BLOCK_A * 4) {
        float4 v = *reinterpret_cast<const float4*>(rv + lo + i);
        st4A(srv, i, v);
    }
    __syncwarp();

    int t0 = blk0 + threadIdx.x * CHUNK_A;
    ZC A;
    if (blockIdx.x != 0) {
        z_seed(cs, A, y, srv, t0, lo);
        #pragma unroll 4
        for (int it = 0; it < WITER_A; ++it)
            z_iter<0>(cs, A, y, srv, zo, t0 + CHUNK_A);
        #pragma unroll 4
        for (int it = 0; it < EITER_A; ++it)
            z_iter<1>(cs, A, y, srv, zo, t0 + CHUNK_A);
    } else {
        z_init_any(cs, A, y, srv, zo, t0);
        for (int it = 0; it < TRIPS_A; ++it)
            z_iter_pred(cs, A, y, srv, zo, t0, t0 + CHUNK_A);
    }
}

// one GARCH h step (MUFU sqrt — unconditionally stable):
// h' = phi*h + H0 + alpha*z^2 + nK2*z*sqrt(h)
__device__ __forceinline__ void steph(const Consts& cs, float zp, float& h) {
    float u = fmaf(cs.alpha * zp, zp, cs.H0);
    h = fmaf(cs.phi, h, fmaf(cs.nK2 * zp, sqtf(h), u));
}

struct HC {
    float h, zprev;     // zprev = z[gb-1]
    float4 cur;         // z[gb..gb+3]
    int gb, rel;        // rel = gb - lo (4-aligned)
};

template<int MODE>   // 0 warm, 1 emit, 2 predicated
__device__ __forceinline__ void h_iter(const Consts& cs, HC& S,
    const float* __restrict__ sz, float* __restrict__ ho,
    int t0, int tend) {
    int nrel = S.rel + 4;
    if (MODE != 0) nrel = (S.gb + 4 < tend) ? nrel : S.rel;
    float4 nxt = ld4B(sz, nrel);
    float4 hh;
    steph(cs, S.zprev, S.h); hh.x = S.h;   // step gb uses z[gb-1]
    steph(cs, S.cur.x, S.h); hh.y = S.h;
    steph(cs, S.cur.y, S.h); hh.z = S.h;
    steph(cs, S.cur.z, S.h); hh.w = S.h;
    if (MODE == 1)
        *reinterpret_cast<float4*>(ho + S.gb) = hh;
    if (MODE == 2) {
        if (S.gb >= t0 && S.gb < tend)
            *reinterpret_cast<float4*>(ho + S.gb) = hh;
    }
    S.zprev = S.cur.w;
    S.cur = nxt;
    S.rel = nrel;
    S.gb += 4;
}

__device__ __forceinline__ void h_seed(const Consts& cs, HC& S,
    const float* __restrict__ sz, int t0, int lo) {
    int g0 = t0 - WARM_B;          // 4-aligned
    S.h = cs.omega;
    int rel0 = g0 - lo;            // 4-aligned
    float4 q0 = ld4B(sz, rel0);    // z[g0..g0+3]
    steph(cs, q0.x, S.h);
    steph(cs, q0.y, S.h);
    steph(cs, q0.z, S.h);
    S.zprev = q0.w;
    S.gb = g0 + 4;
    S.rel = rel0 + 4;
    S.cur = ld4B(sz, S.rel);
}

__device__ __forceinline__ void h_init_any(const Consts& cs, HC& S,
    const float* __restrict__ sz, float* __restrict__ ho, int t0) {
    if (t0 > WARM_B) { h_seed(cs, S, sz, t0, 0); return; }
    S.h = cs.h0;
    float4 q0 = ld4B(sz, 0);
    float h1, h2, h3;
    steph(cs, q0.x, S.h); h1 = S.h;
    steph(cs, q0.y, S.h); h2 = S.h;
    steph(cs, q0.z, S.h); h3 = S.h;
    if (t0 == 0) {
        float4 v; v.x = cs.h0; v.y = h1; v.z = h2; v.w = h3;
        *reinterpret_cast<float4*>(ho) = v;
    }
    S.zprev = q0.w;
    S.gb = 4;
    S.rel = 4;
    S.cur = ld4B(sz, 4);
}

__global__ void __launch_bounds__(BLOCK_B)
k_hvol(const float* __restrict__ zo, float* __restrict__ ho) {
    __shared__ alignas(16) float sz[PAD_B];
    const Consts cs = g_cs;
    const int blk0 = blockIdx.x * SPAN_B;
    int lo = blk0 - WARM_B; if (lo < 0) lo = 0;
    const int n = blk0 + SPAN_B - lo;
    for (int i = threadIdx.x * 4; i < n; i += BLOCK_B * 4) {
        float4 v = *reinterpret_cast<const float4*>(zo + lo + i);
        st4B(sz, i, v);
    }
    __syncwarp();

    int t0 = blk0 + threadIdx.x * CHUNK_B;
    HC A;
    if (blockIdx.x != 0) {
        h_seed(cs, A, sz, t0, lo);
        #pragma unroll 8
        for (int it = 0; it < WITER_B; ++it)
            h_iter<0>(cs, A, sz, ho, t0, t0 + CHUNK_B);
        #pragma unroll 8
        for (int it = 0; it < EITER_B; ++it)
            h_iter<1>(cs, A, sz, ho, t0, t0 + CHUNK_B);
    } else {
        h_init_any(cs, A, sz, ho, t0);
        for (int it = 0; it < TRIPS_B; ++it)
            h_iter<2>(cs, A, sz, ho, t0, t0 + CHUNK_B);
    }
}

extern "C" void kernel_launch(void* const* d_in, const int* in_sizes, int n_in,
                              void* d_out, int out_size) {
    const float* y  = (const float*)d_in[0];
    const float* rv = (const float*)d_in[1];
    float* zo = (float*)d_out;
    float* ho = zo + T_TOTAL;

    k_reduce<<<RED_BLOCKS, RED_THREADS>>>((const float4*)y);
    k_setup<<<1, RED_THREADS>>>(y,
        (const float*)d_in[2],  (const float*)d_in[3],  (const float*)d_in[4],
        (const float*)d_in[5],  (const float*)d_in[6],  (const float*)d_in[7],
        (const float*)d_in[8],  (const float*)d_in[9],  (const float*)d_in[10],
        (const float*)d_in[11], (const float*)d_in[12], (const float*)d_in[13],
        (const float*)d_in[14], (const float*)d_in[15], (const float*)d_in[16],
        (const float*)d_in[17], (const float*)d_in[18]);
    k_main<<<NBLK_A, BLOCK_A>>>(y, rv, zo);
    k_hvol<<<NBLK_B, BLOCK_B>>>(zo, ho);
}